// round 1
// baseline (speedup 1.0000x reference)
#include <cuda_runtime.h>

// Problem constants
#define B_ 8
#define N_ 2048
#define H_ 256

// Scratch (allocation-free rule: __device__ globals)
__device__ float g_dinv[B_ * N_];
__device__ float g_buf0[(size_t)B_ * N_ * H_];
__device__ float g_buf1[(size_t)B_ * N_ * H_];

// ---------------------------------------------------------------------------
// Kernel 0: dinv[b,n] = rsqrt(sum_m graph[b,n,m])
// One block (256 threads) per row; 2048 floats per row.
// ---------------------------------------------------------------------------
__global__ void rowsum_kernel(const float* __restrict__ graph) {
    int row = blockIdx.x;  // b*N_ + n
    const float* p = graph + (size_t)row * N_;
    float s = 0.f;
    for (int j = threadIdx.x * 4; j < N_; j += blockDim.x * 4) {
        float4 v = *(const float4*)(p + j);
        s += v.x + v.y + v.z + v.w;
    }
#pragma unroll
    for (int o = 16; o; o >>= 1) s += __shfl_down_sync(0xffffffffu, s, o);
    __shared__ float ws[8];
    int lane = threadIdx.x & 31, w = threadIdx.x >> 5;
    if (lane == 0) ws[w] = s;
    __syncthreads();
    if (threadIdx.x == 0) {
        float t = 0.f;
#pragma unroll
        for (int i = 0; i < 8; i++) t += ws[i];
        g_dinv[row] = rsqrtf(t);
    }
}

// ---------------------------------------------------------------------------
// Kernel 1: C[b,i,h] = dinv[b,i] * sum_m graph[b,i,m] * dinv[b,m] * X[b,m,h]
// Tiled SGEMM: BM=128, BN=128, BK=16, 256 threads, 8x8 per thread,
// register-prefetch pipeline on global loads.
// dinv[m] folded into the B-tile smem store; dinv[i] applied in epilogue.
// ---------------------------------------------------------------------------
__global__ void __launch_bounds__(256) agg_gemm_kernel(
    const float* __restrict__ graph, const float* __restrict__ X,
    float* __restrict__ C)
{
    const int b  = blockIdx.z;
    const int m0 = blockIdx.y * 128;
    const int h0 = blockIdx.x * 128;
    const float* A    = graph + (size_t)b * N_ * N_;
    const float* Xb   = X + (size_t)b * N_ * H_;
    const float* dinv = g_dinv + b * N_;

    __shared__ float As[16][132];  // [k][m], padded
    __shared__ float Bs[16][132];  // [k][h], padded

    const int tid = threadIdx.x;
    // A-tile loader: 128 rows x 16 cols, 2 x float4 per thread
    const int aty = tid >> 2;            // 0..63
    const int atx = (tid & 3) << 2;      // 0,4,8,12
    // X-tile loader: 16 rows x 128 cols, 2 x float4 per thread
    const int xty = tid >> 5;            // 0..7
    const int xtx = (tid & 31) << 2;     // 0..124
    // compute mapping: 16x16 threads, 8x8 outputs each
    const int tm = (tid >> 4) << 3;      // 0..120
    const int tn = (tid & 15) << 3;      // 0..120

    float acc[8][8] = {};

    float4 ra0, ra1, rx0, rx1;
    float rd0, rd1;

    // prefetch k0 = 0
    ra0 = *(const float4*)(A + (size_t)(m0 + aty) * N_ + atx);
    ra1 = *(const float4*)(A + (size_t)(m0 + aty + 64) * N_ + atx);
    rd0 = dinv[xty];
    rd1 = dinv[xty + 8];
    rx0 = *(const float4*)(Xb + (size_t)xty * H_ + h0 + xtx);
    rx1 = *(const float4*)(Xb + (size_t)(xty + 8) * H_ + h0 + xtx);

    for (int k0 = 0; k0 < N_; k0 += 16) {
        As[atx + 0][aty]      = ra0.x;
        As[atx + 1][aty]      = ra0.y;
        As[atx + 2][aty]      = ra0.z;
        As[atx + 3][aty]      = ra0.w;
        As[atx + 0][aty + 64] = ra1.x;
        As[atx + 1][aty + 64] = ra1.y;
        As[atx + 2][aty + 64] = ra1.z;
        As[atx + 3][aty + 64] = ra1.w;
        *(float4*)&Bs[xty][xtx] =
            make_float4(rx0.x * rd0, rx0.y * rd0, rx0.z * rd0, rx0.w * rd0);
        *(float4*)&Bs[xty + 8][xtx] =
            make_float4(rx1.x * rd1, rx1.y * rd1, rx1.z * rd1, rx1.w * rd1);
        __syncthreads();

        int kn = k0 + 16;
        if (kn < N_) {
            ra0 = *(const float4*)(A + (size_t)(m0 + aty) * N_ + kn + atx);
            ra1 = *(const float4*)(A + (size_t)(m0 + aty + 64) * N_ + kn + atx);
            rd0 = dinv[kn + xty];
            rd1 = dinv[kn + xty + 8];
            rx0 = *(const float4*)(Xb + (size_t)(kn + xty) * H_ + h0 + xtx);
            rx1 = *(const float4*)(Xb + (size_t)(kn + xty + 8) * H_ + h0 + xtx);
        }

#pragma unroll
        for (int kk = 0; kk < 16; kk++) {
            float4 a0 = *(const float4*)&As[kk][tm];
            float4 a1 = *(const float4*)&As[kk][tm + 4];
            float4 b0 = *(const float4*)&Bs[kk][tn];
            float4 b1 = *(const float4*)&Bs[kk][tn + 4];
            float av[8] = {a0.x, a0.y, a0.z, a0.w, a1.x, a1.y, a1.z, a1.w};
            float bv[8] = {b0.x, b0.y, b0.z, b0.w, b1.x, b1.y, b1.z, b1.w};
#pragma unroll
            for (int i = 0; i < 8; i++)
#pragma unroll
                for (int j = 0; j < 8; j++)
                    acc[i][j] += av[i] * bv[j];
        }
        __syncthreads();
    }

    float* Cb = C + (size_t)b * N_ * H_;
#pragma unroll
    for (int i = 0; i < 8; i++) {
        int row = m0 + tm + i;
        float dv = dinv[row];
        float4 o0 = make_float4(acc[i][0] * dv, acc[i][1] * dv,
                                acc[i][2] * dv, acc[i][3] * dv);
        float4 o1 = make_float4(acc[i][4] * dv, acc[i][5] * dv,
                                acc[i][6] * dv, acc[i][7] * dv);
        *(float4*)(Cb + (size_t)row * H_ + h0 + tn)     = o0;
        *(float4*)(Cb + (size_t)row * H_ + h0 + tn + 4) = o1;
    }
}

// ---------------------------------------------------------------------------
// Kernel 2: C[i,o] = relu( sum_k Aload(i,k) * W[o,k] + bias[o] )
// A is [M=B*N, 256] row-major (for CONCAT, logical [M,512]: k<256 from A0,
// k>=256 from A1, both stride 256). W is [256, K] row-major.
// Same 128x128x16 tiling.
// ---------------------------------------------------------------------------
template <int K, bool CONCAT>
__global__ void __launch_bounds__(256) fc_gemm_kernel(
    const float* __restrict__ A0, const float* __restrict__ A1,
    const float* __restrict__ W, const float* __restrict__ bias,
    float* __restrict__ C)
{
    const int i0 = blockIdx.y * 128;
    const int o0 = blockIdx.x * 128;

    __shared__ float As[16][132];
    __shared__ float Ws[16][132];

    const int tid = threadIdx.x;
    const int aty = tid >> 2;
    const int atx = (tid & 3) << 2;
    const int tm = (tid >> 4) << 3;
    const int tn = (tid & 15) << 3;

    float acc[8][8] = {};

    float4 ra0, ra1, rw0, rw1;

    // prefetch k0 = 0
    {
        const float* src = A0;
        ra0 = *(const float4*)(src + (size_t)(i0 + aty) * H_ + atx);
        ra1 = *(const float4*)(src + (size_t)(i0 + aty + 64) * H_ + atx);
        rw0 = *(const float4*)(W + (size_t)(o0 + aty) * K + atx);
        rw1 = *(const float4*)(W + (size_t)(o0 + aty + 64) * K + atx);
    }

    for (int k0 = 0; k0 < K; k0 += 16) {
        As[atx + 0][aty]      = ra0.x;
        As[atx + 1][aty]      = ra0.y;
        As[atx + 2][aty]      = ra0.z;
        As[atx + 3][aty]      = ra0.w;
        As[atx + 0][aty + 64] = ra1.x;
        As[atx + 1][aty + 64] = ra1.y;
        As[atx + 2][aty + 64] = ra1.z;
        As[atx + 3][aty + 64] = ra1.w;
        Ws[atx + 0][aty]      = rw0.x;
        Ws[atx + 1][aty]      = rw0.y;
        Ws[atx + 2][aty]      = rw0.z;
        Ws[atx + 3][aty]      = rw0.w;
        Ws[atx + 0][aty + 64] = rw1.x;
        Ws[atx + 1][aty + 64] = rw1.y;
        Ws[atx + 2][aty + 64] = rw1.z;
        Ws[atx + 3][aty + 64] = rw1.w;
        __syncthreads();

        int kn = k0 + 16;
        if (kn < K) {
            const float* src = A0;
            int kc = kn;
            if (CONCAT && kn >= 256) { src = A1; kc = kn - 256; }
            ra0 = *(const float4*)(src + (size_t)(i0 + aty) * H_ + kc + atx);
            ra1 = *(const float4*)(src + (size_t)(i0 + aty + 64) * H_ + kc + atx);
            rw0 = *(const float4*)(W + (size_t)(o0 + aty) * K + kn + atx);
            rw1 = *(const float4*)(W + (size_t)(o0 + aty + 64) * K + kn + atx);
        }

#pragma unroll
        for (int kk = 0; kk < 16; kk++) {
            float4 a0 = *(const float4*)&As[kk][tm];
            float4 a1 = *(const float4*)&As[kk][tm + 4];
            float4 w0 = *(const float4*)&Ws[kk][tn];
            float4 w1 = *(const float4*)&Ws[kk][tn + 4];
            float av[8] = {a0.x, a0.y, a0.z, a0.w, a1.x, a1.y, a1.z, a1.w};
            float wv[8] = {w0.x, w0.y, w0.z, w0.w, w1.x, w1.y, w1.z, w1.w};
#pragma unroll
            for (int i = 0; i < 8; i++)
#pragma unroll
                for (int j = 0; j < 8; j++)
                    acc[i][j] += av[i] * wv[j];
        }
        __syncthreads();
    }

    float4 bv0 = *(const float4*)(bias + o0 + tn);
    float4 bv1 = *(const float4*)(bias + o0 + tn + 4);
    float bb[8] = {bv0.x, bv0.y, bv0.z, bv0.w, bv1.x, bv1.y, bv1.z, bv1.w};

#pragma unroll
    for (int i = 0; i < 8; i++) {
        int row = i0 + tm + i;
        float4 o0v = make_float4(fmaxf(acc[i][0] + bb[0], 0.f),
                                 fmaxf(acc[i][1] + bb[1], 0.f),
                                 fmaxf(acc[i][2] + bb[2], 0.f),
                                 fmaxf(acc[i][3] + bb[3], 0.f));
        float4 o1v = make_float4(fmaxf(acc[i][4] + bb[4], 0.f),
                                 fmaxf(acc[i][5] + bb[5], 0.f),
                                 fmaxf(acc[i][6] + bb[6], 0.f),
                                 fmaxf(acc[i][7] + bb[7], 0.f));
        *(float4*)(C + (size_t)row * H_ + o0 + tn)     = o0v;
        *(float4*)(C + (size_t)row * H_ + o0 + tn + 4) = o1v;
    }
}

// ---------------------------------------------------------------------------
// Launch
// ---------------------------------------------------------------------------
extern "C" void kernel_launch(void* const* d_in, const int* in_sizes, int n_in,
                              void* d_out, int out_size) {
    const float* node  = (const float*)d_in[0];
    const float* graph = (const float*)d_in[1];
    const float* W1    = (const float*)d_in[2];
    const float* b1    = (const float*)d_in[3];
    const float* W2    = (const float*)d_in[4];
    const float* b2    = (const float*)d_in[5];
    const float* Wout  = (const float*)d_in[6];
    const float* bout  = (const float*)d_in[7];
    float* out = (float*)d_out;

    float *buf0, *buf1;
    cudaGetSymbolAddress((void**)&buf0, g_buf0);
    cudaGetSymbolAddress((void**)&buf1, g_buf1);

    dim3 blk(256);
    dim3 gAgg(H_ / 128, N_ / 128, B_);        // (2, 16, 8)
    dim3 gFc(H_ / 128, (B_ * N_) / 128);      // (2, 128)

    rowsum_kernel<<<B_ * N_, blk>>>(graph);
    agg_gemm_kernel<<<gAgg, blk>>>(graph, node, buf0);
    fc_gemm_kernel<256, false><<<gFc, blk>>>(buf0, nullptr, W1, b1, buf1);
    agg_gemm_kernel<<<gAgg, blk>>>(graph, buf1, buf0);
    fc_gemm_kernel<256, false><<<gFc, blk>>>(buf0, nullptr, W2, b2, buf1);
    fc_gemm_kernel<512, true><<<gFc, blk>>>(node, buf1, Wout, bout, out);
}

// round 3
// speedup vs baseline: 2.3984x; 2.3984x over previous
#include <cuda_runtime.h>
#include <cuda_bf16.h>
#include <cstdint>

#define B_ 8
#define N_ 2048
#define H_ 256
#define M_TOT (B_ * N_)  // 16384

// ---------------------------------------------------------------------------
// Device scratch (allocation-free rule: __device__ globals)
// ---------------------------------------------------------------------------
__device__ __nv_bfloat16 g_Ghi[(size_t)B_ * N_ * N_];
__device__ __nv_bfloat16 g_Glo[(size_t)B_ * N_ * N_];
__device__ __nv_bfloat16 g_Xthi[(size_t)B_ * H_ * N_];
__device__ __nv_bfloat16 g_Xtlo[(size_t)B_ * H_ * N_];
__device__ __nv_bfloat16 g_Chi[(size_t)M_TOT * H_];
__device__ __nv_bfloat16 g_Clo[(size_t)M_TOT * H_];
__device__ float         g_H1[(size_t)M_TOT * H_];
__device__ __nv_bfloat16 g_H2hi[(size_t)M_TOT * H_];
__device__ __nv_bfloat16 g_H2lo[(size_t)M_TOT * H_];
__device__ __nv_bfloat16 g_Nhi[(size_t)M_TOT * H_];
__device__ __nv_bfloat16 g_Nlo[(size_t)M_TOT * H_];
__device__ __nv_bfloat16 g_W1hi[H_ * H_], g_W1lo[H_ * H_];
__device__ __nv_bfloat16 g_W2hi[H_ * H_], g_W2lo[H_ * H_];
__device__ __nv_bfloat16 g_Wohi[H_ * 2 * H_], g_Wolo[H_ * 2 * H_];
__device__ float g_dinv[B_ * N_];

// ---------------------------------------------------------------------------
// PTX helpers (portable: sm_80-era instructions only)
// ---------------------------------------------------------------------------
__device__ __forceinline__ uint32_t s2u(const void* p) {
    uint32_t r;
    asm("{ .reg .u64 t; cvta.to.shared.u64 t, %1; cvt.u32.u64 %0, t; }"
        : "=r"(r) : "l"(p));
    return r;
}
__device__ __forceinline__ void cp16(uint32_t s, const void* g) {
    asm volatile("cp.async.cg.shared.global [%0], [%1], 16;" :: "r"(s), "l"(g) : "memory");
}
#define CP_COMMIT() asm volatile("cp.async.commit_group;" ::: "memory")
#define CP_WAIT1()  asm volatile("cp.async.wait_group 1;" ::: "memory")
#define CP_WAIT0()  asm volatile("cp.async.wait_group 0;" ::: "memory")

__device__ __forceinline__ void ldsm4(uint32_t* r, uint32_t a) {
    asm volatile("ldmatrix.sync.aligned.m8n8.x4.shared.b16 {%0,%1,%2,%3}, [%4];"
                 : "=r"(r[0]), "=r"(r[1]), "=r"(r[2]), "=r"(r[3]) : "r"(a));
}
__device__ __forceinline__ void mma_bf16(float* d, const uint32_t* a, const uint32_t* b) {
    asm volatile(
        "mma.sync.aligned.m16n8k16.row.col.f32.bf16.bf16.f32 "
        "{%0,%1,%2,%3}, {%4,%5,%6,%7}, {%8,%9}, {%0,%1,%2,%3};"
        : "+f"(d[0]), "+f"(d[1]), "+f"(d[2]), "+f"(d[3])
        : "r"(a[0]), "r"(a[1]), "r"(a[2]), "r"(a[3]), "r"(b[0]), "r"(b[1]));
}

__device__ __forceinline__ void split1(float v, __nv_bfloat16& h, __nv_bfloat16& l) {
    h = __float2bfloat16(v);
    l = __float2bfloat16(v - __bfloat162float(h));
}
__device__ __forceinline__ uint32_t packbf2(__nv_bfloat16 a, __nv_bfloat16 b) {
    __nv_bfloat162 t(a, b);
    return *reinterpret_cast<uint32_t*>(&t);
}

// ---------------------------------------------------------------------------
// graph -> bf16 hi/lo + fused row-sum -> dinv
// ---------------------------------------------------------------------------
__global__ void graph_conv(const float* __restrict__ graph) {
    int row = blockIdx.x;
    size_t base = (size_t)row * N_;
    float s = 0.f;
#pragma unroll
    for (int it = 0; it < 2; it++) {
        int j = (threadIdx.x + it * 256) * 4;
        float4 v = *(const float4*)(graph + base + j);
        s += v.x + v.y + v.z + v.w;
        __nv_bfloat16 h0, l0, h1, l1, h2, l2, h3, l3;
        split1(v.x, h0, l0); split1(v.y, h1, l1);
        split1(v.z, h2, l2); split1(v.w, h3, l3);
        *(uint2*)(g_Ghi + base + j) = make_uint2(packbf2(h0, h1), packbf2(h2, h3));
        *(uint2*)(g_Glo + base + j) = make_uint2(packbf2(l0, l1), packbf2(l2, l3));
    }
#pragma unroll
    for (int o = 16; o; o >>= 1) s += __shfl_down_sync(0xffffffffu, s, o);
    __shared__ float ws[8];
    int lane = threadIdx.x & 31, w = threadIdx.x >> 5;
    if (lane == 0) ws[w] = s;
    __syncthreads();
    if (threadIdx.x == 0) {
        float t = 0.f;
#pragma unroll
        for (int i = 0; i < 8; i++) t += ws[i];
        g_dinv[row] = rsqrtf(t);
    }
}

// ---------------------------------------------------------------------------
// fp32 -> bf16 hi/lo split (elementwise)
// ---------------------------------------------------------------------------
__global__ void split_conv(const float* __restrict__ src, __nv_bfloat16* __restrict__ hi,
                           __nv_bfloat16* __restrict__ lo) {
    size_t j = ((size_t)blockIdx.x * 256 + threadIdx.x) * 4;
    float4 v = *(const float4*)(src + j);
    __nv_bfloat16 h0, l0, h1, l1, h2, l2, h3, l3;
    split1(v.x, h0, l0); split1(v.y, h1, l1);
    split1(v.z, h2, l2); split1(v.w, h3, l3);
    *(uint2*)(hi + j) = make_uint2(packbf2(h0, h1), packbf2(h2, h3));
    *(uint2*)(lo + j) = make_uint2(packbf2(l0, l1), packbf2(l2, l3));
}

// ---------------------------------------------------------------------------
// Xt[b][n][k] = src[b][k][n] * dinv[b][k], split bf16 hi/lo
// ---------------------------------------------------------------------------
__global__ void xt_build(const float* __restrict__ src) {
    __shared__ float t[32][33];
    int b = blockIdx.z, k0 = blockIdx.x * 32, n0 = blockIdx.y * 32;
    const float* S = src + (size_t)b * N_ * H_;
    for (int j = threadIdx.y; j < 32; j += 8)
        t[j][threadIdx.x] = S[(size_t)(k0 + j) * H_ + n0 + threadIdx.x] *
                            g_dinv[b * N_ + k0 + j];
    __syncthreads();
    for (int j = threadIdx.y; j < 32; j += 8) {
        float v = t[threadIdx.x][j];
        __nv_bfloat16 h, l;
        split1(v, h, l);
        size_t o = (size_t)(b * H_ + n0 + j) * N_ + k0 + threadIdx.x;
        g_Xthi[o] = h;
        g_Xtlo[o] = l;
    }
}

// ---------------------------------------------------------------------------
// HMMA GEMM: D[128 x 128] block = A[128 x KTOT] @ Bt[128 x KTOT]^T with
// bf16 hi/lo 3-MMA split. A smem [m][k], B smem [n][k], both 80B row stride.
// MODE: 0=agg (dinv, bf16 out), 1=fc relu f32 out, 2=fc relu bf16 out,
// 3=concat-fc relu f32 out.
// ---------------------------------------------------------------------------
#define LDSB 80          // smem row stride in bytes (40 bf16, conflict-free)
#define PART 10240       // 128 rows * 80 B
#define STAGE 40960      // Ahi, Alo, Bhi, Blo
#define SMEM_TOTAL (2 * STAGE)

template <int KTOT, int MODE>
__global__ void __launch_bounds__(256, 1) gemm_kernel(
    const __nv_bfloat16* __restrict__ A0hi, const __nv_bfloat16* __restrict__ A0lo,
    const __nv_bfloat16* __restrict__ A1hi, const __nv_bfloat16* __restrict__ A1lo,
    const __nv_bfloat16* __restrict__ Bhi,  const __nv_bfloat16* __restrict__ Blo,
    const float* __restrict__ bias, float* __restrict__ outf,
    __nv_bfloat16* __restrict__ ohi, __nv_bfloat16* __restrict__ olo)
{
    extern __shared__ char smem[];
    const uint32_t sb = s2u(smem);
    constexpr int NC = KTOT / 32;
    constexpr int LDA = (MODE == 0) ? N_ : H_;
    constexpr int LDB = (MODE == 0) ? N_ : ((MODE == 3) ? 2 * H_ : H_);

    const int tid = threadIdx.x, wid = tid >> 5, lane = tid & 31;
    const int b = blockIdx.z;
    const int m0 = blockIdx.y * 128;
    const int n0 = blockIdx.x * 128;
    const int warp_m = (wid & 3) * 32;   // 4 warps along M
    const int warp_n = (wid >> 2) * 64;  // 2 warps along N

    const size_t aoff = (MODE == 0) ? ((size_t)b * N_ * N_ + (size_t)m0 * N_)
                                    : ((size_t)m0 * H_);
    const size_t boff = (MODE == 0) ? (((size_t)b * H_ + n0) * N_)
                                    : ((size_t)n0 * LDB);

    float acc[2][8][4];
#pragma unroll
    for (int i = 0; i < 2; i++)
#pragma unroll
        for (int j = 0; j < 8; j++)
#pragma unroll
            for (int q = 0; q < 4; q++) acc[i][j][q] = 0.f;

    auto load_stage = [&](int s, int kc) {
        const int k0 = kc * 32;
        const __nv_bfloat16 *pAh, *pAl;
        int ka = k0;
        if (MODE == 3 && k0 >= H_) {
            pAh = A1hi + aoff; pAl = A1lo + aoff; ka = k0 - H_;
        } else {
            pAh = A0hi + aoff; pAl = A0lo + aoff;
        }
        const __nv_bfloat16* pBh = Bhi + boff;
        const __nv_bfloat16* pBl = Blo + boff;
        const uint32_t base = sb + s * STAGE;
#pragma unroll
        for (int c8 = 0; c8 < 8; c8++) {
            int c = c8 * 256 + tid;
            int part = c >> 9, row = (c >> 2) & 127, seg = c & 3;
            uint32_t dst = base + part * PART + row * LDSB + seg * 16;
            const __nv_bfloat16* src;
            if (part == 0)      src = pAh + (size_t)row * LDA + ka + seg * 8;
            else if (part == 1) src = pAl + (size_t)row * LDA + ka + seg * 8;
            else if (part == 2) src = pBh + (size_t)row * LDB + k0 + seg * 8;
            else                src = pBl + (size_t)row * LDB + k0 + seg * 8;
            cp16(dst, src);
        }
        CP_COMMIT();
    };

    // Lane-dependent ldmatrix offsets
    const uint32_t a_row = (uint32_t)(lane & 15);
    const uint32_t a_cb  = (uint32_t)((lane >> 4) * 16);  // bytes
    const uint32_t b_row = (uint32_t)((lane & 7) + ((lane & 16) ? 8 : 0));
    const uint32_t b_cb  = (uint32_t)((lane & 8) << 1);   // bytes

    // Prologue
    load_stage(0, 0);
    load_stage(1, 1);

    for (int k = 0; k < NC; k++) {
        if (k == NC - 1) { CP_WAIT0(); } else { CP_WAIT1(); }
        __syncthreads();

        const int s = k & 1;
        const uint32_t sA = sb + s * STAGE;
        const uint32_t sB = sA + 2 * PART;

#pragma unroll
        for (int ks = 0; ks < 2; ks++) {
            const uint32_t kb = ks * 32;  // bytes within row (16 bf16)
            uint32_t Ah[2][4], Al[2][4], Bh[8][2], Bl[8][2];
#pragma unroll
            for (int mi = 0; mi < 2; mi++) {
                uint32_t ra = (warp_m + mi * 16 + a_row) * LDSB + kb + a_cb;
                ldsm4(Ah[mi], sA + ra);
                ldsm4(Al[mi], sA + PART + ra);
            }
#pragma unroll
            for (int g = 0; g < 4; g++) {
                uint32_t rb = (warp_n + g * 16 + b_row) * LDSB + kb + b_cb;
                uint32_t t[4];
                ldsm4(t, sB + rb);
                Bh[2 * g][0] = t[0]; Bh[2 * g][1] = t[1];
                Bh[2 * g + 1][0] = t[2]; Bh[2 * g + 1][1] = t[3];
                ldsm4(t, sB + PART + rb);
                Bl[2 * g][0] = t[0]; Bl[2 * g][1] = t[1];
                Bl[2 * g + 1][0] = t[2]; Bl[2 * g + 1][1] = t[3];
            }
#pragma unroll
            for (int mi = 0; mi < 2; mi++)
#pragma unroll
                for (int ni = 0; ni < 8; ni++) {
                    mma_bf16(acc[mi][ni], Ah[mi], Bh[ni]);
                    mma_bf16(acc[mi][ni], Ah[mi], Bl[ni]);
                    mma_bf16(acc[mi][ni], Al[mi], Bh[ni]);
                }
        }

        if (k + 2 < NC) {
            __syncthreads();
            load_stage(s, k + 2);
        }
    }

    // ------------------------------------------------------------------ epi
    const int colb = n0 + warp_n + (lane & 3) * 2;  // global col (pair start)
#pragma unroll
    for (int mi = 0; mi < 2; mi++) {
#pragma unroll
        for (int p = 0; p < 2; p++) {
            const int m = m0 + warp_m + mi * 16 + (lane >> 2) + p * 8;
            if (MODE == 0) {
                const float dv = g_dinv[b * N_ + m];
                const size_t orow = ((size_t)(b * N_ + m)) * H_;
#pragma unroll
                for (int ni = 0; ni < 8; ni++) {
                    float f0 = acc[mi][ni][2 * p]     * dv;
                    float f1 = acc[mi][ni][2 * p + 1] * dv;
                    __nv_bfloat16 h0, l0, h1, l1;
                    split1(f0, h0, l0); split1(f1, h1, l1);
                    *(uint32_t*)(ohi + orow + colb + ni * 8) = packbf2(h0, h1);
                    *(uint32_t*)(olo + orow + colb + ni * 8) = packbf2(l0, l1);
                }
            } else if (MODE == 1 || MODE == 3) {
                const size_t orow = (size_t)m * H_;
#pragma unroll
                for (int ni = 0; ni < 8; ni++) {
                    int c = colb + ni * 8;
                    float2 o;
                    o.x = fmaxf(acc[mi][ni][2 * p]     + bias[c],     0.f);
                    o.y = fmaxf(acc[mi][ni][2 * p + 1] + bias[c + 1], 0.f);
                    *(float2*)(outf + orow + c) = o;
                }
            } else {  // MODE 2
                const size_t orow = (size_t)m * H_;
#pragma unroll
                for (int ni = 0; ni < 8; ni++) {
                    int c = colb + ni * 8;
                    float f0 = fmaxf(acc[mi][ni][2 * p]     + bias[c],     0.f);
                    float f1 = fmaxf(acc[mi][ni][2 * p + 1] + bias[c + 1], 0.f);
                    __nv_bfloat16 h0, l0, h1, l1;
                    split1(f0, h0, l0); split1(f1, h1, l1);
                    *(uint32_t*)(ohi + orow + c) = packbf2(h0, h1);
                    *(uint32_t*)(olo + orow + c) = packbf2(l0, l1);
                }
            }
        }
    }
}

// ---------------------------------------------------------------------------
// Launch
// ---------------------------------------------------------------------------
extern "C" void kernel_launch(void* const* d_in, const int* in_sizes, int n_in,
                              void* d_out, int out_size) {
    const float* node  = (const float*)d_in[0];
    const float* graph = (const float*)d_in[1];
    const float* W1    = (const float*)d_in[2];
    const float* b1    = (const float*)d_in[3];
    const float* W2    = (const float*)d_in[4];
    const float* b2    = (const float*)d_in[5];
    const float* Wout  = (const float*)d_in[6];
    const float* bout  = (const float*)d_in[7];
    float* out = (float*)d_out;

    __nv_bfloat16 *Ghi, *Glo, *Xthi, *Xtlo, *Chi, *Clo, *H2hi, *H2lo, *Nhi, *Nlo;
    __nv_bfloat16 *W1hi, *W1lo, *W2hi, *W2lo, *Wohi, *Wolo;
    float* H1;
    cudaGetSymbolAddress((void**)&Ghi, g_Ghi);
    cudaGetSymbolAddress((void**)&Glo, g_Glo);
    cudaGetSymbolAddress((void**)&Xthi, g_Xthi);
    cudaGetSymbolAddress((void**)&Xtlo, g_Xtlo);
    cudaGetSymbolAddress((void**)&Chi, g_Chi);
    cudaGetSymbolAddress((void**)&Clo, g_Clo);
    cudaGetSymbolAddress((void**)&H1, g_H1);
    cudaGetSymbolAddress((void**)&H2hi, g_H2hi);
    cudaGetSymbolAddress((void**)&H2lo, g_H2lo);
    cudaGetSymbolAddress((void**)&Nhi, g_Nhi);
    cudaGetSymbolAddress((void**)&Nlo, g_Nlo);
    cudaGetSymbolAddress((void**)&W1hi, g_W1hi);
    cudaGetSymbolAddress((void**)&W1lo, g_W1lo);
    cudaGetSymbolAddress((void**)&W2hi, g_W2hi);
    cudaGetSymbolAddress((void**)&W2lo, g_W2lo);
    cudaGetSymbolAddress((void**)&Wohi, g_Wohi);
    cudaGetSymbolAddress((void**)&Wolo, g_Wolo);

    cudaFuncSetAttribute(gemm_kernel<2048, 0>, cudaFuncAttributeMaxDynamicSharedMemorySize, SMEM_TOTAL);
    cudaFuncSetAttribute(gemm_kernel<256, 1>,  cudaFuncAttributeMaxDynamicSharedMemorySize, SMEM_TOTAL);
    cudaFuncSetAttribute(gemm_kernel<256, 2>,  cudaFuncAttributeMaxDynamicSharedMemorySize, SMEM_TOTAL);
    cudaFuncSetAttribute(gemm_kernel<512, 3>,  cudaFuncAttributeMaxDynamicSharedMemorySize, SMEM_TOTAL);

    dim3 blk(256);
    dim3 gAgg(H_ / 128, N_ / 128, B_);    // (2, 16, 8)
    dim3 gFc(H_ / 128, M_TOT / 128, 1);   // (2, 128)

    // Convert inputs
    graph_conv<<<B_ * N_, 256>>>(graph);
    split_conv<<<(M_TOT * H_) / 1024, 256>>>(node, Nhi, Nlo);
    split_conv<<<(H_ * H_) / 1024, 256>>>(W1, W1hi, W1lo);
    split_conv<<<(H_ * H_) / 1024, 256>>>(W2, W2hi, W2lo);
    split_conv<<<(H_ * 2 * H_) / 1024, 256>>>(Wout, Wohi, Wolo);
    xt_build<<<dim3(64, 8, 8), dim3(32, 8)>>>(node);

    // Layer 1
    gemm_kernel<2048, 0><<<gAgg, blk, SMEM_TOTAL>>>(Ghi, Glo, nullptr, nullptr,
                                                    Xthi, Xtlo, nullptr, nullptr, Chi, Clo);
    gemm_kernel<256, 1><<<gFc, blk, SMEM_TOTAL>>>(Chi, Clo, nullptr, nullptr,
                                                  W1hi, W1lo, b1, H1, nullptr, nullptr);
    xt_build<<<dim3(64, 8, 8), dim3(32, 8)>>>(H1);

    // Layer 2
    gemm_kernel<2048, 0><<<gAgg, blk, SMEM_TOTAL>>>(Ghi, Glo, nullptr, nullptr,
                                                    Xthi, Xtlo, nullptr, nullptr, Chi, Clo);
    gemm_kernel<256, 2><<<gFc, blk, SMEM_TOTAL>>>(Chi, Clo, nullptr, nullptr,
                                                  W2hi, W2lo, b2, nullptr, H2hi, H2lo);

    // Output: concat([node, h]) @ Wout^T + bout, relu
    gemm_kernel<512, 3><<<gFc, blk, SMEM_TOTAL>>>(Nhi, Nlo, H2hi, H2lo,
                                                  Wohi, Wolo, bout, out, nullptr, nullptr);
}

// round 4
// speedup vs baseline: 2.5734x; 1.0730x over previous
#include <cuda_runtime.h>
#include <cuda_bf16.h>
#include <cstdint>

#define B_ 8
#define N_ 2048
#define H_ 256
#define M_TOT (B_ * N_)  // 16384

// ---------------------------------------------------------------------------
// Device scratch (allocation-free rule: __device__ globals)
// ---------------------------------------------------------------------------
__device__ __nv_bfloat16 g_Ghi[(size_t)B_ * N_ * N_];
__device__ __nv_bfloat16 g_Glo[(size_t)B_ * N_ * N_];
__device__ __nv_bfloat16 g_Xthi[(size_t)B_ * H_ * N_];
__device__ __nv_bfloat16 g_Xtlo[(size_t)B_ * H_ * N_];
__device__ __nv_bfloat16 g_Chi[(size_t)M_TOT * H_];
__device__ __nv_bfloat16 g_Clo[(size_t)M_TOT * H_];
__device__ float         g_H1[(size_t)M_TOT * H_];
__device__ __nv_bfloat16 g_H2hi[(size_t)M_TOT * H_];
__device__ __nv_bfloat16 g_H2lo[(size_t)M_TOT * H_];
__device__ __nv_bfloat16 g_Nhi[(size_t)M_TOT * H_];
__device__ __nv_bfloat16 g_Nlo[(size_t)M_TOT * H_];
__device__ __nv_bfloat16 g_W1hi[H_ * H_], g_W1lo[H_ * H_];
__device__ __nv_bfloat16 g_W2hi[H_ * H_], g_W2lo[H_ * H_];
__device__ __nv_bfloat16 g_Wohi[H_ * 2 * H_], g_Wolo[H_ * 2 * H_];
__device__ float g_dinv[B_ * N_];

// ---------------------------------------------------------------------------
// PTX helpers (sm_80-portable only)
// ---------------------------------------------------------------------------
__device__ __forceinline__ uint32_t s2u(const void* p) {
    uint32_t r;
    asm("{ .reg .u64 t; cvta.to.shared.u64 t, %1; cvt.u32.u64 %0, t; }"
        : "=r"(r) : "l"(p));
    return r;
}
__device__ __forceinline__ void cp16(uint32_t s, const void* g) {
    asm volatile("cp.async.cg.shared.global [%0], [%1], 16;" :: "r"(s), "l"(g) : "memory");
}
#define CP_COMMIT() asm volatile("cp.async.commit_group;" ::: "memory")
#define CP_WAIT1()  asm volatile("cp.async.wait_group 1;" ::: "memory")
#define CP_WAIT0()  asm volatile("cp.async.wait_group 0;" ::: "memory")

__device__ __forceinline__ void ldsm4(uint32_t* r, uint32_t a) {
    asm volatile("ldmatrix.sync.aligned.m8n8.x4.shared.b16 {%0,%1,%2,%3}, [%4];"
                 : "=r"(r[0]), "=r"(r[1]), "=r"(r[2]), "=r"(r[3]) : "r"(a));
}
__device__ __forceinline__ void mma_bf16(float* d, const uint32_t* a, const uint32_t* b) {
    asm volatile(
        "mma.sync.aligned.m16n8k16.row.col.f32.bf16.bf16.f32 "
        "{%0,%1,%2,%3}, {%4,%5,%6,%7}, {%8,%9}, {%0,%1,%2,%3};"
        : "+f"(d[0]), "+f"(d[1]), "+f"(d[2]), "+f"(d[3])
        : "r"(a[0]), "r"(a[1]), "r"(a[2]), "r"(a[3]), "r"(b[0]), "r"(b[1]));
}

__device__ __forceinline__ void split1(float v, __nv_bfloat16& h, __nv_bfloat16& l) {
    h = __float2bfloat16(v);
    l = __float2bfloat16(v - __bfloat162float(h));
}
__device__ __forceinline__ uint32_t packbf2(__nv_bfloat16 a, __nv_bfloat16 b) {
    __nv_bfloat162 t(a, b);
    return *reinterpret_cast<uint32_t*>(&t);
}

// ---------------------------------------------------------------------------
// graph -> bf16 hi/lo + fused row-sum -> dinv
// ---------------------------------------------------------------------------
__global__ void graph_conv(const float* __restrict__ graph) {
    int row = blockIdx.x;
    size_t base = (size_t)row * N_;
    float s = 0.f;
#pragma unroll
    for (int it = 0; it < 2; it++) {
        int j = (threadIdx.x + it * 256) * 4;
        float4 v = *(const float4*)(graph + base + j);
        s += v.x + v.y + v.z + v.w;
        __nv_bfloat16 h0, l0, h1, l1, h2, l2, h3, l3;
        split1(v.x, h0, l0); split1(v.y, h1, l1);
        split1(v.z, h2, l2); split1(v.w, h3, l3);
        *(uint2*)(g_Ghi + base + j) = make_uint2(packbf2(h0, h1), packbf2(h2, h3));
        *(uint2*)(g_Glo + base + j) = make_uint2(packbf2(l0, l1), packbf2(l2, l3));
    }
#pragma unroll
    for (int o = 16; o; o >>= 1) s += __shfl_down_sync(0xffffffffu, s, o);
    __shared__ float ws[8];
    int lane = threadIdx.x & 31, w = threadIdx.x >> 5;
    if (lane == 0) ws[w] = s;
    __syncthreads();
    if (threadIdx.x == 0) {
        float t = 0.f;
#pragma unroll
        for (int i = 0; i < 8; i++) t += ws[i];
        g_dinv[row] = rsqrtf(t);
    }
}

// ---------------------------------------------------------------------------
// fp32 -> bf16 hi/lo split (elementwise)
// ---------------------------------------------------------------------------
__global__ void split_conv(const float* __restrict__ src, __nv_bfloat16* __restrict__ hi,
                           __nv_bfloat16* __restrict__ lo) {
    size_t j = ((size_t)blockIdx.x * 256 + threadIdx.x) * 4;
    float4 v = *(const float4*)(src + j);
    __nv_bfloat16 h0, l0, h1, l1, h2, l2, h3, l3;
    split1(v.x, h0, l0); split1(v.y, h1, l1);
    split1(v.z, h2, l2); split1(v.w, h3, l3);
    *(uint2*)(hi + j) = make_uint2(packbf2(h0, h1), packbf2(h2, h3));
    *(uint2*)(lo + j) = make_uint2(packbf2(l0, l1), packbf2(l2, l3));
}

// ---------------------------------------------------------------------------
// Xt[b][n][k] = src[b][k][n] * dinv[b][k], split bf16 hi/lo
// ---------------------------------------------------------------------------
__global__ void xt_build(const float* __restrict__ src) {
    __shared__ float t[32][33];
    int b = blockIdx.z, k0 = blockIdx.x * 32, n0 = blockIdx.y * 32;
    const float* S = src + (size_t)b * N_ * H_;
    for (int j = threadIdx.y; j < 32; j += 8)
        t[j][threadIdx.x] = S[(size_t)(k0 + j) * H_ + n0 + threadIdx.x] *
                            g_dinv[b * N_ + k0 + j];
    __syncthreads();
    for (int j = threadIdx.y; j < 32; j += 8) {
        float v = t[threadIdx.x][j];
        __nv_bfloat16 h, l;
        split1(v, h, l);
        size_t o = (size_t)(b * H_ + n0 + j) * N_ + k0 + threadIdx.x;
        g_Xthi[o] = h;
        g_Xtlo[o] = l;
    }
}

// ===========================================================================
// Agg GEMM: C[b, m0:m0+128, 0:256] = dinv .* (G @ Xt^T), bf16 hi/lo 3-MMA.
// BM=128, BN=256(=H), BK=32, 512 threads (16 warps 4x4, warp tile 32x64).
// ===========================================================================
#define LDSB 80
#define A_PART 10240          // 128 * 80
#define B_PART 20480          // 256 * 80
#define AGG_STAGE (2 * A_PART + 2 * B_PART)   // 61440
#define AGG_SMEM (2 * AGG_STAGE)              // 122880

__global__ void __launch_bounds__(512, 1) agg_gemm(
    const __nv_bfloat16* __restrict__ Ghi, const __nv_bfloat16* __restrict__ Glo,
    const __nv_bfloat16* __restrict__ Xthi, const __nv_bfloat16* __restrict__ Xtlo,
    __nv_bfloat16* __restrict__ ohi, __nv_bfloat16* __restrict__ olo)
{
    extern __shared__ char smem[];
    const uint32_t sb = s2u(smem);
    constexpr int NC = N_ / 32;  // 64

    const int tid = threadIdx.x, wid = tid >> 5, lane = tid & 31;
    const int b = blockIdx.z;
    const int m0 = blockIdx.y * 128;
    const int warp_m = (wid & 3) * 32;
    const int warp_n = (wid >> 2) * 64;

    const __nv_bfloat16* pAh = Ghi + (size_t)b * N_ * N_ + (size_t)m0 * N_;
    const __nv_bfloat16* pAl = Glo + (size_t)b * N_ * N_ + (size_t)m0 * N_;
    const __nv_bfloat16* pBh = Xthi + (size_t)b * H_ * N_;
    const __nv_bfloat16* pBl = Xtlo + (size_t)b * H_ * N_;

    float acc[2][8][4];
#pragma unroll
    for (int i = 0; i < 2; i++)
#pragma unroll
        for (int j = 0; j < 8; j++)
#pragma unroll
            for (int q = 0; q < 4; q++) acc[i][j][q] = 0.f;

    auto load_stage = [&](int s, int kc) {
        const int k0 = kc * 32;
        const uint32_t base = sb + s * AGG_STAGE;
        // A: 1024 cp16 (2 parts x 128 rows x 4 segs), B: 2048 cp16
#pragma unroll
        for (int it = 0; it < 6; it++) {
            int c = it * 512 + tid;
            if (c < 1024) {
                int part = c >> 9, row = (c >> 2) & 127, seg = c & 3;
                uint32_t dst = base + part * A_PART + row * LDSB + seg * 16;
                const __nv_bfloat16* src = (part ? pAl : pAh) + (size_t)row * N_ + k0 + seg * 8;
                cp16(dst, src);
            } else {
                int cb = c - 1024;
                int part = cb >> 10, row = (cb >> 2) & 255, seg = cb & 3;
                uint32_t dst = base + 2 * A_PART + part * B_PART + row * LDSB + seg * 16;
                const __nv_bfloat16* src = (part ? pBl : pBh) + (size_t)row * N_ + k0 + seg * 8;
                cp16(dst, src);
            }
        }
        CP_COMMIT();
    };

    const uint32_t a_row = (uint32_t)(lane & 15);
    const uint32_t a_cb  = (uint32_t)((lane >> 4) * 16);
    const uint32_t b_row = (uint32_t)((lane & 7) + ((lane & 16) ? 8 : 0));
    const uint32_t b_cb  = (uint32_t)((lane & 8) << 1);

    load_stage(0, 0);
    load_stage(1, 1);

    for (int k = 0; k < NC; k++) {
        if (k == NC - 1) { CP_WAIT0(); } else { CP_WAIT1(); }
        __syncthreads();

        const int s = k & 1;
        const uint32_t sA = sb + s * AGG_STAGE;
        const uint32_t sB = sA + 2 * A_PART;

#pragma unroll
        for (int ks = 0; ks < 2; ks++) {
            const uint32_t kb = ks * 32;
            uint32_t Ah[2][4], Al[2][4];
#pragma unroll
            for (int mi = 0; mi < 2; mi++) {
                uint32_t ra = (warp_m + mi * 16 + a_row) * LDSB + kb + a_cb;
                ldsm4(Ah[mi], sA + ra);
                ldsm4(Al[mi], sA + A_PART + ra);
            }
#pragma unroll
            for (int g = 0; g < 4; g++) {
                uint32_t rb = (warp_n + g * 16 + b_row) * LDSB + kb + b_cb;
                uint32_t th[4], tl[4];
                ldsm4(th, sB + rb);
                ldsm4(tl, sB + B_PART + rb);
#pragma unroll
                for (int mi = 0; mi < 2; mi++) {
                    mma_bf16(acc[mi][2 * g],     Ah[mi], th);
                    mma_bf16(acc[mi][2 * g],     Ah[mi], tl);
                    mma_bf16(acc[mi][2 * g],     Al[mi], th);
                    mma_bf16(acc[mi][2 * g + 1], Ah[mi], th + 2);
                    mma_bf16(acc[mi][2 * g + 1], Ah[mi], tl + 2);
                    mma_bf16(acc[mi][2 * g + 1], Al[mi], th + 2);
                }
            }
        }

        if (k + 2 < NC) {
            __syncthreads();
            load_stage(s, k + 2);
        }
    }

    // epilogue: dinv row scale, split to bf16 hi/lo
    const int colb = warp_n + (lane & 3) * 2;
#pragma unroll
    for (int mi = 0; mi < 2; mi++) {
#pragma unroll
        for (int p = 0; p < 2; p++) {
            const int m = m0 + warp_m + mi * 16 + (lane >> 2) + p * 8;
            const float dv = g_dinv[b * N_ + m];
            const size_t orow = ((size_t)(b * N_ + m)) * H_;
#pragma unroll
            for (int ni = 0; ni < 8; ni++) {
                float f0 = acc[mi][ni][2 * p]     * dv;
                float f1 = acc[mi][ni][2 * p + 1] * dv;
                __nv_bfloat16 h0, l0, h1, l1;
                split1(f0, h0, l0); split1(f1, h1, l1);
                *(uint32_t*)(ohi + orow + colb + ni * 8) = packbf2(h0, h1);
                *(uint32_t*)(olo + orow + colb + ni * 8) = packbf2(l0, l1);
            }
        }
    }
}

// ===========================================================================
// FC GEMM (unchanged from R3): 128x128 tiles, 256 threads.
// MODE: 1=fc relu f32 out, 2=fc relu bf16 out, 3=concat-fc relu f32 out.
// ===========================================================================
#define FPART 10240
#define FSTAGE 40960
#define FC_SMEM (2 * FSTAGE)

template <int KTOT, int MODE>
__global__ void __launch_bounds__(256, 1) fc_gemm(
    const __nv_bfloat16* __restrict__ A0hi, const __nv_bfloat16* __restrict__ A0lo,
    const __nv_bfloat16* __restrict__ A1hi, const __nv_bfloat16* __restrict__ A1lo,
    const __nv_bfloat16* __restrict__ Bhi,  const __nv_bfloat16* __restrict__ Blo,
    const float* __restrict__ bias, float* __restrict__ outf,
    __nv_bfloat16* __restrict__ ohi, __nv_bfloat16* __restrict__ olo)
{
    extern __shared__ char smem[];
    const uint32_t sb = s2u(smem);
    constexpr int NC = KTOT / 32;
    constexpr int LDB = (MODE == 3) ? 2 * H_ : H_;

    const int tid = threadIdx.x, wid = tid >> 5, lane = tid & 31;
    const int m0 = blockIdx.y * 128;
    const int n0 = blockIdx.x * 128;
    const int warp_m = (wid & 3) * 32;
    const int warp_n = (wid >> 2) * 64;

    const size_t aoff = (size_t)m0 * H_;
    const size_t boff = (size_t)n0 * LDB;

    float acc[2][8][4];
#pragma unroll
    for (int i = 0; i < 2; i++)
#pragma unroll
        for (int j = 0; j < 8; j++)
#pragma unroll
            for (int q = 0; q < 4; q++) acc[i][j][q] = 0.f;

    auto load_stage = [&](int s, int kc) {
        const int k0 = kc * 32;
        const __nv_bfloat16 *pAh, *pAl;
        int ka = k0;
        if (MODE == 3 && k0 >= H_) {
            pAh = A1hi + aoff; pAl = A1lo + aoff; ka = k0 - H_;
        } else {
            pAh = A0hi + aoff; pAl = A0lo + aoff;
        }
        const __nv_bfloat16* pBh = Bhi + boff;
        const __nv_bfloat16* pBl = Blo + boff;
        const uint32_t base = sb + s * FSTAGE;
#pragma unroll
        for (int c8 = 0; c8 < 8; c8++) {
            int c = c8 * 256 + tid;
            int part = c >> 9, row = (c >> 2) & 127, seg = c & 3;
            uint32_t dst = base + part * FPART + row * LDSB + seg * 16;
            const __nv_bfloat16* src;
            if (part == 0)      src = pAh + (size_t)row * H_ + ka + seg * 8;
            else if (part == 1) src = pAl + (size_t)row * H_ + ka + seg * 8;
            else if (part == 2) src = pBh + (size_t)row * LDB + k0 + seg * 8;
            else                src = pBl + (size_t)row * LDB + k0 + seg * 8;
            cp16(dst, src);
        }
        CP_COMMIT();
    };

    const uint32_t a_row = (uint32_t)(lane & 15);
    const uint32_t a_cb  = (uint32_t)((lane >> 4) * 16);
    const uint32_t b_row = (uint32_t)((lane & 7) + ((lane & 16) ? 8 : 0));
    const uint32_t b_cb  = (uint32_t)((lane & 8) << 1);

    load_stage(0, 0);
    load_stage(1, 1);

    for (int k = 0; k < NC; k++) {
        if (k == NC - 1) { CP_WAIT0(); } else { CP_WAIT1(); }
        __syncthreads();

        const int s = k & 1;
        const uint32_t sA = sb + s * FSTAGE;
        const uint32_t sB = sA + 2 * FPART;

#pragma unroll
        for (int ks = 0; ks < 2; ks++) {
            const uint32_t kb = ks * 32;
            uint32_t Ah[2][4], Al[2][4];
#pragma unroll
            for (int mi = 0; mi < 2; mi++) {
                uint32_t ra = (warp_m + mi * 16 + a_row) * LDSB + kb + a_cb;
                ldsm4(Ah[mi], sA + ra);
                ldsm4(Al[mi], sA + FPART + ra);
            }
#pragma unroll
            for (int g = 0; g < 4; g++) {
                uint32_t rb = (warp_n + g * 16 + b_row) * LDSB + kb + b_cb;
                uint32_t th[4], tl[4];
                ldsm4(th, sB + rb);
                ldsm4(tl, sB + FPART + rb);
#pragma unroll
                for (int mi = 0; mi < 2; mi++) {
                    mma_bf16(acc[mi][2 * g],     Ah[mi], th);
                    mma_bf16(acc[mi][2 * g],     Ah[mi], tl);
                    mma_bf16(acc[mi][2 * g],     Al[mi], th);
                    mma_bf16(acc[mi][2 * g + 1], Ah[mi], th + 2);
                    mma_bf16(acc[mi][2 * g + 1], Ah[mi], tl + 2);
                    mma_bf16(acc[mi][2 * g + 1], Al[mi], th + 2);
                }
            }
        }

        if (k + 2 < NC) {
            __syncthreads();
            load_stage(s, k + 2);
        }
    }

    const int colb = n0 + warp_n + (lane & 3) * 2;
#pragma unroll
    for (int mi = 0; mi < 2; mi++) {
#pragma unroll
        for (int p = 0; p < 2; p++) {
            const int m = m0 + warp_m + mi * 16 + (lane >> 2) + p * 8;
            const size_t orow = (size_t)m * H_;
            if (MODE == 1 || MODE == 3) {
#pragma unroll
                for (int ni = 0; ni < 8; ni++) {
                    int c = colb + ni * 8;
                    float2 o;
                    o.x = fmaxf(acc[mi][ni][2 * p]     + bias[c],     0.f);
                    o.y = fmaxf(acc[mi][ni][2 * p + 1] + bias[c + 1], 0.f);
                    *(float2*)(outf + orow + c) = o;
                }
            } else {
#pragma unroll
                for (int ni = 0; ni < 8; ni++) {
                    int c = colb + ni * 8;
                    float f0 = fmaxf(acc[mi][ni][2 * p]     + bias[c],     0.f);
                    float f1 = fmaxf(acc[mi][ni][2 * p + 1] + bias[c + 1], 0.f);
                    __nv_bfloat16 h0, l0, h1, l1;
                    split1(f0, h0, l0); split1(f1, h1, l1);
                    *(uint32_t*)(ohi + orow + c) = packbf2(h0, h1);
                    *(uint32_t*)(olo + orow + c) = packbf2(l0, l1);
                }
            }
        }
    }
}

// ---------------------------------------------------------------------------
// Launch
// ---------------------------------------------------------------------------
extern "C" void kernel_launch(void* const* d_in, const int* in_sizes, int n_in,
                              void* d_out, int out_size) {
    const float* node  = (const float*)d_in[0];
    const float* graph = (const float*)d_in[1];
    const float* W1    = (const float*)d_in[2];
    const float* b1    = (const float*)d_in[3];
    const float* W2    = (const float*)d_in[4];
    const float* b2    = (const float*)d_in[5];
    const float* Wout  = (const float*)d_in[6];
    const float* bout  = (const float*)d_in[7];
    float* out = (float*)d_out;

    __nv_bfloat16 *Ghi, *Glo, *Xthi, *Xtlo, *Chi, *Clo, *H2hi, *H2lo, *Nhi, *Nlo;
    __nv_bfloat16 *W1hi, *W1lo, *W2hi, *W2lo, *Wohi, *Wolo;
    float* H1;
    cudaGetSymbolAddress((void**)&Ghi, g_Ghi);
    cudaGetSymbolAddress((void**)&Glo, g_Glo);
    cudaGetSymbolAddress((void**)&Xthi, g_Xthi);
    cudaGetSymbolAddress((void**)&Xtlo, g_Xtlo);
    cudaGetSymbolAddress((void**)&Chi, g_Chi);
    cudaGetSymbolAddress((void**)&Clo, g_Clo);
    cudaGetSymbolAddress((void**)&H1, g_H1);
    cudaGetSymbolAddress((void**)&H2hi, g_H2hi);
    cudaGetSymbolAddress((void**)&H2lo, g_H2lo);
    cudaGetSymbolAddress((void**)&Nhi, g_Nhi);
    cudaGetSymbolAddress((void**)&Nlo, g_Nlo);
    cudaGetSymbolAddress((void**)&W1hi, g_W1hi);
    cudaGetSymbolAddress((void**)&W1lo, g_W1lo);
    cudaGetSymbolAddress((void**)&W2hi, g_W2hi);
    cudaGetSymbolAddress((void**)&W2lo, g_W2lo);
    cudaGetSymbolAddress((void**)&Wohi, g_Wohi);
    cudaGetSymbolAddress((void**)&Wolo, g_Wolo);

    cudaFuncSetAttribute(agg_gemm, cudaFuncAttributeMaxDynamicSharedMemorySize, AGG_SMEM);
    cudaFuncSetAttribute(fc_gemm<256, 1>, cudaFuncAttributeMaxDynamicSharedMemorySize, FC_SMEM);
    cudaFuncSetAttribute(fc_gemm<256, 2>, cudaFuncAttributeMaxDynamicSharedMemorySize, FC_SMEM);
    cudaFuncSetAttribute(fc_gemm<512, 3>, cudaFuncAttributeMaxDynamicSharedMemorySize, FC_SMEM);

    dim3 gAgg(1, N_ / 128, B_);           // (1, 16, 8)
    dim3 gFc(H_ / 128, M_TOT / 128, 1);   // (2, 128)
    dim3 gXt(64, 8, 8), bXt(32, 8);

    // 0..4: conversions (agg layer-1 lands at launch index 5 for ncu -s 5)
    graph_conv<<<B_ * N_, 256>>>(graph);                                   // 0
    xt_build<<<gXt, bXt>>>(node);                                          // 1
    split_conv<<<(M_TOT * H_) / 1024, 256>>>(node, Nhi, Nlo);              // 2
    split_conv<<<(H_ * H_) / 1024, 256>>>(W1, W1hi, W1lo);                 // 3
    split_conv<<<(H_ * H_) / 1024, 256>>>(W2, W2hi, W2lo);                 // 4

    // Layer 1
    agg_gemm<<<gAgg, 512, AGG_SMEM>>>(Ghi, Glo, Xthi, Xtlo, Chi, Clo);     // 5
    fc_gemm<256, 1><<<gFc, 256, FC_SMEM>>>(Chi, Clo, nullptr, nullptr,
                                           W1hi, W1lo, b1, H1, nullptr, nullptr);
    xt_build<<<gXt, bXt>>>(H1);

    // Layer 2
    agg_gemm<<<gAgg, 512, AGG_SMEM>>>(Ghi, Glo, Xthi, Xtlo, Chi, Clo);
    fc_gemm<256, 2><<<gFc, 256, FC_SMEM>>>(Chi, Clo, nullptr, nullptr,
                                           W2hi, W2lo, b2, nullptr, H2hi, H2lo);

    // Output
    split_conv<<<(H_ * 2 * H_) / 1024, 256>>>(Wout, Wohi, Wolo);
    fc_gemm<512, 3><<<gFc, 256, FC_SMEM>>>(Nhi, Nlo, H2hi, H2lo,
                                           Wohi, Wolo, bout, out, nullptr, nullptr);
}

// round 5
// speedup vs baseline: 2.7145x; 1.0548x over previous
#include <cuda_runtime.h>
#include <cuda_bf16.h>
#include <cstdint>

#define B_ 8
#define N_ 2048
#define H_ 256
#define M_TOT (B_ * N_)  // 16384

// ---------------------------------------------------------------------------
// Device scratch
// ---------------------------------------------------------------------------
__device__ __nv_bfloat16 g_Ghi[(size_t)B_ * N_ * N_];
__device__ __nv_bfloat16 g_Glo[(size_t)B_ * N_ * N_];
__device__ __nv_bfloat16 g_Xthi[(size_t)B_ * H_ * N_];
__device__ __nv_bfloat16 g_Xtlo[(size_t)B_ * H_ * N_];
__device__ __nv_bfloat16 g_Chi[(size_t)M_TOT * H_];
__device__ __nv_bfloat16 g_Clo[(size_t)M_TOT * H_];
__device__ float         g_H1[(size_t)M_TOT * H_];
__device__ __nv_bfloat16 g_H2hi[(size_t)M_TOT * H_];
__device__ __nv_bfloat16 g_H2lo[(size_t)M_TOT * H_];
__device__ __nv_bfloat16 g_Nhi[(size_t)M_TOT * H_];
__device__ __nv_bfloat16 g_Nlo[(size_t)M_TOT * H_];
__device__ __nv_bfloat16 g_W1hi[H_ * H_], g_W1lo[H_ * H_];
__device__ __nv_bfloat16 g_W2hi[H_ * H_], g_W2lo[H_ * H_];
__device__ __nv_bfloat16 g_Wohi[H_ * 2 * H_], g_Wolo[H_ * 2 * H_];
__device__ float g_dinv[B_ * N_];

// ---------------------------------------------------------------------------
// PTX helpers (sm_80-portable only)
// ---------------------------------------------------------------------------
__device__ __forceinline__ uint32_t s2u(const void* p) {
    uint32_t r;
    asm("{ .reg .u64 t; cvta.to.shared.u64 t, %1; cvt.u32.u64 %0, t; }"
        : "=r"(r) : "l"(p));
    return r;
}
__device__ __forceinline__ void cp16(uint32_t s, const void* g) {
    asm volatile("cp.async.cg.shared.global [%0], [%1], 16;" :: "r"(s), "l"(g) : "memory");
}
#define CP_COMMIT() asm volatile("cp.async.commit_group;" ::: "memory")
#define CP_WAITG1() asm volatile("cp.async.wait_group 1;" ::: "memory")

__device__ __forceinline__ void ldsm4(uint32_t* r, uint32_t a) {
    asm volatile("ldmatrix.sync.aligned.m8n8.x4.shared.b16 {%0,%1,%2,%3}, [%4];"
                 : "=r"(r[0]), "=r"(r[1]), "=r"(r[2]), "=r"(r[3]) : "r"(a));
}
__device__ __forceinline__ void mma_bf16(float* d, const uint32_t* a, const uint32_t* b) {
    asm volatile(
        "mma.sync.aligned.m16n8k16.row.col.f32.bf16.bf16.f32 "
        "{%0,%1,%2,%3}, {%4,%5,%6,%7}, {%8,%9}, {%0,%1,%2,%3};"
        : "+f"(d[0]), "+f"(d[1]), "+f"(d[2]), "+f"(d[3])
        : "r"(a[0]), "r"(a[1]), "r"(a[2]), "r"(a[3]), "r"(b[0]), "r"(b[1]));
}

__device__ __forceinline__ void split1(float v, __nv_bfloat16& h, __nv_bfloat16& l) {
    h = __float2bfloat16(v);
    l = __float2bfloat16(v - __bfloat162float(h));
}
__device__ __forceinline__ uint32_t packbf2(__nv_bfloat16 a, __nv_bfloat16 b) {
    __nv_bfloat162 t(a, b);
    return *reinterpret_cast<uint32_t*>(&t);
}

// ---------------------------------------------------------------------------
// graph -> bf16 hi/lo + fused row-sum -> dinv
// ---------------------------------------------------------------------------
__global__ void graph_conv(const float* __restrict__ graph) {
    int row = blockIdx.x;
    size_t base = (size_t)row * N_;
    float s = 0.f;
#pragma unroll
    for (int it = 0; it < 2; it++) {
        int j = (threadIdx.x + it * 256) * 4;
        float4 v = *(const float4*)(graph + base + j);
        s += v.x + v.y + v.z + v.w;
        __nv_bfloat16 h0, l0, h1, l1, h2, l2, h3, l3;
        split1(v.x, h0, l0); split1(v.y, h1, l1);
        split1(v.z, h2, l2); split1(v.w, h3, l3);
        *(uint2*)(g_Ghi + base + j) = make_uint2(packbf2(h0, h1), packbf2(h2, h3));
        *(uint2*)(g_Glo + base + j) = make_uint2(packbf2(l0, l1), packbf2(l2, l3));
    }
#pragma unroll
    for (int o = 16; o; o >>= 1) s += __shfl_down_sync(0xffffffffu, s, o);
    __shared__ float ws[8];
    int lane = threadIdx.x & 31, w = threadIdx.x >> 5;
    if (lane == 0) ws[w] = s;
    __syncthreads();
    if (threadIdx.x == 0) {
        float t = 0.f;
#pragma unroll
        for (int i = 0; i < 8; i++) t += ws[i];
        g_dinv[row] = rsqrtf(t);
    }
}

// ---------------------------------------------------------------------------
// fp32 -> bf16 hi/lo split
// ---------------------------------------------------------------------------
__global__ void split_conv(const float* __restrict__ src, __nv_bfloat16* __restrict__ hi,
                           __nv_bfloat16* __restrict__ lo) {
    size_t j = ((size_t)blockIdx.x * 256 + threadIdx.x) * 4;
    float4 v = *(const float4*)(src + j);
    __nv_bfloat16 h0, l0, h1, l1, h2, l2, h3, l3;
    split1(v.x, h0, l0); split1(v.y, h1, l1);
    split1(v.z, h2, l2); split1(v.w, h3, l3);
    *(uint2*)(hi + j) = make_uint2(packbf2(h0, h1), packbf2(h2, h3));
    *(uint2*)(lo + j) = make_uint2(packbf2(l0, l1), packbf2(l2, l3));
}

// ---------------------------------------------------------------------------
// Xt[b][n][k] = src[b][k][n] * dinv[b][k], split bf16 hi/lo
// ---------------------------------------------------------------------------
__global__ void xt_build(const float* __restrict__ src) {
    __shared__ float t[32][33];
    int b = blockIdx.z, k0 = blockIdx.x * 32, n0 = blockIdx.y * 32;
    const float* S = src + (size_t)b * N_ * H_;
    for (int j = threadIdx.y; j < 32; j += 8)
        t[j][threadIdx.x] = S[(size_t)(k0 + j) * H_ + n0 + threadIdx.x] *
                            g_dinv[b * N_ + k0 + j];
    __syncthreads();
    for (int j = threadIdx.y; j < 32; j += 8) {
        float v = t[threadIdx.x][j];
        __nv_bfloat16 h, l;
        split1(v, h, l);
        size_t o = (size_t)(b * H_ + n0 + j) * N_ + k0 + threadIdx.x;
        g_Xthi[o] = h;
        g_Xtlo[o] = l;
    }
}

// ===========================================================================
// Unified GEMM: D[128 x 256] = A[128 x KTOT] @ B[256 x KTOT]^T, bf16 hi/lo
// 3-MMA split. 512 threads (16 warps 4x4), 3-stage cp.async pipeline,
// ONE __syncthreads per k-chunk.
// MODE 0: agg   (A=G[b], B=Xt[b], epilogue: *dinv -> bf16 hi/lo)
// MODE 1: fc    (A=C,    B=W,     epilogue: +bias relu -> f32)
// MODE 2: fc    (A=C,    B=W,     epilogue: +bias relu -> bf16 hi/lo)
// MODE 3: cfc   (A=[N|H2], B=Wout,epilogue: +bias relu -> f32)
// ===========================================================================
#define LDSB 80
#define A_PART 10240                          // 128 * 80
#define B_PART 20480                          // 256 * 80
#define G_STAGE (2 * A_PART + 2 * B_PART)     // 61440
#define NSTAGE 3
#define G_SMEM (NSTAGE * G_STAGE)             // 184320

template <int KTOT, int MODE>
__global__ void __launch_bounds__(512, 1) gemm512(
    const __nv_bfloat16* __restrict__ A0hi, const __nv_bfloat16* __restrict__ A0lo,
    const __nv_bfloat16* __restrict__ A1hi, const __nv_bfloat16* __restrict__ A1lo,
    const __nv_bfloat16* __restrict__ Bhi,  const __nv_bfloat16* __restrict__ Blo,
    const float* __restrict__ bias, float* __restrict__ outf,
    __nv_bfloat16* __restrict__ ohi, __nv_bfloat16* __restrict__ olo)
{
    extern __shared__ char smem[];
    const uint32_t sb = s2u(smem);
    constexpr int NC = KTOT / 32;
    constexpr int LDA = (MODE == 0) ? N_ : H_;
    constexpr int LDB = (MODE == 0) ? N_ : ((MODE == 3) ? 2 * H_ : H_);

    const int tid = threadIdx.x, wid = tid >> 5, lane = tid & 31;
    const int b = (MODE == 0) ? blockIdx.z : 0;
    const int m0 = blockIdx.y * 128;
    const int warp_m = (wid & 3) * 32;
    const int warp_n = (wid >> 2) * 64;

    const size_t aoff = (MODE == 0) ? ((size_t)b * N_ * N_ + (size_t)m0 * N_)
                                    : ((size_t)m0 * H_);
    const size_t boff = (MODE == 0) ? ((size_t)b * H_ * N_) : 0;

    const __nv_bfloat16* pBh = Bhi + boff;
    const __nv_bfloat16* pBl = Blo + boff;

    float acc[2][8][4];
#pragma unroll
    for (int i = 0; i < 2; i++)
#pragma unroll
        for (int j = 0; j < 8; j++)
#pragma unroll
            for (int q = 0; q < 4; q++) acc[i][j][q] = 0.f;

    auto load_stage = [&](int s, int kc) {
        const int k0 = kc * 32;
        const __nv_bfloat16 *pAh, *pAl;
        int ka = k0;
        if (MODE == 3 && k0 >= H_) {
            pAh = A1hi + aoff; pAl = A1lo + aoff; ka = k0 - H_;
        } else {
            pAh = A0hi + aoff; pAl = A0lo + aoff;
        }
        const uint32_t base = sb + s * G_STAGE;
#pragma unroll
        for (int it = 0; it < 6; it++) {
            int c = it * 512 + tid;
            if (c < 1024) {
                int part = c >> 9, row = (c >> 2) & 127, seg = c & 3;
                uint32_t dst = base + part * A_PART + row * LDSB + seg * 16;
                const __nv_bfloat16* src = (part ? pAl : pAh) + (size_t)row * LDA + ka + seg * 8;
                cp16(dst, src);
            } else {
                int cb = c - 1024;
                int part = cb >> 10, row = (cb >> 2) & 255, seg = cb & 3;
                uint32_t dst = base + 2 * A_PART + part * B_PART + row * LDSB + seg * 16;
                const __nv_bfloat16* src = (part ? pBl : pBh) + (size_t)row * LDB + k0 + seg * 8;
                cp16(dst, src);
            }
        }
    };

    const uint32_t a_row = (uint32_t)(lane & 15);
    const uint32_t a_cb  = (uint32_t)((lane >> 4) * 16);
    const uint32_t b_row = (uint32_t)((lane & 7) + ((lane & 16) ? 8 : 0));
    const uint32_t b_cb  = (uint32_t)((lane & 8) << 1);

    // Prologue: 2 stages in flight
    load_stage(0, 0); CP_COMMIT();
    load_stage(1, 1); CP_COMMIT();

    for (int k = 0; k < NC; k++) {
        CP_WAITG1();          // group k complete (<=1 newer pending)
        __syncthreads();      // data visible + stage (k+2)%3 free

        // prefetch k+2 into stage (k+2)%3; always commit to keep counts aligned
        if (k + 2 < NC) load_stage((k + 2) % NSTAGE, k + 2);
        CP_COMMIT();

        const uint32_t sA = sb + (k % NSTAGE) * G_STAGE;
        const uint32_t sB = sA + 2 * A_PART;

#pragma unroll
        for (int ks = 0; ks < 2; ks++) {
            const uint32_t kb = ks * 32;
            uint32_t Ah[2][4], Al[2][4];
#pragma unroll
            for (int mi = 0; mi < 2; mi++) {
                uint32_t ra = (warp_m + mi * 16 + a_row) * LDSB + kb + a_cb;
                ldsm4(Ah[mi], sA + ra);
                ldsm4(Al[mi], sA + A_PART + ra);
            }
#pragma unroll
            for (int g = 0; g < 4; g++) {
                uint32_t rb = (warp_n + g * 16 + b_row) * LDSB + kb + b_cb;
                uint32_t th[4], tl[4];
                ldsm4(th, sB + rb);
                ldsm4(tl, sB + B_PART + rb);
#pragma unroll
                for (int mi = 0; mi < 2; mi++) {
                    mma_bf16(acc[mi][2 * g],     Ah[mi], th);
                    mma_bf16(acc[mi][2 * g],     Ah[mi], tl);
                    mma_bf16(acc[mi][2 * g],     Al[mi], th);
                    mma_bf16(acc[mi][2 * g + 1], Ah[mi], th + 2);
                    mma_bf16(acc[mi][2 * g + 1], Ah[mi], tl + 2);
                    mma_bf16(acc[mi][2 * g + 1], Al[mi], th + 2);
                }
            }
        }
        __syncthreads();  // stage k consumed before anyone overwrites it next iter
    }

    // ------------------------------------------------------------------ epi
    const int colb = warp_n + (lane & 3) * 2;
#pragma unroll
    for (int mi = 0; mi < 2; mi++) {
#pragma unroll
        for (int p = 0; p < 2; p++) {
            const int m = m0 + warp_m + mi * 16 + (lane >> 2) + p * 8;
            if (MODE == 0) {
                const float dv = g_dinv[b * N_ + m];
                const size_t orow = ((size_t)(b * N_ + m)) * H_;
#pragma unroll
                for (int ni = 0; ni < 8; ni++) {
                    float f0 = acc[mi][ni][2 * p]     * dv;
                    float f1 = acc[mi][ni][2 * p + 1] * dv;
                    __nv_bfloat16 h0, l0, h1, l1;
                    split1(f0, h0, l0); split1(f1, h1, l1);
                    *(uint32_t*)(ohi + orow + colb + ni * 8) = packbf2(h0, h1);
                    *(uint32_t*)(olo + orow + colb + ni * 8) = packbf2(l0, l1);
                }
            } else if (MODE == 1 || MODE == 3) {
                const size_t orow = (size_t)m * H_;
#pragma unroll
                for (int ni = 0; ni < 8; ni++) {
                    int c = colb + ni * 8;
                    float2 o;
                    o.x = fmaxf(acc[mi][ni][2 * p]     + bias[c],     0.f);
                    o.y = fmaxf(acc[mi][ni][2 * p + 1] + bias[c + 1], 0.f);
                    *(float2*)(outf + orow + c) = o;
                }
            } else {
                const size_t orow = (size_t)m * H_;
#pragma unroll
                for (int ni = 0; ni < 8; ni++) {
                    int c = colb + ni * 8;
                    float f0 = fmaxf(acc[mi][ni][2 * p]     + bias[c],     0.f);
                    float f1 = fmaxf(acc[mi][ni][2 * p + 1] + bias[c + 1], 0.f);
                    __nv_bfloat16 h0, l0, h1, l1;
                    split1(f0, h0, l0); split1(f1, h1, l1);
                    *(uint32_t*)(ohi + orow + c) = packbf2(h0, h1);
                    *(uint32_t*)(olo + orow + c) = packbf2(l0, l1);
                }
            }
        }
    }
}

// ---------------------------------------------------------------------------
// Launch
// ---------------------------------------------------------------------------
extern "C" void kernel_launch(void* const* d_in, const int* in_sizes, int n_in,
                              void* d_out, int out_size) {
    const float* node  = (const float*)d_in[0];
    const float* graph = (const float*)d_in[1];
    const float* W1    = (const float*)d_in[2];
    const float* b1    = (const float*)d_in[3];
    const float* W2    = (const float*)d_in[4];
    const float* b2    = (const float*)d_in[5];
    const float* Wout  = (const float*)d_in[6];
    const float* bout  = (const float*)d_in[7];
    float* out = (float*)d_out;

    __nv_bfloat16 *Ghi, *Glo, *Xthi, *Xtlo, *Chi, *Clo, *H2hi, *H2lo, *Nhi, *Nlo;
    __nv_bfloat16 *W1hi, *W1lo, *W2hi, *W2lo, *Wohi, *Wolo;
    float* H1;
    cudaGetSymbolAddress((void**)&Ghi, g_Ghi);
    cudaGetSymbolAddress((void**)&Glo, g_Glo);
    cudaGetSymbolAddress((void**)&Xthi, g_Xthi);
    cudaGetSymbolAddress((void**)&Xtlo, g_Xtlo);
    cudaGetSymbolAddress((void**)&Chi, g_Chi);
    cudaGetSymbolAddress((void**)&Clo, g_Clo);
    cudaGetSymbolAddress((void**)&H1, g_H1);
    cudaGetSymbolAddress((void**)&H2hi, g_H2hi);
    cudaGetSymbolAddress((void**)&H2lo, g_H2lo);
    cudaGetSymbolAddress((void**)&Nhi, g_Nhi);
    cudaGetSymbolAddress((void**)&Nlo, g_Nlo);
    cudaGetSymbolAddress((void**)&W1hi, g_W1hi);
    cudaGetSymbolAddress((void**)&W1lo, g_W1lo);
    cudaGetSymbolAddress((void**)&W2hi, g_W2hi);
    cudaGetSymbolAddress((void**)&W2lo, g_W2lo);
    cudaGetSymbolAddress((void**)&Wohi, g_Wohi);
    cudaGetSymbolAddress((void**)&Wolo, g_Wolo);

    cudaFuncSetAttribute(gemm512<2048, 0>, cudaFuncAttributeMaxDynamicSharedMemorySize, G_SMEM);
    cudaFuncSetAttribute(gemm512<256, 1>,  cudaFuncAttributeMaxDynamicSharedMemorySize, G_SMEM);
    cudaFuncSetAttribute(gemm512<256, 2>,  cudaFuncAttributeMaxDynamicSharedMemorySize, G_SMEM);
    cudaFuncSetAttribute(gemm512<512, 3>,  cudaFuncAttributeMaxDynamicSharedMemorySize, G_SMEM);

    dim3 gAgg(1, N_ / 128, B_);       // 128 CTAs
    dim3 gFc(1, M_TOT / 128, 1);      // 128 CTAs
    dim3 gXt(64, 8, 8), bXt(32, 8);

    graph_conv<<<B_ * N_, 256>>>(graph);
    xt_build<<<gXt, bXt>>>(node);
    split_conv<<<(M_TOT * H_) / 1024, 256>>>(node, Nhi, Nlo);
    split_conv<<<(H_ * H_) / 1024, 256>>>(W1, W1hi, W1lo);
    split_conv<<<(H_ * H_) / 1024, 256>>>(W2, W2hi, W2lo);

    // Layer 1
    gemm512<2048, 0><<<gAgg, 512, G_SMEM>>>(Ghi, Glo, nullptr, nullptr,
                                            Xthi, Xtlo, nullptr, nullptr, Chi, Clo);
    gemm512<256, 1><<<gFc, 512, G_SMEM>>>(Chi, Clo, nullptr, nullptr,
                                          W1hi, W1lo, b1, H1, nullptr, nullptr);
    xt_build<<<gXt, bXt>>>(H1);

    // Layer 2
    gemm512<2048, 0><<<gAgg, 512, G_SMEM>>>(Ghi, Glo, nullptr, nullptr,
                                            Xthi, Xtlo, nullptr, nullptr, Chi, Clo);
    gemm512<256, 2><<<gFc, 512, G_SMEM>>>(Chi, Clo, nullptr, nullptr,
                                          W2hi, W2lo, b2, nullptr, H2hi, H2lo);

    // Output
    split_conv<<<(H_ * 2 * H_) / 1024, 256>>>(Wout, Wohi, Wolo);
    gemm512<512, 3><<<gFc, 512, G_SMEM>>>(Nhi, Nlo, H2hi, H2lo,
                                          Wohi, Wolo, bout, out, nullptr, nullptr);
}

// round 6
// speedup vs baseline: 3.2779x; 1.2076x over previous
#include <cuda_runtime.h>
#include <cuda_bf16.h>
#include <cuda_fp16.h>
#include <cstdint>

#define B_ 8
#define N_ 2048
#define H_ 256
#define M_TOT (B_ * N_)  // 16384

// ---------------------------------------------------------------------------
// Device scratch
// ---------------------------------------------------------------------------
__device__ __half        g_Gf16[(size_t)B_ * N_ * N_];
__device__ __half        g_Xthi[(size_t)B_ * H_ * N_];
__device__ __half        g_Xtlo[(size_t)B_ * H_ * N_];
__device__ __nv_bfloat16 g_Chi[(size_t)M_TOT * H_];
__device__ __nv_bfloat16 g_Clo[(size_t)M_TOT * H_];
__device__ float         g_H1[(size_t)M_TOT * H_];
__device__ __nv_bfloat16 g_H2hi[(size_t)M_TOT * H_];
__device__ __nv_bfloat16 g_H2lo[(size_t)M_TOT * H_];
__device__ __nv_bfloat16 g_Nhi[(size_t)M_TOT * H_];
__device__ __nv_bfloat16 g_Nlo[(size_t)M_TOT * H_];
__device__ __nv_bfloat16 g_W1hi[H_ * H_], g_W1lo[H_ * H_];
__device__ __nv_bfloat16 g_W2hi[H_ * H_], g_W2lo[H_ * H_];
__device__ __nv_bfloat16 g_Wohi[H_ * 2 * H_], g_Wolo[H_ * 2 * H_];
__device__ float g_dinv[B_ * N_];

#define XSCALE 1024.0f
#define XISCALE (1.0f / 1024.0f)

// ---------------------------------------------------------------------------
// PTX helpers (sm_80-portable only)
// ---------------------------------------------------------------------------
__device__ __forceinline__ uint32_t s2u(const void* p) {
    uint32_t r;
    asm("{ .reg .u64 t; cvta.to.shared.u64 t, %1; cvt.u32.u64 %0, t; }"
        : "=r"(r) : "l"(p));
    return r;
}
__device__ __forceinline__ void cp16(uint32_t s, const void* g) {
    asm volatile("cp.async.cg.shared.global [%0], [%1], 16;" :: "r"(s), "l"(g) : "memory");
}
#define CP_COMMIT() asm volatile("cp.async.commit_group;" ::: "memory")
#define CP_WAITG1() asm volatile("cp.async.wait_group 1;" ::: "memory")

__device__ __forceinline__ void ldsm4(uint32_t* r, uint32_t a) {
    asm volatile("ldmatrix.sync.aligned.m8n8.x4.shared.b16 {%0,%1,%2,%3}, [%4];"
                 : "=r"(r[0]), "=r"(r[1]), "=r"(r[2]), "=r"(r[3]) : "r"(a));
}
__device__ __forceinline__ void mma_bf16(float* d, const uint32_t* a, const uint32_t* b) {
    asm volatile(
        "mma.sync.aligned.m16n8k16.row.col.f32.bf16.bf16.f32 "
        "{%0,%1,%2,%3}, {%4,%5,%6,%7}, {%8,%9}, {%0,%1,%2,%3};"
        : "+f"(d[0]), "+f"(d[1]), "+f"(d[2]), "+f"(d[3])
        : "r"(a[0]), "r"(a[1]), "r"(a[2]), "r"(a[3]), "r"(b[0]), "r"(b[1]));
}
__device__ __forceinline__ void mma_f16(float* d, const uint32_t* a, const uint32_t* b) {
    asm volatile(
        "mma.sync.aligned.m16n8k16.row.col.f32.f16.f16.f32 "
        "{%0,%1,%2,%3}, {%4,%5,%6,%7}, {%8,%9}, {%0,%1,%2,%3};"
        : "+f"(d[0]), "+f"(d[1]), "+f"(d[2]), "+f"(d[3])
        : "r"(a[0]), "r"(a[1]), "r"(a[2]), "r"(a[3]), "r"(b[0]), "r"(b[1]));
}

__device__ __forceinline__ void split1(float v, __nv_bfloat16& h, __nv_bfloat16& l) {
    h = __float2bfloat16(v);
    l = __float2bfloat16(v - __bfloat162float(h));
}
__device__ __forceinline__ uint32_t packbf2(__nv_bfloat16 a, __nv_bfloat16 b) {
    __nv_bfloat162 t(a, b);
    return *reinterpret_cast<uint32_t*>(&t);
}

// ---------------------------------------------------------------------------
// graph -> fp16 (single) + fused row-sum -> dinv
// ---------------------------------------------------------------------------
__global__ void graph_conv(const float* __restrict__ graph) {
    int row = blockIdx.x;
    size_t base = (size_t)row * N_;
    float s = 0.f;
#pragma unroll
    for (int it = 0; it < 2; it++) {
        int j = (threadIdx.x + it * 256) * 4;
        float4 v = *(const float4*)(graph + base + j);
        s += v.x + v.y + v.z + v.w;
        __half2 p0(__float2half_rn(v.x), __float2half_rn(v.y));
        __half2 p1(__float2half_rn(v.z), __float2half_rn(v.w));
        *(uint2*)(g_Gf16 + base + j) =
            make_uint2(*(uint32_t*)&p0, *(uint32_t*)&p1);
    }
#pragma unroll
    for (int o = 16; o; o >>= 1) s += __shfl_down_sync(0xffffffffu, s, o);
    __shared__ float ws[8];
    int lane = threadIdx.x & 31, w = threadIdx.x >> 5;
    if (lane == 0) ws[w] = s;
    __syncthreads();
    if (threadIdx.x == 0) {
        float t = 0.f;
#pragma unroll
        for (int i = 0; i < 8; i++) t += ws[i];
        g_dinv[row] = rsqrtf(t);
    }
}

// ---------------------------------------------------------------------------
// fp32 -> bf16 hi/lo split
// ---------------------------------------------------------------------------
__global__ void split_conv(const float* __restrict__ src, __nv_bfloat16* __restrict__ hi,
                           __nv_bfloat16* __restrict__ lo) {
    size_t j = ((size_t)blockIdx.x * 256 + threadIdx.x) * 4;
    float4 v = *(const float4*)(src + j);
    __nv_bfloat16 h0, l0, h1, l1, h2, l2, h3, l3;
    split1(v.x, h0, l0); split1(v.y, h1, l1);
    split1(v.z, h2, l2); split1(v.w, h3, l3);
    *(uint2*)(hi + j) = make_uint2(packbf2(h0, h1), packbf2(h2, h3));
    *(uint2*)(lo + j) = make_uint2(packbf2(l0, l1), packbf2(l2, l3));
}

// ---------------------------------------------------------------------------
// Xt[b][n][k] = src[b][k][n] * dinv[b][k] * XSCALE, split fp16 hi/lo
// ---------------------------------------------------------------------------
__global__ void xt_build(const float* __restrict__ src) {
    __shared__ float t[32][33];
    int b = blockIdx.z, k0 = blockIdx.x * 32, n0 = blockIdx.y * 32;
    const float* S = src + (size_t)b * N_ * H_;
    for (int j = threadIdx.y; j < 32; j += 8)
        t[j][threadIdx.x] = S[(size_t)(k0 + j) * H_ + n0 + threadIdx.x] *
                            g_dinv[b * N_ + k0 + j] * XSCALE;
    __syncthreads();
    for (int j = threadIdx.y; j < 32; j += 8) {
        float v = t[threadIdx.x][j];
        __half h = __float2half_rn(v);
        __half l = __float2half_rn(v - __half2float(h));
        size_t o = (size_t)(b * H_ + n0 + j) * N_ + k0 + threadIdx.x;
        g_Xthi[o] = h;
        g_Xtlo[o] = l;
    }
}

// ===========================================================================
// Agg GEMM (fp16, 2-pass): C[b,m,0:256] = dinv[m]/XSCALE * (Gf16 @ (Xh+Xl)^T)
// 512 threads (16 warps 4x4), 3-stage cp.async, epilogue -> bf16 hi/lo.
// ===========================================================================
#define LDSB 80
#define AG_A_PART 10240                         // 128 * 80
#define AG_B_PART 20480                         // 256 * 80
#define AG_STAGE (AG_A_PART + 2 * AG_B_PART)    // 51200
#define NSTAGE 3
#define AG_SMEM (NSTAGE * AG_STAGE)             // 153600

__global__ void __launch_bounds__(512, 1) agg_gemm(
    const __half* __restrict__ G, const __half* __restrict__ Xh,
    const __half* __restrict__ Xl,
    __nv_bfloat16* __restrict__ ohi, __nv_bfloat16* __restrict__ olo)
{
    extern __shared__ char smem[];
    const uint32_t sb = s2u(smem);
    constexpr int NC = N_ / 32;  // 64

    const int tid = threadIdx.x, wid = tid >> 5, lane = tid & 31;
    const int b = blockIdx.z;
    const int m0 = blockIdx.y * 128;
    const int warp_m = (wid & 3) * 32;
    const int warp_n = (wid >> 2) * 64;

    const __half* pA  = G  + (size_t)b * N_ * N_ + (size_t)m0 * N_;
    const __half* pBh = Xh + (size_t)b * H_ * N_;
    const __half* pBl = Xl + (size_t)b * H_ * N_;

    float acc[2][8][4];
#pragma unroll
    for (int i = 0; i < 2; i++)
#pragma unroll
        for (int j = 0; j < 8; j++)
#pragma unroll
            for (int q = 0; q < 4; q++) acc[i][j][q] = 0.f;

    auto load_stage = [&](int s, int kc) {
        const int k0 = kc * 32;
        const uint32_t base = sb + s * AG_STAGE;
#pragma unroll
        for (int it = 0; it < 5; it++) {
            int c = it * 512 + tid;
            if (c < 512) {
                int row = c >> 2, seg = c & 3;
                uint32_t dst = base + row * LDSB + seg * 16;
                cp16(dst, pA + (size_t)row * N_ + k0 + seg * 8);
            } else {
                int cb = c - 512;
                int part = cb >> 10, row = (cb >> 2) & 255, seg = cb & 3;
                uint32_t dst = base + AG_A_PART + part * AG_B_PART + row * LDSB + seg * 16;
                const __half* src = (part ? pBl : pBh) + (size_t)row * N_ + k0 + seg * 8;
                cp16(dst, src);
            }
        }
    };

    const uint32_t a_row = (uint32_t)(lane & 15);
    const uint32_t a_cb  = (uint32_t)((lane >> 4) * 16);
    const uint32_t b_row = (uint32_t)((lane & 7) + ((lane & 16) ? 8 : 0));
    const uint32_t b_cb  = (uint32_t)((lane & 8) << 1);

    load_stage(0, 0); CP_COMMIT();
    load_stage(1, 1); CP_COMMIT();

    for (int k = 0; k < NC; k++) {
        CP_WAITG1();
        __syncthreads();

        if (k + 2 < NC) load_stage((k + 2) % NSTAGE, k + 2);
        CP_COMMIT();

        const uint32_t sA = sb + (k % NSTAGE) * AG_STAGE;
        const uint32_t sB = sA + AG_A_PART;

#pragma unroll
        for (int ks = 0; ks < 2; ks++) {
            const uint32_t kb = ks * 32;
            uint32_t Af[2][4];
#pragma unroll
            for (int mi = 0; mi < 2; mi++) {
                uint32_t ra = (warp_m + mi * 16 + a_row) * LDSB + kb + a_cb;
                ldsm4(Af[mi], sA + ra);
            }
#pragma unroll
            for (int g = 0; g < 4; g++) {
                uint32_t rb = (warp_n + g * 16 + b_row) * LDSB + kb + b_cb;
                uint32_t th[4], tl[4];
                ldsm4(th, sB + rb);
                ldsm4(tl, sB + AG_B_PART + rb);
#pragma unroll
                for (int mi = 0; mi < 2; mi++) {
                    mma_f16(acc[mi][2 * g],     Af[mi], th);
                    mma_f16(acc[mi][2 * g],     Af[mi], tl);
                    mma_f16(acc[mi][2 * g + 1], Af[mi], th + 2);
                    mma_f16(acc[mi][2 * g + 1], Af[mi], tl + 2);
                }
            }
        }
        __syncthreads();
    }

    const int colb = warp_n + (lane & 3) * 2;
#pragma unroll
    for (int mi = 0; mi < 2; mi++) {
#pragma unroll
        for (int p = 0; p < 2; p++) {
            const int m = m0 + warp_m + mi * 16 + (lane >> 2) + p * 8;
            const float dv = g_dinv[b * N_ + m] * XISCALE;
            const size_t orow = ((size_t)(b * N_ + m)) * H_;
#pragma unroll
            for (int ni = 0; ni < 8; ni++) {
                float f0 = acc[mi][ni][2 * p]     * dv;
                float f1 = acc[mi][ni][2 * p + 1] * dv;
                __nv_bfloat16 h0, l0, h1, l1;
                split1(f0, h0, l0); split1(f1, h1, l1);
                *(uint32_t*)(ohi + orow + colb + ni * 8) = packbf2(h0, h1);
                *(uint32_t*)(olo + orow + colb + ni * 8) = packbf2(l0, l1);
            }
        }
    }
}

// ===========================================================================
// FC GEMM (bf16 3-pass): D[128 x 256] = A[128 x KTOT] @ W[256 x KTOT]^T
// MODE 1: +bias relu -> f32; MODE 2: +bias relu -> bf16 hi/lo;
// MODE 3: concat A=[A0|A1], +bias relu -> f32.
// ===========================================================================
#define FC_A_PART 10240
#define FC_B_PART 20480
#define FC_STAGE (2 * FC_A_PART + 2 * FC_B_PART)   // 61440
#define FC_SMEM (NSTAGE * FC_STAGE)                // 184320

template <int KTOT, int MODE>
__global__ void __launch_bounds__(512, 1) fc_gemm(
    const __nv_bfloat16* __restrict__ A0hi, const __nv_bfloat16* __restrict__ A0lo,
    const __nv_bfloat16* __restrict__ A1hi, const __nv_bfloat16* __restrict__ A1lo,
    const __nv_bfloat16* __restrict__ Bhi,  const __nv_bfloat16* __restrict__ Blo,
    const float* __restrict__ bias, float* __restrict__ outf,
    __nv_bfloat16* __restrict__ ohi, __nv_bfloat16* __restrict__ olo)
{
    extern __shared__ char smem[];
    const uint32_t sb = s2u(smem);
    constexpr int NC = KTOT / 32;
    constexpr int LDB = (MODE == 3) ? 2 * H_ : H_;

    const int tid = threadIdx.x, wid = tid >> 5, lane = tid & 31;
    const int m0 = blockIdx.y * 128;
    const int warp_m = (wid & 3) * 32;
    const int warp_n = (wid >> 2) * 64;

    const size_t aoff = (size_t)m0 * H_;

    float acc[2][8][4];
#pragma unroll
    for (int i = 0; i < 2; i++)
#pragma unroll
        for (int j = 0; j < 8; j++)
#pragma unroll
            for (int q = 0; q < 4; q++) acc[i][j][q] = 0.f;

    auto load_stage = [&](int s, int kc) {
        const int k0 = kc * 32;
        const __nv_bfloat16 *pAh, *pAl;
        int ka = k0;
        if (MODE == 3 && k0 >= H_) {
            pAh = A1hi + aoff; pAl = A1lo + aoff; ka = k0 - H_;
        } else {
            pAh = A0hi + aoff; pAl = A0lo + aoff;
        }
        const uint32_t base = sb + s * FC_STAGE;
#pragma unroll
        for (int it = 0; it < 6; it++) {
            int c = it * 512 + tid;
            if (c < 1024) {
                int part = c >> 9, row = (c >> 2) & 127, seg = c & 3;
                uint32_t dst = base + part * FC_A_PART + row * LDSB + seg * 16;
                const __nv_bfloat16* src = (part ? pAl : pAh) + (size_t)row * H_ + ka + seg * 8;
                cp16(dst, src);
            } else {
                int cb = c - 1024;
                int part = cb >> 10, row = (cb >> 2) & 255, seg = cb & 3;
                uint32_t dst = base + 2 * FC_A_PART + part * FC_B_PART + row * LDSB + seg * 16;
                const __nv_bfloat16* src = (part ? Blo : Bhi) + (size_t)row * LDB + k0 + seg * 8;
                cp16(dst, src);
            }
        }
    };

    const uint32_t a_row = (uint32_t)(lane & 15);
    const uint32_t a_cb  = (uint32_t)((lane >> 4) * 16);
    const uint32_t b_row = (uint32_t)((lane & 7) + ((lane & 16) ? 8 : 0));
    const uint32_t b_cb  = (uint32_t)((lane & 8) << 1);

    load_stage(0, 0); CP_COMMIT();
    load_stage(1, 1); CP_COMMIT();

    for (int k = 0; k < NC; k++) {
        CP_WAITG1();
        __syncthreads();

        if (k + 2 < NC) load_stage((k + 2) % NSTAGE, k + 2);
        CP_COMMIT();

        const uint32_t sA = sb + (k % NSTAGE) * FC_STAGE;
        const uint32_t sB = sA + 2 * FC_A_PART;

#pragma unroll
        for (int ks = 0; ks < 2; ks++) {
            const uint32_t kb = ks * 32;
            uint32_t Ah[2][4], Al[2][4];
#pragma unroll
            for (int mi = 0; mi < 2; mi++) {
                uint32_t ra = (warp_m + mi * 16 + a_row) * LDSB + kb + a_cb;
                ldsm4(Ah[mi], sA + ra);
                ldsm4(Al[mi], sA + FC_A_PART + ra);
            }
#pragma unroll
            for (int g = 0; g < 4; g++) {
                uint32_t rb = (warp_n + g * 16 + b_row) * LDSB + kb + b_cb;
                uint32_t th[4], tl[4];
                ldsm4(th, sB + rb);
                ldsm4(tl, sB + FC_B_PART + rb);
#pragma unroll
                for (int mi = 0; mi < 2; mi++) {
                    mma_bf16(acc[mi][2 * g],     Ah[mi], th);
                    mma_bf16(acc[mi][2 * g],     Ah[mi], tl);
                    mma_bf16(acc[mi][2 * g],     Al[mi], th);
                    mma_bf16(acc[mi][2 * g + 1], Ah[mi], th + 2);
                    mma_bf16(acc[mi][2 * g + 1], Ah[mi], tl + 2);
                    mma_bf16(acc[mi][2 * g + 1], Al[mi], th + 2);
                }
            }
        }
        __syncthreads();
    }

    const int colb = warp_n + (lane & 3) * 2;
#pragma unroll
    for (int mi = 0; mi < 2; mi++) {
#pragma unroll
        for (int p = 0; p < 2; p++) {
            const int m = m0 + warp_m + mi * 16 + (lane >> 2) + p * 8;
            const size_t orow = (size_t)m * H_;
            if (MODE == 1 || MODE == 3) {
#pragma unroll
                for (int ni = 0; ni < 8; ni++) {
                    int c = colb + ni * 8;
                    float2 o;
                    o.x = fmaxf(acc[mi][ni][2 * p]     + bias[c],     0.f);
                    o.y = fmaxf(acc[mi][ni][2 * p + 1] + bias[c + 1], 0.f);
                    *(float2*)(outf + orow + c) = o;
                }
            } else {
#pragma unroll
                for (int ni = 0; ni < 8; ni++) {
                    int c = colb + ni * 8;
                    float f0 = fmaxf(acc[mi][ni][2 * p]     + bias[c],     0.f);
                    float f1 = fmaxf(acc[mi][ni][2 * p + 1] + bias[c + 1], 0.f);
                    __nv_bfloat16 h0, l0, h1, l1;
                    split1(f0, h0, l0); split1(f1, h1, l1);
                    *(uint32_t*)(ohi + orow + c) = packbf2(h0, h1);
                    *(uint32_t*)(olo + orow + c) = packbf2(l0, l1);
                }
            }
        }
    }
}

// ---------------------------------------------------------------------------
// Launch
// ---------------------------------------------------------------------------
extern "C" void kernel_launch(void* const* d_in, const int* in_sizes, int n_in,
                              void* d_out, int out_size) {
    const float* node  = (const float*)d_in[0];
    const float* graph = (const float*)d_in[1];
    const float* W1    = (const float*)d_in[2];
    const float* b1    = (const float*)d_in[3];
    const float* W2    = (const float*)d_in[4];
    const float* b2    = (const float*)d_in[5];
    const float* Wout  = (const float*)d_in[6];
    const float* bout  = (const float*)d_in[7];
    float* out = (float*)d_out;

    __half *Gf16, *Xthi, *Xtlo;
    __nv_bfloat16 *Chi, *Clo, *H2hi, *H2lo, *Nhi, *Nlo;
    __nv_bfloat16 *W1hi, *W1lo, *W2hi, *W2lo, *Wohi, *Wolo;
    float* H1;
    cudaGetSymbolAddress((void**)&Gf16, g_Gf16);
    cudaGetSymbolAddress((void**)&Xthi, g_Xthi);
    cudaGetSymbolAddress((void**)&Xtlo, g_Xtlo);
    cudaGetSymbolAddress((void**)&Chi, g_Chi);
    cudaGetSymbolAddress((void**)&Clo, g_Clo);
    cudaGetSymbolAddress((void**)&H1, g_H1);
    cudaGetSymbolAddress((void**)&H2hi, g_H2hi);
    cudaGetSymbolAddress((void**)&H2lo, g_H2lo);
    cudaGetSymbolAddress((void**)&Nhi, g_Nhi);
    cudaGetSymbolAddress((void**)&Nlo, g_Nlo);
    cudaGetSymbolAddress((void**)&W1hi, g_W1hi);
    cudaGetSymbolAddress((void**)&W1lo, g_W1lo);
    cudaGetSymbolAddress((void**)&W2hi, g_W2hi);
    cudaGetSymbolAddress((void**)&W2lo, g_W2lo);
    cudaGetSymbolAddress((void**)&Wohi, g_Wohi);
    cudaGetSymbolAddress((void**)&Wolo, g_Wolo);

    cudaFuncSetAttribute(agg_gemm, cudaFuncAttributeMaxDynamicSharedMemorySize, AG_SMEM);
    cudaFuncSetAttribute(fc_gemm<256, 1>, cudaFuncAttributeMaxDynamicSharedMemorySize, FC_SMEM);
    cudaFuncSetAttribute(fc_gemm<256, 2>, cudaFuncAttributeMaxDynamicSharedMemorySize, FC_SMEM);
    cudaFuncSetAttribute(fc_gemm<512, 3>, cudaFuncAttributeMaxDynamicSharedMemorySize, FC_SMEM);

    dim3 gAgg(1, N_ / 128, B_);       // 128 CTAs
    dim3 gFc(1, M_TOT / 128, 1);      // 128 CTAs
    dim3 gXt(64, 8, 8), bXt(32, 8);

    graph_conv<<<B_ * N_, 256>>>(graph);                         // 0
    xt_build<<<gXt, bXt>>>(node);                                // 1
    split_conv<<<(H_ * H_) / 1024, 256>>>(W1, W1hi, W1lo);       // 2
    split_conv<<<(M_TOT * H_) / 1024, 256>>>(node, Nhi, Nlo);    // 3
    agg_gemm<<<gAgg, 512, AG_SMEM>>>(Gf16, Xthi, Xtlo, Chi, Clo);// 4
    fc_gemm<256, 1><<<gFc, 512, FC_SMEM>>>(Chi, Clo, nullptr, nullptr,
                                           W1hi, W1lo, b1, H1, nullptr, nullptr);
    xt_build<<<gXt, bXt>>>(H1);
    split_conv<<<(H_ * H_) / 1024, 256>>>(W2, W2hi, W2lo);
    agg_gemm<<<gAgg, 512, AG_SMEM>>>(Gf16, Xthi, Xtlo, Chi, Clo);
    fc_gemm<256, 2><<<gFc, 512, FC_SMEM>>>(Chi, Clo, nullptr, nullptr,
                                           W2hi, W2lo, b2, nullptr, H2hi, H2lo);
    split_conv<<<(H_ * 2 * H_) / 1024, 256>>>(Wout, Wohi, Wolo);
    fc_gemm<512, 3><<<gFc, 512, FC_SMEM>>>(Nhi, Nlo, H2hi, H2lo,
                                           Wohi, Wolo, bout, out, nullptr, nullptr);
}

// round 7
// speedup vs baseline: 4.4679x; 1.3630x over previous
#include <cuda_runtime.h>
#include <cuda_bf16.h>
#include <cuda_fp16.h>
#include <cstdint>

#define B_ 8
#define N_ 2048
#define H_ 256
#define M_TOT (B_ * N_)  // 16384

// ---------------------------------------------------------------------------
// Device scratch
// ---------------------------------------------------------------------------
__device__ __half        g_Gf16[(size_t)B_ * N_ * N_];
__device__ __half        g_Xt[(size_t)B_ * H_ * N_];
__device__ __nv_bfloat16 g_Chi[(size_t)M_TOT * H_];
__device__ __nv_bfloat16 g_Clo[(size_t)M_TOT * H_];
__device__ float         g_H1[(size_t)M_TOT * H_];
__device__ __nv_bfloat16 g_H2hi[(size_t)M_TOT * H_];
__device__ __nv_bfloat16 g_H2lo[(size_t)M_TOT * H_];
__device__ __nv_bfloat16 g_Nhi[(size_t)M_TOT * H_];
__device__ __nv_bfloat16 g_Nlo[(size_t)M_TOT * H_];
__device__ __nv_bfloat16 g_W1hi[H_ * H_], g_W1lo[H_ * H_];
__device__ __nv_bfloat16 g_W2hi[H_ * H_], g_W2lo[H_ * H_];
__device__ __nv_bfloat16 g_Wohi[H_ * 2 * H_], g_Wolo[H_ * 2 * H_];
__device__ float g_dinv[B_ * N_];

// ---------------------------------------------------------------------------
// PTX helpers (sm_80-portable only)
// ---------------------------------------------------------------------------
__device__ __forceinline__ uint32_t s2u(const void* p) {
    uint32_t r;
    asm("{ .reg .u64 t; cvta.to.shared.u64 t, %1; cvt.u32.u64 %0, t; }"
        : "=r"(r) : "l"(p));
    return r;
}
__device__ __forceinline__ void cp16(uint32_t s, const void* g) {
    asm volatile("cp.async.cg.shared.global [%0], [%1], 16;" :: "r"(s), "l"(g) : "memory");
}
#define CP_COMMIT() asm volatile("cp.async.commit_group;" ::: "memory")
#define CP_WAITG1() asm volatile("cp.async.wait_group 1;" ::: "memory")
#define CP_WAITG2() asm volatile("cp.async.wait_group 2;" ::: "memory")

__device__ __forceinline__ void ldsm4(uint32_t* r, uint32_t a) {
    asm volatile("ldmatrix.sync.aligned.m8n8.x4.shared.b16 {%0,%1,%2,%3}, [%4];"
                 : "=r"(r[0]), "=r"(r[1]), "=r"(r[2]), "=r"(r[3]) : "r"(a));
}
__device__ __forceinline__ void mma_bf16(float* d, const uint32_t* a, const uint32_t* b) {
    asm volatile(
        "mma.sync.aligned.m16n8k16.row.col.f32.bf16.bf16.f32 "
        "{%0,%1,%2,%3}, {%4,%5,%6,%7}, {%8,%9}, {%0,%1,%2,%3};"
        : "+f"(d[0]), "+f"(d[1]), "+f"(d[2]), "+f"(d[3])
        : "r"(a[0]), "r"(a[1]), "r"(a[2]), "r"(a[3]), "r"(b[0]), "r"(b[1]));
}
__device__ __forceinline__ void mma_f16(float* d, const uint32_t* a, const uint32_t* b) {
    asm volatile(
        "mma.sync.aligned.m16n8k16.row.col.f32.f16.f16.f32 "
        "{%0,%1,%2,%3}, {%4,%5,%6,%7}, {%8,%9}, {%0,%1,%2,%3};"
        : "+f"(d[0]), "+f"(d[1]), "+f"(d[2]), "+f"(d[3])
        : "r"(a[0]), "r"(a[1]), "r"(a[2]), "r"(a[3]), "r"(b[0]), "r"(b[1]));
}

__device__ __forceinline__ void split1(float v, __nv_bfloat16& h, __nv_bfloat16& l) {
    h = __float2bfloat16(v);
    l = __float2bfloat16(v - __bfloat162float(h));
}
__device__ __forceinline__ uint32_t packbf2(__nv_bfloat16 a, __nv_bfloat16 b) {
    __nv_bfloat162 t(a, b);
    return *reinterpret_cast<uint32_t*>(&t);
}

// ---------------------------------------------------------------------------
// graph -> fp16 (single) + fused row-sum -> dinv
// ---------------------------------------------------------------------------
__global__ void graph_conv(const float* __restrict__ graph) {
    int row = blockIdx.x;
    size_t base = (size_t)row * N_;
    float s = 0.f;
#pragma unroll
    for (int it = 0; it < 2; it++) {
        int j = (threadIdx.x + it * 256) * 4;
        float4 v = *(const float4*)(graph + base + j);
        s += v.x + v.y + v.z + v.w;
        __half2 p0(__float2half_rn(v.x), __float2half_rn(v.y));
        __half2 p1(__float2half_rn(v.z), __float2half_rn(v.w));
        *(uint2*)(g_Gf16 + base + j) =
            make_uint2(*(uint32_t*)&p0, *(uint32_t*)&p1);
    }
#pragma unroll
    for (int o = 16; o; o >>= 1) s += __shfl_down_sync(0xffffffffu, s, o);
    __shared__ float ws[8];
    int lane = threadIdx.x & 31, w = threadIdx.x >> 5;
    if (lane == 0) ws[w] = s;
    __syncthreads();
    if (threadIdx.x == 0) {
        float t = 0.f;
#pragma unroll
        for (int i = 0; i < 8; i++) t += ws[i];
        g_dinv[row] = rsqrtf(t);
    }
}

// ---------------------------------------------------------------------------
// fp32 -> bf16 hi/lo split
// ---------------------------------------------------------------------------
__global__ void split_conv(const float* __restrict__ src, __nv_bfloat16* __restrict__ hi,
                           __nv_bfloat16* __restrict__ lo) {
    size_t j = ((size_t)blockIdx.x * 256 + threadIdx.x) * 4;
    float4 v = *(const float4*)(src + j);
    __nv_bfloat16 h0, l0, h1, l1, h2, l2, h3, l3;
    split1(v.x, h0, l0); split1(v.y, h1, l1);
    split1(v.z, h2, l2); split1(v.w, h3, l3);
    *(uint2*)(hi + j) = make_uint2(packbf2(h0, h1), packbf2(h2, h3));
    *(uint2*)(lo + j) = make_uint2(packbf2(l0, l1), packbf2(l2, l3));
}

// ---------------------------------------------------------------------------
// Xt[b][n][k] = src[b][k][n] * dinv[b][k], fp16 single
// ---------------------------------------------------------------------------
__global__ void xt_build(const float* __restrict__ src) {
    __shared__ float t[32][33];
    int b = blockIdx.z, k0 = blockIdx.x * 32, n0 = blockIdx.y * 32;
    const float* S = src + (size_t)b * N_ * H_;
    for (int j = threadIdx.y; j < 32; j += 8)
        t[j][threadIdx.x] = S[(size_t)(k0 + j) * H_ + n0 + threadIdx.x] *
                            g_dinv[b * N_ + k0 + j];
    __syncthreads();
    for (int j = threadIdx.y; j < 32; j += 8) {
        float v = t[threadIdx.x][j];
        size_t o = (size_t)(b * H_ + n0 + j) * N_ + k0 + threadIdx.x;
        g_Xt[o] = __float2half_rn(v);
    }
}

// ===========================================================================
// Agg GEMM (fp16, 1-pass): C[b,m,0:256] = dinv[m] * (Gf16 @ Xt^T)
// 512 threads (16 warps 4x4), 4-stage cp.async, prefetch distance 3,
// single __syncthreads per chunk. Epilogue -> bf16 hi/lo.
// ===========================================================================
#define LDSB 80
#define AG_A_PART 10240                      // 128 * 80
#define AG_B_PART 20480                      // 256 * 80
#define AG_STAGE (AG_A_PART + AG_B_PART)     // 30720
#define AG_NSTAGE 4
#define AG_SMEM (AG_NSTAGE * AG_STAGE)       // 122880

__global__ void __launch_bounds__(512, 1) agg_gemm(
    const __half* __restrict__ G, const __half* __restrict__ X,
    __nv_bfloat16* __restrict__ ohi, __nv_bfloat16* __restrict__ olo)
{
    extern __shared__ char smem[];
    const uint32_t sb = s2u(smem);
    constexpr int NC = N_ / 32;  // 64

    const int tid = threadIdx.x, wid = tid >> 5, lane = tid & 31;
    const int b = blockIdx.z;
    const int m0 = blockIdx.y * 128;
    const int warp_m = (wid & 3) * 32;
    const int warp_n = (wid >> 2) * 64;

    const __half* pA = G + (size_t)b * N_ * N_ + (size_t)m0 * N_;
    const __half* pB = X + (size_t)b * H_ * N_;

    float acc[2][8][4];
#pragma unroll
    for (int i = 0; i < 2; i++)
#pragma unroll
        for (int j = 0; j < 8; j++)
#pragma unroll
            for (int q = 0; q < 4; q++) acc[i][j][q] = 0.f;

    auto load_stage = [&](int s, int kc) {
        const int k0 = kc * 32;
        const uint32_t base = sb + s * AG_STAGE;
#pragma unroll
        for (int it = 0; it < 3; it++) {
            int c = it * 512 + tid;
            if (c < 512) {
                int row = c >> 2, seg = c & 3;
                cp16(base + row * LDSB + seg * 16,
                     pA + (size_t)row * N_ + k0 + seg * 8);
            } else {
                int cb = c - 512;
                int row = cb >> 2, seg = cb & 3;
                cp16(base + AG_A_PART + row * LDSB + seg * 16,
                     pB + (size_t)row * N_ + k0 + seg * 8);
            }
        }
    };

    const uint32_t a_row = (uint32_t)(lane & 15);
    const uint32_t a_cb  = (uint32_t)((lane >> 4) * 16);
    const uint32_t b_row = (uint32_t)((lane & 7) + ((lane & 16) ? 8 : 0));
    const uint32_t b_cb  = (uint32_t)((lane & 8) << 1);

    load_stage(0, 0); CP_COMMIT();
    load_stage(1, 1); CP_COMMIT();
    load_stage(2, 2); CP_COMMIT();

    for (int k = 0; k < NC; k++) {
        CP_WAITG2();
        __syncthreads();

        if (k + 3 < NC) load_stage((k + 3) % AG_NSTAGE, k + 3);
        CP_COMMIT();

        const uint32_t sA = sb + (k % AG_NSTAGE) * AG_STAGE;
        const uint32_t sB = sA + AG_A_PART;

#pragma unroll
        for (int ks = 0; ks < 2; ks++) {
            const uint32_t kb = ks * 32;
            uint32_t Af[2][4];
#pragma unroll
            for (int mi = 0; mi < 2; mi++) {
                uint32_t ra = (warp_m + mi * 16 + a_row) * LDSB + kb + a_cb;
                ldsm4(Af[mi], sA + ra);
            }
#pragma unroll
            for (int g = 0; g < 4; g++) {
                uint32_t rb = (warp_n + g * 16 + b_row) * LDSB + kb + b_cb;
                uint32_t th[4];
                ldsm4(th, sB + rb);
#pragma unroll
                for (int mi = 0; mi < 2; mi++) {
                    mma_f16(acc[mi][2 * g],     Af[mi], th);
                    mma_f16(acc[mi][2 * g + 1], Af[mi], th + 2);
                }
            }
        }
    }

    const int colb = warp_n + (lane & 3) * 2;
#pragma unroll
    for (int mi = 0; mi < 2; mi++) {
#pragma unroll
        for (int p = 0; p < 2; p++) {
            const int m = m0 + warp_m + mi * 16 + (lane >> 2) + p * 8;
            const float dv = g_dinv[b * N_ + m];
            const size_t orow = ((size_t)(b * N_ + m)) * H_;
#pragma unroll
            for (int ni = 0; ni < 8; ni++) {
                float f0 = acc[mi][ni][2 * p]     * dv;
                float f1 = acc[mi][ni][2 * p + 1] * dv;
                __nv_bfloat16 h0, l0, h1, l1;
                split1(f0, h0, l0); split1(f1, h1, l1);
                *(uint32_t*)(ohi + orow + colb + ni * 8) = packbf2(h0, h1);
                *(uint32_t*)(olo + orow + colb + ni * 8) = packbf2(l0, l1);
            }
        }
    }
}

// ===========================================================================
// FC GEMM (bf16 3-pass): D[128 x 256] = A[128 x KTOT] @ W[256 x KTOT]^T
// MODE 1: +bias relu -> f32; MODE 2: +bias relu -> bf16 hi/lo;
// MODE 3: concat A=[A0|A1], +bias relu -> f32.
// ===========================================================================
#define FC_A_PART 10240
#define FC_B_PART 20480
#define FC_STAGE (2 * FC_A_PART + 2 * FC_B_PART)   // 61440
#define FC_NSTAGE 3
#define FC_SMEM (FC_NSTAGE * FC_STAGE)             // 184320

template <int KTOT, int MODE>
__global__ void __launch_bounds__(512, 1) fc_gemm(
    const __nv_bfloat16* __restrict__ A0hi, const __nv_bfloat16* __restrict__ A0lo,
    const __nv_bfloat16* __restrict__ A1hi, const __nv_bfloat16* __restrict__ A1lo,
    const __nv_bfloat16* __restrict__ Bhi,  const __nv_bfloat16* __restrict__ Blo,
    const float* __restrict__ bias, float* __restrict__ outf,
    __nv_bfloat16* __restrict__ ohi, __nv_bfloat16* __restrict__ olo)
{
    extern __shared__ char smem[];
    const uint32_t sb = s2u(smem);
    constexpr int NC = KTOT / 32;
    constexpr int LDB = (MODE == 3) ? 2 * H_ : H_;

    const int tid = threadIdx.x, wid = tid >> 5, lane = tid & 31;
    const int m0 = blockIdx.y * 128;
    const int warp_m = (wid & 3) * 32;
    const int warp_n = (wid >> 2) * 64;

    const size_t aoff = (size_t)m0 * H_;

    float acc[2][8][4];
#pragma unroll
    for (int i = 0; i < 2; i++)
#pragma unroll
        for (int j = 0; j < 8; j++)
#pragma unroll
            for (int q = 0; q < 4; q++) acc[i][j][q] = 0.f;

    auto load_stage = [&](int s, int kc) {
        const int k0 = kc * 32;
        const __nv_bfloat16 *pAh, *pAl;
        int ka = k0;
        if (MODE == 3 && k0 >= H_) {
            pAh = A1hi + aoff; pAl = A1lo + aoff; ka = k0 - H_;
        } else {
            pAh = A0hi + aoff; pAl = A0lo + aoff;
        }
        const uint32_t base = sb + s * FC_STAGE;
#pragma unroll
        for (int it = 0; it < 6; it++) {
            int c = it * 512 + tid;
            if (c < 1024) {
                int part = c >> 9, row = (c >> 2) & 127, seg = c & 3;
                uint32_t dst = base + part * FC_A_PART + row * LDSB + seg * 16;
                const __nv_bfloat16* src = (part ? pAl : pAh) + (size_t)row * H_ + ka + seg * 8;
                cp16(dst, src);
            } else {
                int cb = c - 1024;
                int part = cb >> 10, row = (cb >> 2) & 255, seg = cb & 3;
                uint32_t dst = base + 2 * FC_A_PART + part * FC_B_PART + row * LDSB + seg * 16;
                const __nv_bfloat16* src = (part ? Blo : Bhi) + (size_t)row * LDB + k0 + seg * 8;
                cp16(dst, src);
            }
        }
    };

    const uint32_t a_row = (uint32_t)(lane & 15);
    const uint32_t a_cb  = (uint32_t)((lane >> 4) * 16);
    const uint32_t b_row = (uint32_t)((lane & 7) + ((lane & 16) ? 8 : 0));
    const uint32_t b_cb  = (uint32_t)((lane & 8) << 1);

    load_stage(0, 0); CP_COMMIT();
    load_stage(1, 1); CP_COMMIT();

    for (int k = 0; k < NC; k++) {
        CP_WAITG1();
        __syncthreads();

        if (k + 2 < NC) load_stage((k + 2) % FC_NSTAGE, k + 2);
        CP_COMMIT();

        const uint32_t sA = sb + (k % FC_NSTAGE) * FC_STAGE;
        const uint32_t sB = sA + 2 * FC_A_PART;

#pragma unroll
        for (int ks = 0; ks < 2; ks++) {
            const uint32_t kb = ks * 32;
            uint32_t Ah[2][4], Al[2][4];
#pragma unroll
            for (int mi = 0; mi < 2; mi++) {
                uint32_t ra = (warp_m + mi * 16 + a_row) * LDSB + kb + a_cb;
                ldsm4(Ah[mi], sA + ra);
                ldsm4(Al[mi], sA + FC_A_PART + ra);
            }
#pragma unroll
            for (int g = 0; g < 4; g++) {
                uint32_t rb = (warp_n + g * 16 + b_row) * LDSB + kb + b_cb;
                uint32_t th[4], tl[4];
                ldsm4(th, sB + rb);
                ldsm4(tl, sB + FC_B_PART + rb);
#pragma unroll
                for (int mi = 0; mi < 2; mi++) {
                    mma_bf16(acc[mi][2 * g],     Ah[mi], th);
                    mma_bf16(acc[mi][2 * g],     Ah[mi], tl);
                    mma_bf16(acc[mi][2 * g],     Al[mi], th);
                    mma_bf16(acc[mi][2 * g + 1], Ah[mi], th + 2);
                    mma_bf16(acc[mi][2 * g + 1], Ah[mi], tl + 2);
                    mma_bf16(acc[mi][2 * g + 1], Al[mi], th + 2);
                }
            }
        }
    }

    const int colb = warp_n + (lane & 3) * 2;
#pragma unroll
    for (int mi = 0; mi < 2; mi++) {
#pragma unroll
        for (int p = 0; p < 2; p++) {
            const int m = m0 + warp_m + mi * 16 + (lane >> 2) + p * 8;
            const size_t orow = (size_t)m * H_;
            if (MODE == 1 || MODE == 3) {
#pragma unroll
                for (int ni = 0; ni < 8; ni++) {
                    int c = colb + ni * 8;
                    float2 o;
                    o.x = fmaxf(acc[mi][ni][2 * p]     + bias[c],     0.f);
                    o.y = fmaxf(acc[mi][ni][2 * p + 1] + bias[c + 1], 0.f);
                    *(float2*)(outf + orow + c) = o;
                }
            } else {
#pragma unroll
                for (int ni = 0; ni < 8; ni++) {
                    int c = colb + ni * 8;
                    float f0 = fmaxf(acc[mi][ni][2 * p]     + bias[c],     0.f);
                    float f1 = fmaxf(acc[mi][ni][2 * p + 1] + bias[c + 1], 0.f);
                    __nv_bfloat16 h0, l0, h1, l1;
                    split1(f0, h0, l0); split1(f1, h1, l1);
                    *(uint32_t*)(ohi + orow + c) = packbf2(h0, h1);
                    *(uint32_t*)(olo + orow + c) = packbf2(l0, l1);
                }
            }
        }
    }
}

// ---------------------------------------------------------------------------
// Launch
// ---------------------------------------------------------------------------
extern "C" void kernel_launch(void* const* d_in, const int* in_sizes, int n_in,
                              void* d_out, int out_size) {
    const float* node  = (const float*)d_in[0];
    const float* graph = (const float*)d_in[1];
    const float* W1    = (const float*)d_in[2];
    const float* b1    = (const float*)d_in[3];
    const float* W2    = (const float*)d_in[4];
    const float* b2    = (const float*)d_in[5];
    const float* Wout  = (const float*)d_in[6];
    const float* bout  = (const float*)d_in[7];
    float* out = (float*)d_out;

    __half *Gf16, *Xt;
    __nv_bfloat16 *Chi, *Clo, *H2hi, *H2lo, *Nhi, *Nlo;
    __nv_bfloat16 *W1hi, *W1lo, *W2hi, *W2lo, *Wohi, *Wolo;
    float* H1;
    cudaGetSymbolAddress((void**)&Gf16, g_Gf16);
    cudaGetSymbolAddress((void**)&Xt, g_Xt);
    cudaGetSymbolAddress((void**)&Chi, g_Chi);
    cudaGetSymbolAddress((void**)&Clo, g_Clo);
    cudaGetSymbolAddress((void**)&H1, g_H1);
    cudaGetSymbolAddress((void**)&H2hi, g_H2hi);
    cudaGetSymbolAddress((void**)&H2lo, g_H2lo);
    cudaGetSymbolAddress((void**)&Nhi, g_Nhi);
    cudaGetSymbolAddress((void**)&Nlo, g_Nlo);
    cudaGetSymbolAddress((void**)&W1hi, g_W1hi);
    cudaGetSymbolAddress((void**)&W1lo, g_W1lo);
    cudaGetSymbolAddress((void**)&W2hi, g_W2hi);
    cudaGetSymbolAddress((void**)&W2lo, g_W2lo);
    cudaGetSymbolAddress((void**)&Wohi, g_Wohi);
    cudaGetSymbolAddress((void**)&Wolo, g_Wolo);

    cudaFuncSetAttribute(agg_gemm, cudaFuncAttributeMaxDynamicSharedMemorySize, AG_SMEM);
    cudaFuncSetAttribute(fc_gemm<256, 1>, cudaFuncAttributeMaxDynamicSharedMemorySize, FC_SMEM);
    cudaFuncSetAttribute(fc_gemm<256, 2>, cudaFuncAttributeMaxDynamicSharedMemorySize, FC_SMEM);
    cudaFuncSetAttribute(fc_gemm<512, 3>, cudaFuncAttributeMaxDynamicSharedMemorySize, FC_SMEM);

    dim3 gAgg(1, N_ / 128, B_);       // 128 CTAs
    dim3 gFc(1, M_TOT / 128, 1);      // 128 CTAs
    dim3 gXt(64, 8, 8), bXt(32, 8);

    graph_conv<<<B_ * N_, 256>>>(graph);
    xt_build<<<gXt, bXt>>>(node);
    split_conv<<<(H_ * H_) / 1024, 256>>>(W1, W1hi, W1lo);
    split_conv<<<(M_TOT * H_) / 1024, 256>>>(node, Nhi, Nlo);
    agg_gemm<<<gAgg, 512, AG_SMEM>>>(Gf16, Xt, Chi, Clo);
    fc_gemm<256, 1><<<gFc, 512, FC_SMEM>>>(Chi, Clo, nullptr, nullptr,
                                           W1hi, W1lo, b1, H1, nullptr, nullptr);
    xt_build<<<gXt, bXt>>>(H1);
    split_conv<<<(H_ * H_) / 1024, 256>>>(W2, W2hi, W2lo);
    agg_gemm<<<gAgg, 512, AG_SMEM>>>(Gf16, Xt, Chi, Clo);
    fc_gemm<256, 2><<<gFc, 512, FC_SMEM>>>(Chi, Clo, nullptr, nullptr,
                                           W2hi, W2lo, b2, nullptr, H2hi, H2lo);
    split_conv<<<(H_ * 2 * H_) / 1024, 256>>>(Wout, Wohi, Wolo);
    fc_gemm<512, 3><<<gFc, 512, FC_SMEM>>>(Nhi, Nlo, H2hi, H2lo,
                                           Wohi, Wolo, bout, out, nullptr, nullptr);
}

// round 8
// speedup vs baseline: 5.5622x; 1.2449x over previous
#include <cuda_runtime.h>
#include <cuda_fp16.h>
#include <cstdint>

#define B_ 8
#define N_ 2048
#define H_ 256
#define M_TOT (B_ * N_)  // 16384

// ---------------------------------------------------------------------------
// Device scratch (fp16 everywhere)
// ---------------------------------------------------------------------------
__device__ __half g_Gf16[(size_t)B_ * N_ * N_];
__device__ __half g_Xt[(size_t)B_ * H_ * N_];
__device__ __half g_C[(size_t)M_TOT * H_];
__device__ __half g_H1[(size_t)M_TOT * H_];
__device__ __half g_H2[(size_t)M_TOT * H_];
__device__ __half g_Nf[(size_t)M_TOT * H_];
__device__ __half g_W1[H_ * H_];
__device__ __half g_W2[H_ * H_];
__device__ __half g_Wo[H_ * 2 * H_];
__device__ float  g_dinv[B_ * N_];

// ---------------------------------------------------------------------------
// PTX helpers (sm_80-portable only)
// ---------------------------------------------------------------------------
__device__ __forceinline__ uint32_t s2u(const void* p) {
    uint32_t r;
    asm("{ .reg .u64 t; cvta.to.shared.u64 t, %1; cvt.u32.u64 %0, t; }"
        : "=r"(r) : "l"(p));
    return r;
}
__device__ __forceinline__ void cp16(uint32_t s, const void* g) {
    asm volatile("cp.async.cg.shared.global [%0], [%1], 16;" :: "r"(s), "l"(g) : "memory");
}
#define CP_COMMIT() asm volatile("cp.async.commit_group;" ::: "memory")
#define CP_WAITG2() asm volatile("cp.async.wait_group 2;" ::: "memory")

__device__ __forceinline__ void ldsm4(uint32_t* r, uint32_t a) {
    asm volatile("ldmatrix.sync.aligned.m8n8.x4.shared.b16 {%0,%1,%2,%3}, [%4];"
                 : "=r"(r[0]), "=r"(r[1]), "=r"(r[2]), "=r"(r[3]) : "r"(a));
}
__device__ __forceinline__ void mma_f16(float* d, const uint32_t* a, const uint32_t* b) {
    asm volatile(
        "mma.sync.aligned.m16n8k16.row.col.f32.f16.f16.f32 "
        "{%0,%1,%2,%3}, {%4,%5,%6,%7}, {%8,%9}, {%0,%1,%2,%3};"
        : "+f"(d[0]), "+f"(d[1]), "+f"(d[2]), "+f"(d[3])
        : "r"(a[0]), "r"(a[1]), "r"(a[2]), "r"(a[3]), "r"(b[0]), "r"(b[1]));
}
__device__ __forceinline__ uint32_t packh2(float a, float b) {
    __half2 t(__float2half_rn(a), __float2half_rn(b));
    return *reinterpret_cast<uint32_t*>(&t);
}

// ---------------------------------------------------------------------------
// graph -> fp16 + fused row-sum -> dinv
// ---------------------------------------------------------------------------
__global__ void graph_conv(const float* __restrict__ graph) {
    int row = blockIdx.x;
    size_t base = (size_t)row * N_;
    float s = 0.f;
#pragma unroll
    for (int it = 0; it < 2; it++) {
        int j = (threadIdx.x + it * 256) * 4;
        float4 v = *(const float4*)(graph + base + j);
        s += v.x + v.y + v.z + v.w;
        *(uint2*)(g_Gf16 + base + j) =
            make_uint2(packh2(v.x, v.y), packh2(v.z, v.w));
    }
#pragma unroll
    for (int o = 16; o; o >>= 1) s += __shfl_down_sync(0xffffffffu, s, o);
    __shared__ float ws[8];
    int lane = threadIdx.x & 31, w = threadIdx.x >> 5;
    if (lane == 0) ws[w] = s;
    __syncthreads();
    if (threadIdx.x == 0) {
        float t = 0.f;
#pragma unroll
        for (int i = 0; i < 8; i++) t += ws[i];
        g_dinv[row] = rsqrtf(t);
    }
}

// ---------------------------------------------------------------------------
// fp32 -> fp16 convert (elementwise, 4/thread)
// ---------------------------------------------------------------------------
__global__ void fconv(const float* __restrict__ src, __half* __restrict__ dst) {
    size_t j = ((size_t)blockIdx.x * 256 + threadIdx.x) * 4;
    float4 v = *(const float4*)(src + j);
    *(uint2*)(dst + j) = make_uint2(packh2(v.x, v.y), packh2(v.z, v.w));
}

// ---------------------------------------------------------------------------
// Xt[b][n][k] = src[b][k][n] * dinv[b][k], fp16 out. T = float or __half.
// ---------------------------------------------------------------------------
template <typename T>
__global__ void xt_build(const T* __restrict__ src) {
    __shared__ float t[32][33];
    int b = blockIdx.z, k0 = blockIdx.x * 32, n0 = blockIdx.y * 32;
    const T* S = src + (size_t)b * N_ * H_;
    for (int j = threadIdx.y; j < 32; j += 8)
        t[j][threadIdx.x] = (float)S[(size_t)(k0 + j) * H_ + n0 + threadIdx.x] *
                            g_dinv[b * N_ + k0 + j];
    __syncthreads();
    for (int j = threadIdx.y; j < 32; j += 8) {
        size_t o = (size_t)(b * H_ + n0 + j) * N_ + k0 + threadIdx.x;
        g_Xt[o] = __float2half_rn(t[threadIdx.x][j]);
    }
}

// ===========================================================================
// Unified 1-pass fp16 GEMM: D[128 x 256] = A[128 x KTOT] @ B[256 x KTOT]^T
// 512 threads (16 warps 4x4), 4-stage cp.async, prefetch distance 3,
// one __syncthreads per chunk.
// MODE 0: agg  (A=G[b] LDA=N, B=Xt[b] LDB=N; epi: *dinv -> fp16)
// MODE 1: fc   (A fp16 LDA=H, B=W LDB=H;    epi: +bias relu -> fp16)
// MODE 3: cfc  (A=[A0|A1] LDA=H, B=Wo LDB=2H; epi: +bias relu -> f32)
// ===========================================================================
#define LDSB 80
#define G_A_PART 10240                      // 128 * 80
#define G_B_PART 20480                      // 256 * 80
#define G_STAGE (G_A_PART + G_B_PART)       // 30720
#define G_NSTAGE 4
#define G_SMEM (G_NSTAGE * G_STAGE)         // 122880

template <int KTOT, int MODE>
__global__ void __launch_bounds__(512, 1) gemm16(
    const __half* __restrict__ A0, const __half* __restrict__ A1,
    const __half* __restrict__ Bm,
    const float* __restrict__ bias, float* __restrict__ outf,
    __half* __restrict__ outh)
{
    extern __shared__ char smem[];
    const uint32_t sb = s2u(smem);
    constexpr int NC = KTOT / 32;
    constexpr int LDA = (MODE == 0) ? N_ : H_;
    constexpr int LDB = (MODE == 0) ? N_ : ((MODE == 3) ? 2 * H_ : H_);

    const int tid = threadIdx.x, wid = tid >> 5, lane = tid & 31;
    const int b = (MODE == 0) ? blockIdx.z : 0;
    const int m0 = blockIdx.y * 128;
    const int warp_m = (wid & 3) * 32;
    const int warp_n = (wid >> 2) * 64;

    const size_t aoff = (MODE == 0) ? ((size_t)b * N_ * N_ + (size_t)m0 * N_)
                                    : ((size_t)m0 * H_);
    const __half* pB = Bm + ((MODE == 0) ? ((size_t)b * H_ * N_) : 0);

    float acc[2][8][4];
#pragma unroll
    for (int i = 0; i < 2; i++)
#pragma unroll
        for (int j = 0; j < 8; j++)
#pragma unroll
            for (int q = 0; q < 4; q++) acc[i][j][q] = 0.f;

    auto load_stage = [&](int s, int kc) {
        const int k0 = kc * 32;
        const __half* pA;
        int ka = k0;
        if (MODE == 3 && k0 >= H_) { pA = A1 + aoff; ka = k0 - H_; }
        else                       { pA = A0 + aoff; }
        const uint32_t base = sb + s * G_STAGE;
#pragma unroll
        for (int it = 0; it < 3; it++) {
            int c = it * 512 + tid;
            if (c < 512) {
                int row = c >> 2, seg = c & 3;
                cp16(base + row * LDSB + seg * 16,
                     pA + (size_t)row * LDA + ka + seg * 8);
            } else {
                int cb = c - 512;
                int row = cb >> 2, seg = cb & 3;
                cp16(base + G_A_PART + row * LDSB + seg * 16,
                     pB + (size_t)row * LDB + k0 + seg * 8);
            }
        }
    };

    const uint32_t a_row = (uint32_t)(lane & 15);
    const uint32_t a_cb  = (uint32_t)((lane >> 4) * 16);
    const uint32_t b_row = (uint32_t)((lane & 7) + ((lane & 16) ? 8 : 0));
    const uint32_t b_cb  = (uint32_t)((lane & 8) << 1);

    load_stage(0, 0); CP_COMMIT();
    load_stage(1, 1); CP_COMMIT();
    load_stage(2, 2); CP_COMMIT();

    for (int k = 0; k < NC; k++) {
        CP_WAITG2();
        __syncthreads();

        if (k + 3 < NC) load_stage((k + 3) % G_NSTAGE, k + 3);
        CP_COMMIT();

        const uint32_t sA = sb + (k % G_NSTAGE) * G_STAGE;
        const uint32_t sB = sA + G_A_PART;

#pragma unroll
        for (int ks = 0; ks < 2; ks++) {
            const uint32_t kb = ks * 32;
            uint32_t Af[2][4];
#pragma unroll
            for (int mi = 0; mi < 2; mi++) {
                uint32_t ra = (warp_m + mi * 16 + a_row) * LDSB + kb + a_cb;
                ldsm4(Af[mi], sA + ra);
            }
#pragma unroll
            for (int g = 0; g < 4; g++) {
                uint32_t rb = (warp_n + g * 16 + b_row) * LDSB + kb + b_cb;
                uint32_t th[4];
                ldsm4(th, sB + rb);
#pragma unroll
                for (int mi = 0; mi < 2; mi++) {
                    mma_f16(acc[mi][2 * g],     Af[mi], th);
                    mma_f16(acc[mi][2 * g + 1], Af[mi], th + 2);
                }
            }
        }
    }

    // ------------------------------------------------------------------ epi
    const int colb = warp_n + (lane & 3) * 2;
#pragma unroll
    for (int mi = 0; mi < 2; mi++) {
#pragma unroll
        for (int p = 0; p < 2; p++) {
            const int m = m0 + warp_m + mi * 16 + (lane >> 2) + p * 8;
            if (MODE == 0) {
                const float dv = g_dinv[b * N_ + m];
                const size_t orow = ((size_t)(b * N_ + m)) * H_;
#pragma unroll
                for (int ni = 0; ni < 8; ni++) {
                    *(uint32_t*)(outh + orow + colb + ni * 8) =
                        packh2(acc[mi][ni][2 * p] * dv, acc[mi][ni][2 * p + 1] * dv);
                }
            } else if (MODE == 1) {
                const size_t orow = (size_t)m * H_;
#pragma unroll
                for (int ni = 0; ni < 8; ni++) {
                    int c = colb + ni * 8;
                    *(uint32_t*)(outh + orow + c) =
                        packh2(fmaxf(acc[mi][ni][2 * p]     + bias[c],     0.f),
                               fmaxf(acc[mi][ni][2 * p + 1] + bias[c + 1], 0.f));
                }
            } else {
                const size_t orow = (size_t)m * H_;
#pragma unroll
                for (int ni = 0; ni < 8; ni++) {
                    int c = colb + ni * 8;
                    float2 o;
                    o.x = fmaxf(acc[mi][ni][2 * p]     + bias[c],     0.f);
                    o.y = fmaxf(acc[mi][ni][2 * p + 1] + bias[c + 1], 0.f);
                    *(float2*)(outf + orow + c) = o;
                }
            }
        }
    }
}

// ---------------------------------------------------------------------------
// Launch
// ---------------------------------------------------------------------------
extern "C" void kernel_launch(void* const* d_in, const int* in_sizes, int n_in,
                              void* d_out, int out_size) {
    const float* node  = (const float*)d_in[0];
    const float* graph = (const float*)d_in[1];
    const float* W1    = (const float*)d_in[2];
    const float* b1    = (const float*)d_in[3];
    const float* W2    = (const float*)d_in[4];
    const float* b2    = (const float*)d_in[5];
    const float* Wout  = (const float*)d_in[6];
    const float* bout  = (const float*)d_in[7];
    float* out = (float*)d_out;

    __half *Gf16, *Xt, *C, *H1, *H2, *Nf, *W1h, *W2h, *Woh;
    cudaGetSymbolAddress((void**)&Gf16, g_Gf16);
    cudaGetSymbolAddress((void**)&Xt, g_Xt);
    cudaGetSymbolAddress((void**)&C, g_C);
    cudaGetSymbolAddress((void**)&H1, g_H1);
    cudaGetSymbolAddress((void**)&H2, g_H2);
    cudaGetSymbolAddress((void**)&Nf, g_Nf);
    cudaGetSymbolAddress((void**)&W1h, g_W1);
    cudaGetSymbolAddress((void**)&W2h, g_W2);
    cudaGetSymbolAddress((void**)&Woh, g_Wo);

    cudaFuncSetAttribute(gemm16<2048, 0>, cudaFuncAttributeMaxDynamicSharedMemorySize, G_SMEM);
    cudaFuncSetAttribute(gemm16<256, 1>,  cudaFuncAttributeMaxDynamicSharedMemorySize, G_SMEM);
    cudaFuncSetAttribute(gemm16<512, 3>,  cudaFuncAttributeMaxDynamicSharedMemorySize, G_SMEM);

    dim3 gAgg(1, N_ / 128, B_);       // 128 CTAs
    dim3 gFc(1, M_TOT / 128, 1);      // 128 CTAs
    dim3 gXt(64, 8, 8), bXt(32, 8);

    graph_conv<<<B_ * N_, 256>>>(graph);
    xt_build<float><<<gXt, bXt>>>(node);
    fconv<<<(M_TOT * H_) / 1024, 256>>>(node, Nf);
    fconv<<<(H_ * H_) / 1024, 256>>>(W1, W1h);
    fconv<<<(H_ * H_) / 1024, 256>>>(W2, W2h);
    fconv<<<(H_ * 2 * H_) / 1024, 256>>>(Wout, Woh);

    // Layer 1
    gemm16<2048, 0><<<gAgg, 512, G_SMEM>>>(Gf16, nullptr, Xt, nullptr, nullptr, C);
    gemm16<256, 1><<<gFc, 512, G_SMEM>>>(C, nullptr, W1h, b1, nullptr, H1);
    xt_build<__half><<<gXt, bXt>>>(H1);

    // Layer 2
    gemm16<2048, 0><<<gAgg, 512, G_SMEM>>>(Gf16, nullptr, Xt, nullptr, nullptr, C);
    gemm16<256, 1><<<gFc, 512, G_SMEM>>>(C, nullptr, W2h, b2, nullptr, H2);

    // Output: concat([node, h]) @ Wout^T + bout, relu
    gemm16<512, 3><<<gFc, 512, G_SMEM>>>(Nf, H2, Woh, bout, out, nullptr);
}

// round 9
// speedup vs baseline: 6.1555x; 1.1067x over previous
#include <cuda_runtime.h>
#include <cuda_fp16.h>
#include <cstdint>

#define B_ 8
#define N_ 2048
#define H_ 256
#define M_TOT (B_ * N_)  // 16384

// ---------------------------------------------------------------------------
// Device scratch (fp16 everywhere)
// ---------------------------------------------------------------------------
__device__ __half g_Gf16[(size_t)B_ * N_ * N_];
__device__ __half g_Xt[(size_t)B_ * H_ * N_];
__device__ __half g_C[(size_t)M_TOT * H_];
__device__ __half g_H1[(size_t)M_TOT * H_];
__device__ __half g_H2[(size_t)M_TOT * H_];
__device__ __half g_Nf[(size_t)M_TOT * H_];
__device__ __half g_W1[H_ * H_];
__device__ __half g_W2[H_ * H_];
__device__ __half g_Wo[H_ * 2 * H_];
__device__ float  g_dinv[B_ * N_];

// ---------------------------------------------------------------------------
// PTX helpers (sm_80-portable only)
// ---------------------------------------------------------------------------
__device__ __forceinline__ uint32_t s2u(const void* p) {
    uint32_t r;
    asm("{ .reg .u64 t; cvta.to.shared.u64 t, %1; cvt.u32.u64 %0, t; }"
        : "=r"(r) : "l"(p));
    return r;
}
__device__ __forceinline__ void cp16(uint32_t s, const void* g) {
    asm volatile("cp.async.cg.shared.global [%0], [%1], 16;" :: "r"(s), "l"(g) : "memory");
}
#define CP_COMMIT() asm volatile("cp.async.commit_group;" ::: "memory")
#define CP_WAITG1() asm volatile("cp.async.wait_group 1;" ::: "memory")

__device__ __forceinline__ void ldsm4(uint32_t* r, uint32_t a) {
    asm volatile("ldmatrix.sync.aligned.m8n8.x4.shared.b16 {%0,%1,%2,%3}, [%4];"
                 : "=r"(r[0]), "=r"(r[1]), "=r"(r[2]), "=r"(r[3]) : "r"(a));
}
__device__ __forceinline__ void mma_f16(float* d, const uint32_t* a, const uint32_t* b) {
    asm volatile(
        "mma.sync.aligned.m16n8k16.row.col.f32.f16.f16.f32 "
        "{%0,%1,%2,%3}, {%4,%5,%6,%7}, {%8,%9}, {%0,%1,%2,%3};"
        : "+f"(d[0]), "+f"(d[1]), "+f"(d[2]), "+f"(d[3])
        : "r"(a[0]), "r"(a[1]), "r"(a[2]), "r"(a[3]), "r"(b[0]), "r"(b[1]));
}
__device__ __forceinline__ uint32_t packh2(float a, float b) {
    __half2 t(__float2half_rn(a), __float2half_rn(b));
    return *reinterpret_cast<uint32_t*>(&t);
}

// ---------------------------------------------------------------------------
// graph -> fp16 + fused row-sum -> dinv
// ---------------------------------------------------------------------------
__global__ void graph_conv(const float* __restrict__ graph) {
    int row = blockIdx.x;
    size_t base = (size_t)row * N_;
    float s = 0.f;
#pragma unroll
    for (int it = 0; it < 2; it++) {
        int j = (threadIdx.x + it * 256) * 4;
        float4 v = *(const float4*)(graph + base + j);
        s += v.x + v.y + v.z + v.w;
        *(uint2*)(g_Gf16 + base + j) =
            make_uint2(packh2(v.x, v.y), packh2(v.z, v.w));
    }
#pragma unroll
    for (int o = 16; o; o >>= 1) s += __shfl_down_sync(0xffffffffu, s, o);
    __shared__ float ws[8];
    int lane = threadIdx.x & 31, w = threadIdx.x >> 5;
    if (lane == 0) ws[w] = s;
    __syncthreads();
    if (threadIdx.x == 0) {
        float t = 0.f;
#pragma unroll
        for (int i = 0; i < 8; i++) t += ws[i];
        g_dinv[row] = rsqrtf(t);
    }
}

// ---------------------------------------------------------------------------
// fp32 -> fp16 convert (elementwise, 4/thread)
// ---------------------------------------------------------------------------
__global__ void fconv(const float* __restrict__ src, __half* __restrict__ dst) {
    size_t j = ((size_t)blockIdx.x * 256 + threadIdx.x) * 4;
    float4 v = *(const float4*)(src + j);
    *(uint2*)(dst + j) = make_uint2(packh2(v.x, v.y), packh2(v.z, v.w));
}

// ---------------------------------------------------------------------------
// Xt[b][n][k] = src[b][k][n] * dinv[b][k], fp16 out. T = float or __half.
// ---------------------------------------------------------------------------
template <typename T>
__global__ void xt_build(const T* __restrict__ src) {
    __shared__ float t[32][33];
    int b = blockIdx.z, k0 = blockIdx.x * 32, n0 = blockIdx.y * 32;
    const T* S = src + (size_t)b * N_ * H_;
    for (int j = threadIdx.y; j < 32; j += 8)
        t[j][threadIdx.x] = (float)S[(size_t)(k0 + j) * H_ + n0 + threadIdx.x] *
                            g_dinv[b * N_ + k0 + j];
    __syncthreads();
    for (int j = threadIdx.y; j < 32; j += 8) {
        size_t o = (size_t)(b * H_ + n0 + j) * N_ + k0 + threadIdx.x;
        g_Xt[o] = __float2half_rn(t[threadIdx.x][j]);
    }
}

// ===========================================================================
// Unified 1-pass fp16 GEMM: D[128 x 256] = A[128 x KTOT] @ B[256 x KTOT]^T
// 512 threads (16 warps 4x4), BK=64, 3-stage cp.async, prefetch distance 2,
// one __syncthreads per chunk. Smem rows 64 fp16 + pad (144B stride).
// MODE 0: agg  (A=G[b] LDA=N, B=Xt[b] LDB=N; epi: *dinv -> fp16)
// MODE 1: fc   (A fp16 LDA=H, B=W LDB=H;    epi: +bias relu -> fp16)
// MODE 3: cfc  (A=[A0|A1] LDA=H, B=Wo LDB=2H; epi: +bias relu -> f32)
// ===========================================================================
#define LDSB 144                            // 64 fp16 = 128B + 16B pad
#define G_A_PART (128 * LDSB)               // 18432
#define G_B_PART (256 * LDSB)               // 36864
#define G_STAGE (G_A_PART + G_B_PART)       // 55296
#define G_NSTAGE 3
#define G_SMEM (G_NSTAGE * G_STAGE)         // 165888

template <int KTOT, int MODE>
__global__ void __launch_bounds__(512, 1) gemm16(
    const __half* __restrict__ A0, const __half* __restrict__ A1,
    const __half* __restrict__ Bm,
    const float* __restrict__ bias, float* __restrict__ outf,
    __half* __restrict__ outh)
{
    extern __shared__ char smem[];
    const uint32_t sb = s2u(smem);
    constexpr int NC = KTOT / 64;
    constexpr int LDA = (MODE == 0) ? N_ : H_;
    constexpr int LDB = (MODE == 0) ? N_ : ((MODE == 3) ? 2 * H_ : H_);

    const int tid = threadIdx.x, wid = tid >> 5, lane = tid & 31;
    const int b = (MODE == 0) ? blockIdx.z : 0;
    const int m0 = blockIdx.y * 128;
    const int warp_m = (wid & 3) * 32;
    const int warp_n = (wid >> 2) * 64;

    const size_t aoff = (MODE == 0) ? ((size_t)b * N_ * N_ + (size_t)m0 * N_)
                                    : ((size_t)m0 * H_);
    const __half* pB = Bm + ((MODE == 0) ? ((size_t)b * H_ * N_) : 0);

    float acc[2][8][4];
#pragma unroll
    for (int i = 0; i < 2; i++)
#pragma unroll
        for (int j = 0; j < 8; j++)
#pragma unroll
            for (int q = 0; q < 4; q++) acc[i][j][q] = 0.f;

    // Stage load: A 128 rows x 8 segs = 1024 cp16, B 256 x 8 = 2048 cp16
    auto load_stage = [&](int s, int kc) {
        const int k0 = kc * 64;
        const __half* pA;
        int ka = k0;
        if (MODE == 3 && k0 >= H_) { pA = A1 + aoff; ka = k0 - H_; }
        else                       { pA = A0 + aoff; }
        const uint32_t base = sb + s * G_STAGE;
#pragma unroll
        for (int it = 0; it < 6; it++) {
            int c = it * 512 + tid;
            if (c < 1024) {
                int row = c >> 3, seg = c & 7;
                cp16(base + row * LDSB + seg * 16,
                     pA + (size_t)row * LDA + ka + seg * 8);
            } else {
                int cb = c - 1024;
                int row = cb >> 3, seg = cb & 7;
                cp16(base + G_A_PART + row * LDSB + seg * 16,
                     pB + (size_t)row * LDB + k0 + seg * 8);
            }
        }
    };

    const uint32_t a_row = (uint32_t)(lane & 15);
    const uint32_t a_cb  = (uint32_t)((lane >> 4) * 16);
    const uint32_t b_row = (uint32_t)((lane & 7) + ((lane & 16) ? 8 : 0));
    const uint32_t b_cb  = (uint32_t)((lane & 8) << 1);

    load_stage(0, 0); CP_COMMIT();
    load_stage(1, 1); CP_COMMIT();

    for (int k = 0; k < NC; k++) {
        CP_WAITG1();
        __syncthreads();

        if (k + 2 < NC) load_stage((k + 2) % G_NSTAGE, k + 2);
        CP_COMMIT();

        const uint32_t sA = sb + (k % G_NSTAGE) * G_STAGE;
        const uint32_t sB = sA + G_A_PART;

#pragma unroll
        for (int ks = 0; ks < 4; ks++) {
            const uint32_t kb = ks * 32;  // 16 fp16 = 32 bytes per K-step
            uint32_t Af[2][4];
#pragma unroll
            for (int mi = 0; mi < 2; mi++) {
                uint32_t ra = (warp_m + mi * 16 + a_row) * LDSB + kb + a_cb;
                ldsm4(Af[mi], sA + ra);
            }
#pragma unroll
            for (int g = 0; g < 4; g++) {
                uint32_t rb = (warp_n + g * 16 + b_row) * LDSB + kb + b_cb;
                uint32_t th[4];
                ldsm4(th, sB + rb);
#pragma unroll
                for (int mi = 0; mi < 2; mi++) {
                    mma_f16(acc[mi][2 * g],     Af[mi], th);
                    mma_f16(acc[mi][2 * g + 1], Af[mi], th + 2);
                }
            }
        }
    }

    // ------------------------------------------------------------------ epi
    const int colb = warp_n + (lane & 3) * 2;
#pragma unroll
    for (int mi = 0; mi < 2; mi++) {
#pragma unroll
        for (int p = 0; p < 2; p++) {
            const int m = m0 + warp_m + mi * 16 + (lane >> 2) + p * 8;
            if (MODE == 0) {
                const float dv = g_dinv[b * N_ + m];
                const size_t orow = ((size_t)(b * N_ + m)) * H_;
#pragma unroll
                for (int ni = 0; ni < 8; ni++) {
                    *(uint32_t*)(outh + orow + colb + ni * 8) =
                        packh2(acc[mi][ni][2 * p] * dv, acc[mi][ni][2 * p + 1] * dv);
                }
            } else if (MODE == 1) {
                const size_t orow = (size_t)m * H_;
#pragma unroll
                for (int ni = 0; ni < 8; ni++) {
                    int c = colb + ni * 8;
                    *(uint32_t*)(outh + orow + c) =
                        packh2(fmaxf(acc[mi][ni][2 * p]     + bias[c],     0.f),
                               fmaxf(acc[mi][ni][2 * p + 1] + bias[c + 1], 0.f));
                }
            } else {
                const size_t orow = (size_t)m * H_;
#pragma unroll
                for (int ni = 0; ni < 8; ni++) {
                    int c = colb + ni * 8;
                    float2 o;
                    o.x = fmaxf(acc[mi][ni][2 * p]     + bias[c],     0.f);
                    o.y = fmaxf(acc[mi][ni][2 * p + 1] + bias[c + 1], 0.f);
                    *(float2*)(outf + orow + c) = o;
                }
            }
        }
    }
}

// ---------------------------------------------------------------------------
// Launch — agg1 is launch index 5 so ncu (-s 5 -c 1) captures it.
// ---------------------------------------------------------------------------
extern "C" void kernel_launch(void* const* d_in, const int* in_sizes, int n_in,
                              void* d_out, int out_size) {
    const float* node  = (const float*)d_in[0];
    const float* graph = (const float*)d_in[1];
    const float* W1    = (const float*)d_in[2];
    const float* b1    = (const float*)d_in[3];
    const float* W2    = (const float*)d_in[4];
    const float* b2    = (const float*)d_in[5];
    const float* Wout  = (const float*)d_in[6];
    const float* bout  = (const float*)d_in[7];
    float* out = (float*)d_out;

    __half *Gf16, *Xt, *C, *H1, *H2, *Nf, *W1h, *W2h, *Woh;
    cudaGetSymbolAddress((void**)&Gf16, g_Gf16);
    cudaGetSymbolAddress((void**)&Xt, g_Xt);
    cudaGetSymbolAddress((void**)&C, g_C);
    cudaGetSymbolAddress((void**)&H1, g_H1);
    cudaGetSymbolAddress((void**)&H2, g_H2);
    cudaGetSymbolAddress((void**)&Nf, g_Nf);
    cudaGetSymbolAddress((void**)&W1h, g_W1);
    cudaGetSymbolAddress((void**)&W2h, g_W2);
    cudaGetSymbolAddress((void**)&Woh, g_Wo);

    cudaFuncSetAttribute(gemm16<2048, 0>, cudaFuncAttributeMaxDynamicSharedMemorySize, G_SMEM);
    cudaFuncSetAttribute(gemm16<256, 1>,  cudaFuncAttributeMaxDynamicSharedMemorySize, G_SMEM);
    cudaFuncSetAttribute(gemm16<512, 3>,  cudaFuncAttributeMaxDynamicSharedMemorySize, G_SMEM);

    dim3 gAgg(1, N_ / 128, B_);       // 128 CTAs
    dim3 gFc(1, M_TOT / 128, 1);      // 128 CTAs
    dim3 gXt(64, 8, 8), bXt(32, 8);

    graph_conv<<<B_ * N_, 256>>>(graph);                     // 0
    xt_build<float><<<gXt, bXt>>>(node);                     // 1
    fconv<<<(M_TOT * H_) / 1024, 256>>>(node, Nf);           // 2
    fconv<<<(H_ * H_) / 1024, 256>>>(W1, W1h);               // 3
    fconv<<<(H_ * H_) / 1024, 256>>>(W2, W2h);               // 4

    // Layer 1 — agg at launch index 5 (ncu capture target)
    gemm16<2048, 0><<<gAgg, 512, G_SMEM>>>(Gf16, nullptr, Xt, nullptr, nullptr, C);  // 5
    gemm16<256, 1><<<gFc, 512, G_SMEM>>>(C, nullptr, W1h, b1, nullptr, H1);
    xt_build<__half><<<gXt, bXt>>>(H1);

    // Layer 2
    gemm16<2048, 0><<<gAgg, 512, G_SMEM>>>(Gf16, nullptr, Xt, nullptr, nullptr, C);
    gemm16<256, 1><<<gFc, 512, G_SMEM>>>(C, nullptr, W2h, b2, nullptr, H2);

    // Output
    fconv<<<(H_ * 2 * H_) / 1024, 256>>>(Wout, Woh);
    gemm16<512, 3><<<gFc, 512, G_SMEM>>>(Nf, H2, Woh, bout, out, nullptr);
}

// round 10
// speedup vs baseline: 6.6448x; 1.0795x over previous
#include <cuda_runtime.h>
#include <cuda_fp16.h>
#include <cstdint>

#define B_ 8
#define N_ 2048
#define H_ 256
#define M_TOT (B_ * N_)  // 16384

// ---------------------------------------------------------------------------
// Device scratch (fp16 everywhere)
// ---------------------------------------------------------------------------
__device__ __half g_Gf16[(size_t)B_ * N_ * N_];
__device__ __half g_Xt[(size_t)B_ * H_ * N_];
__device__ __half g_Xt2[(size_t)B_ * H_ * N_];
__device__ __half g_H2[(size_t)M_TOT * H_];
__device__ __half g_Nf[(size_t)M_TOT * H_];
__device__ __half g_W1[H_ * H_];
__device__ __half g_W2[H_ * H_];
__device__ __half g_Wo[H_ * 2 * H_];
__device__ float  g_dinv[B_ * N_];

// ---------------------------------------------------------------------------
// PTX helpers (sm_80-portable only)
// ---------------------------------------------------------------------------
__device__ __forceinline__ uint32_t s2u(const void* p) {
    uint32_t r;
    asm("{ .reg .u64 t; cvta.to.shared.u64 t, %1; cvt.u32.u64 %0, t; }"
        : "=r"(r) : "l"(p));
    return r;
}
__device__ __forceinline__ void cp16(uint32_t s, const void* g) {
    asm volatile("cp.async.cg.shared.global [%0], [%1], 16;" :: "r"(s), "l"(g) : "memory");
}
#define CP_COMMIT() asm volatile("cp.async.commit_group;" ::: "memory")
#define CP_WAITG1() asm volatile("cp.async.wait_group 1;" ::: "memory")
#define CP_WAITG0() asm volatile("cp.async.wait_group 0;" ::: "memory")

__device__ __forceinline__ void ldsm4(uint32_t* r, uint32_t a) {
    asm volatile("ldmatrix.sync.aligned.m8n8.x4.shared.b16 {%0,%1,%2,%3}, [%4];"
                 : "=r"(r[0]), "=r"(r[1]), "=r"(r[2]), "=r"(r[3]) : "r"(a));
}
__device__ __forceinline__ void mma_f16(float* d, const uint32_t* a, const uint32_t* b) {
    asm volatile(
        "mma.sync.aligned.m16n8k16.row.col.f32.f16.f16.f32 "
        "{%0,%1,%2,%3}, {%4,%5,%6,%7}, {%8,%9}, {%0,%1,%2,%3};"
        : "+f"(d[0]), "+f"(d[1]), "+f"(d[2]), "+f"(d[3])
        : "r"(a[0]), "r"(a[1]), "r"(a[2]), "r"(a[3]), "r"(b[0]), "r"(b[1]));
}
__device__ __forceinline__ uint32_t packh2(float a, float b) {
    __half2 t(__float2half_rn(a), __float2half_rn(b));
    return *reinterpret_cast<uint32_t*>(&t);
}

// ---------------------------------------------------------------------------
// graph -> fp16 + fused row-sum -> dinv
// ---------------------------------------------------------------------------
__global__ void graph_conv(const float* __restrict__ graph) {
    int row = blockIdx.x;
    size_t base = (size_t)row * N_;
    float s = 0.f;
#pragma unroll
    for (int it = 0; it < 2; it++) {
        int j = (threadIdx.x + it * 256) * 4;
        float4 v = *(const float4*)(graph + base + j);
        s += v.x + v.y + v.z + v.w;
        *(uint2*)(g_Gf16 + base + j) =
            make_uint2(packh2(v.x, v.y), packh2(v.z, v.w));
    }
#pragma unroll
    for (int o = 16; o; o >>= 1) s += __shfl_down_sync(0xffffffffu, s, o);
    __shared__ float ws[8];
    int lane = threadIdx.x & 31, w = threadIdx.x >> 5;
    if (lane == 0) ws[w] = s;
    __syncthreads();
    if (threadIdx.x == 0) {
        float t = 0.f;
#pragma unroll
        for (int i = 0; i < 8; i++) t += ws[i];
        g_dinv[row] = rsqrtf(t);
    }
}

// ---------------------------------------------------------------------------
// fp32 -> fp16 convert (elementwise, 4/thread)
// ---------------------------------------------------------------------------
__global__ void fconv(const float* __restrict__ src, __half* __restrict__ dst) {
    size_t j = ((size_t)blockIdx.x * 256 + threadIdx.x) * 4;
    float4 v = *(const float4*)(src + j);
    *(uint2*)(dst + j) = make_uint2(packh2(v.x, v.y), packh2(v.z, v.w));
}

// ---------------------------------------------------------------------------
// Xt[b][n][k] = src[b][k][n] * dinv[b][k], fp16 out (layer-1 input)
// ---------------------------------------------------------------------------
__global__ void xt_build(const float* __restrict__ src) {
    __shared__ float t[32][33];
    int b = blockIdx.z, k0 = blockIdx.x * 32, n0 = blockIdx.y * 32;
    const float* S = src + (size_t)b * N_ * H_;
    for (int j = threadIdx.y; j < 32; j += 8)
        t[j][threadIdx.x] = S[(size_t)(k0 + j) * H_ + n0 + threadIdx.x] *
                            g_dinv[b * N_ + k0 + j];
    __syncthreads();
    for (int j = threadIdx.y; j < 32; j += 8) {
        size_t o = (size_t)(b * H_ + n0 + j) * N_ + k0 + threadIdx.x;
        g_Xt[o] = __float2half_rn(t[threadIdx.x][j]);
    }
}

// ===========================================================================
// Fused agg+FC: per CTA tile [128 tokens x 256 feat]:
//   C   = dinv[m] * (G[b] @ Xin^T)            (mainloop, BK=64, 3 stages)
//   Hfc = relu(C @ W^T + bias)                (epilogue GEMM, W via cp.async)
// MODE_FC 0: write Hfc transposed*dinv -> Xt2[b][h][tok]   (layer 1)
// MODE_FC 1: write Hfc row-major -> H2                     (layer 2)
// ===========================================================================
#define LDSB 144                            // pipeline rows: 64 fp16 + pad
#define G_A_PART (128 * LDSB)               // 18432
#define G_B_PART (256 * LDSB)               // 36864
#define G_STAGE (G_A_PART + G_B_PART)       // 55296
#define G_NSTAGE 3
#define G_SMEM (G_NSTAGE * G_STAGE)         // 165888
// FC-phase smem (reuses pipeline region):
#define CLD 528                             // C rows: 256 fp16 + 16B pad
#define C_BYTES (128 * CLD)                 // 67584
#define WB0_OFF 67584
#define WB1_OFF 104448                      // WB0_OFF + 256*144
#define HT_LD 272                           // transposed H rows: 128 fp16 + pad

template <int MODE_FC>
__global__ void __launch_bounds__(512, 1) aggfc(
    const __half* __restrict__ G, const __half* __restrict__ Xin,
    const __half* __restrict__ W, const float* __restrict__ bias,
    __half* __restrict__ out)
{
    extern __shared__ char smem[];
    const uint32_t sb = s2u(smem);
    constexpr int NC = N_ / 64;  // 32

    const int tid = threadIdx.x, wid = tid >> 5, lane = tid & 31;
    const int b = blockIdx.z;
    const int m0 = blockIdx.y * 128;
    const int warp_m = (wid & 3) * 32;
    const int warp_n = (wid >> 2) * 64;

    const __half* pA = G + (size_t)b * N_ * N_ + (size_t)m0 * N_;
    const __half* pB = Xin + (size_t)b * H_ * N_;

    float acc[2][8][4];
#pragma unroll
    for (int i = 0; i < 2; i++)
#pragma unroll
        for (int j = 0; j < 8; j++)
#pragma unroll
            for (int q = 0; q < 4; q++) acc[i][j][q] = 0.f;

    auto load_stage = [&](int s, int kc) {
        const int k0 = kc * 64;
        const uint32_t base = sb + s * G_STAGE;
#pragma unroll
        for (int it = 0; it < 6; it++) {
            int c = it * 512 + tid;
            if (c < 1024) {
                int row = c >> 3, seg = c & 7;
                cp16(base + row * LDSB + seg * 16,
                     pA + (size_t)row * N_ + k0 + seg * 8);
            } else {
                int cb = c - 1024;
                int row = cb >> 3, seg = cb & 7;
                cp16(base + G_A_PART + row * LDSB + seg * 16,
                     pB + (size_t)row * N_ + k0 + seg * 8);
            }
        }
    };

    const uint32_t a_row = (uint32_t)(lane & 15);
    const uint32_t a_cb  = (uint32_t)((lane >> 4) * 16);
    const uint32_t b_row = (uint32_t)((lane & 7) + ((lane & 16) ? 8 : 0));
    const uint32_t b_cb  = (uint32_t)((lane & 8) << 1);

    load_stage(0, 0); CP_COMMIT();
    load_stage(1, 1); CP_COMMIT();

    for (int k = 0; k < NC; k++) {
        CP_WAITG1();
        __syncthreads();

        if (k + 2 < NC) load_stage((k + 2) % G_NSTAGE, k + 2);
        CP_COMMIT();

        const uint32_t sA = sb + (k % G_NSTAGE) * G_STAGE;
        const uint32_t sB = sA + G_A_PART;

#pragma unroll
        for (int ks = 0; ks < 4; ks++) {
            const uint32_t kb = ks * 32;
            uint32_t Af[2][4];
#pragma unroll
            for (int mi = 0; mi < 2; mi++) {
                uint32_t ra = (warp_m + mi * 16 + a_row) * LDSB + kb + a_cb;
                ldsm4(Af[mi], sA + ra);
            }
#pragma unroll
            for (int g = 0; g < 4; g++) {
                uint32_t rb = (warp_n + g * 16 + b_row) * LDSB + kb + b_cb;
                uint32_t th[4];
                ldsm4(th, sB + rb);
#pragma unroll
                for (int mi = 0; mi < 2; mi++) {
                    mma_f16(acc[mi][2 * g],     Af[mi], th);
                    mma_f16(acc[mi][2 * g + 1], Af[mi], th + 2);
                }
            }
        }
    }

    // ==================================================================
    // FC phase: H = relu((dinv.*aggC) @ W^T + bias)
    // ==================================================================
    __syncthreads();   // pipeline smem fully consumed; drain pending loads
    CP_WAITG0();

    // Kick W chunk 0,1 loads (256 rows x 64 k each, 144B-stride rows)
    auto load_w = [&](uint32_t buf, int kc) {
        const int k0 = kc * 64;
#pragma unroll
        for (int it = 0; it < 4; it++) {
            int c = it * 512 + tid;
            int row = c >> 3, seg = c & 7;
            cp16(buf + row * LDSB + seg * 16,
                 W + (size_t)row * H_ + k0 + seg * 8);
        }
    };
    load_w(sb + WB0_OFF, 0); CP_COMMIT();
    load_w(sb + WB1_OFF, 1); CP_COMMIT();

    // Store C = dinv[m] * acc into smem (fp16, 528B-stride rows), re-zero acc
    const int colb = warp_n + (lane & 3) * 2;
#pragma unroll
    for (int mi = 0; mi < 2; mi++) {
#pragma unroll
        for (int p = 0; p < 2; p++) {
            const int ml = warp_m + mi * 16 + (lane >> 2) + p * 8;
            const float dv = g_dinv[b * N_ + m0 + ml];
#pragma unroll
            for (int ni = 0; ni < 8; ni++) {
                *(uint32_t*)(smem + ml * CLD + (colb + ni * 8) * 2) =
                    packh2(acc[mi][ni][2 * p] * dv, acc[mi][ni][2 * p + 1] * dv);
            }
        }
    }
#pragma unroll
    for (int i = 0; i < 2; i++)
#pragma unroll
        for (int j = 0; j < 8; j++)
#pragma unroll
            for (int q = 0; q < 4; q++) acc[i][j][q] = 0.f;

    CP_WAITG1();        // W chunk0 arrived (this thread)
    __syncthreads();    // C + chunk0 visible to all

    auto fc_chunk = [&](int kc, uint32_t wb) {
#pragma unroll
        for (int ks = 0; ks < 4; ks++) {
            const uint32_t kb = ks * 32;
            uint32_t Af[2][4];
#pragma unroll
            for (int mi = 0; mi < 2; mi++) {
                uint32_t ra = (warp_m + mi * 16 + a_row) * CLD + kc * 128 + kb + a_cb;
                ldsm4(Af[mi], sb + ra);
            }
#pragma unroll
            for (int g = 0; g < 4; g++) {
                uint32_t rb = (warp_n + g * 16 + b_row) * LDSB + kb + b_cb;
                uint32_t th[4];
                ldsm4(th, wb + rb);
#pragma unroll
                for (int mi = 0; mi < 2; mi++) {
                    mma_f16(acc[mi][2 * g],     Af[mi], th);
                    mma_f16(acc[mi][2 * g + 1], Af[mi], th + 2);
                }
            }
        }
    };

    fc_chunk(0, sb + WB0_OFF);
    __syncthreads();                      // all warps done with WB0
    load_w(sb + WB0_OFF, 2); CP_COMMIT();
    CP_WAITG1(); __syncthreads();         // chunk1 visible
    fc_chunk(1, sb + WB1_OFF);
    __syncthreads();
    load_w(sb + WB1_OFF, 3); CP_COMMIT();
    CP_WAITG1(); __syncthreads();         // chunk2 visible
    fc_chunk(2, sb + WB0_OFF);
    CP_WAITG0(); __syncthreads();         // chunk3 visible
    fc_chunk(3, sb + WB1_OFF);

    // ------------------------------------------------------------------
    // Output
    // ------------------------------------------------------------------
    if (MODE_FC == 1) {
        // H2 row-major fp16
#pragma unroll
        for (int mi = 0; mi < 2; mi++) {
#pragma unroll
            for (int p = 0; p < 2; p++) {
                const int ml = warp_m + mi * 16 + (lane >> 2) + p * 8;
                const size_t orow = (size_t)(b * N_ + m0 + ml) * H_;
#pragma unroll
                for (int ni = 0; ni < 8; ni++) {
                    int c = colb + ni * 8;
                    *(uint32_t*)(out + orow + c) =
                        packh2(fmaxf(acc[mi][ni][2 * p]     + bias[c],     0.f),
                               fmaxf(acc[mi][ni][2 * p + 1] + bias[c + 1], 0.f));
                }
            }
        }
    } else {
        // Xt2[b][h][tok] = relu(H + bias) * dinv[tok], via smem transpose
        __syncthreads();  // C-region free (fc_chunk(3) done everywhere)
#pragma unroll
        for (int mi = 0; mi < 2; mi++) {
#pragma unroll
            for (int p = 0; p < 2; p++) {
                const int ml = warp_m + mi * 16 + (lane >> 2) + p * 8;
                const float dv = g_dinv[b * N_ + m0 + ml];
#pragma unroll
                for (int ni = 0; ni < 8; ni++) {
                    int c = colb + ni * 8;
                    float v0 = fmaxf(acc[mi][ni][2 * p]     + bias[c],     0.f) * dv;
                    float v1 = fmaxf(acc[mi][ni][2 * p + 1] + bias[c + 1], 0.f) * dv;
                    *(__half*)(smem + c * HT_LD + ml * 2)       = __float2half_rn(v0);
                    *(__half*)(smem + (c + 1) * HT_LD + ml * 2) = __float2half_rn(v1);
                }
            }
        }
        __syncthreads();
        // Coalesced global write: 512 threads, each one (h, 64-token segment)
        const int h = tid >> 1, seg = tid & 1;
        const char* srow = smem + h * HT_LD + seg * 128;
        __half* drow = out + (size_t)(b * H_ + h) * N_ + m0 + seg * 64;
#pragma unroll
        for (int q = 0; q < 8; q++)
            *(uint4*)(drow + q * 8) = *(const uint4*)(srow + q * 16);
    }
}

// ===========================================================================
// Output FC: out[m,0:256] = relu([Nf | H2][m,0:512] @ Wo^T + bout), f32 out
// ===========================================================================
__global__ void __launch_bounds__(512, 1) fcout(
    const __half* __restrict__ A0, const __half* __restrict__ A1,
    const __half* __restrict__ Bm,
    const float* __restrict__ bias, float* __restrict__ outf)
{
    extern __shared__ char smem[];
    const uint32_t sb = s2u(smem);
    constexpr int NC = 512 / 64;  // 8

    const int tid = threadIdx.x, wid = tid >> 5, lane = tid & 31;
    const int m0 = blockIdx.y * 128;
    const int warp_m = (wid & 3) * 32;
    const int warp_n = (wid >> 2) * 64;
    const size_t aoff = (size_t)m0 * H_;

    float acc[2][8][4];
#pragma unroll
    for (int i = 0; i < 2; i++)
#pragma unroll
        for (int j = 0; j < 8; j++)
#pragma unroll
            for (int q = 0; q < 4; q++) acc[i][j][q] = 0.f;

    auto load_stage = [&](int s, int kc) {
        const int k0 = kc * 64;
        const __half* pA;
        int ka = k0;
        if (k0 >= H_) { pA = A1 + aoff; ka = k0 - H_; }
        else          { pA = A0 + aoff; }
        const uint32_t base = sb + s * G_STAGE;
#pragma unroll
        for (int it = 0; it < 6; it++) {
            int c = it * 512 + tid;
            if (c < 1024) {
                int row = c >> 3, seg = c & 7;
                cp16(base + row * LDSB + seg * 16,
                     pA + (size_t)row * H_ + ka + seg * 8);
            } else {
                int cb = c - 1024;
                int row = cb >> 3, seg = cb & 7;
                cp16(base + G_A_PART + row * LDSB + seg * 16,
                     Bm + (size_t)row * (2 * H_) + k0 + seg * 8);
            }
        }
    };

    const uint32_t a_row = (uint32_t)(lane & 15);
    const uint32_t a_cb  = (uint32_t)((lane >> 4) * 16);
    const uint32_t b_row = (uint32_t)((lane & 7) + ((lane & 16) ? 8 : 0));
    const uint32_t b_cb  = (uint32_t)((lane & 8) << 1);

    load_stage(0, 0); CP_COMMIT();
    load_stage(1, 1); CP_COMMIT();

    for (int k = 0; k < NC; k++) {
        CP_WAITG1();
        __syncthreads();
        if (k + 2 < NC) load_stage((k + 2) % G_NSTAGE, k + 2);
        CP_COMMIT();

        const uint32_t sA = sb + (k % G_NSTAGE) * G_STAGE;
        const uint32_t sB = sA + G_A_PART;
#pragma unroll
        for (int ks = 0; ks < 4; ks++) {
            const uint32_t kb = ks * 32;
            uint32_t Af[2][4];
#pragma unroll
            for (int mi = 0; mi < 2; mi++) {
                uint32_t ra = (warp_m + mi * 16 + a_row) * LDSB + kb + a_cb;
                ldsm4(Af[mi], sA + ra);
            }
#pragma unroll
            for (int g = 0; g < 4; g++) {
                uint32_t rb = (warp_n + g * 16 + b_row) * LDSB + kb + b_cb;
                uint32_t th[4];
                ldsm4(th, sB + rb);
#pragma unroll
                for (int mi = 0; mi < 2; mi++) {
                    mma_f16(acc[mi][2 * g],     Af[mi], th);
                    mma_f16(acc[mi][2 * g + 1], Af[mi], th + 2);
                }
            }
        }
    }

    const int colb = warp_n + (lane & 3) * 2;
#pragma unroll
    for (int mi = 0; mi < 2; mi++) {
#pragma unroll
        for (int p = 0; p < 2; p++) {
            const int m = m0 + warp_m + mi * 16 + (lane >> 2) + p * 8;
            const size_t orow = (size_t)m * H_;
#pragma unroll
            for (int ni = 0; ni < 8; ni++) {
                int c = colb + ni * 8;
                float2 o;
                o.x = fmaxf(acc[mi][ni][2 * p]     + bias[c],     0.f);
                o.y = fmaxf(acc[mi][ni][2 * p + 1] + bias[c + 1], 0.f);
                *(float2*)(outf + orow + c) = o;
            }
        }
    }
}

// ---------------------------------------------------------------------------
// Launch
// ---------------------------------------------------------------------------
extern "C" void kernel_launch(void* const* d_in, const int* in_sizes, int n_in,
                              void* d_out, int out_size) {
    const float* node  = (const float*)d_in[0];
    const float* graph = (const float*)d_in[1];
    const float* W1    = (const float*)d_in[2];
    const float* b1    = (const float*)d_in[3];
    const float* W2    = (const float*)d_in[4];
    const float* b2    = (const float*)d_in[5];
    const float* Wout  = (const float*)d_in[6];
    const float* bout  = (const float*)d_in[7];
    float* out = (float*)d_out;

    __half *Gf16, *Xt, *Xt2, *H2, *Nf, *W1h, *W2h, *Woh;
    cudaGetSymbolAddress((void**)&Gf16, g_Gf16);
    cudaGetSymbolAddress((void**)&Xt, g_Xt);
    cudaGetSymbolAddress((void**)&Xt2, g_Xt2);
    cudaGetSymbolAddress((void**)&H2, g_H2);
    cudaGetSymbolAddress((void**)&Nf, g_Nf);
    cudaGetSymbolAddress((void**)&W1h, g_W1);
    cudaGetSymbolAddress((void**)&W2h, g_W2);
    cudaGetSymbolAddress((void**)&Woh, g_Wo);

    cudaFuncSetAttribute(aggfc<0>, cudaFuncAttributeMaxDynamicSharedMemorySize, G_SMEM);
    cudaFuncSetAttribute(aggfc<1>, cudaFuncAttributeMaxDynamicSharedMemorySize, G_SMEM);
    cudaFuncSetAttribute(fcout,    cudaFuncAttributeMaxDynamicSharedMemorySize, G_SMEM);

    dim3 gAgg(1, N_ / 128, B_);       // 128 CTAs
    dim3 gFc(1, M_TOT / 128, 1);      // 128 CTAs
    dim3 gXt(64, 8, 8), bXt(32, 8);

    graph_conv<<<B_ * N_, 256>>>(graph);                     // 0
    xt_build<<<gXt, bXt>>>(node);                            // 1
    fconv<<<(M_TOT * H_) / 1024, 256>>>(node, Nf);           // 2
    fconv<<<(H_ * H_) / 1024, 256>>>(W1, W1h);               // 3
    fconv<<<(H_ * H_) / 1024, 256>>>(W2, W2h);               // 4

    // Layer 1 fused: agg + FC1 -> Xt2 (transposed, dinv-scaled)
    aggfc<0><<<gAgg, 512, G_SMEM>>>(Gf16, Xt, W1h, b1, Xt2); // 5
    // Layer 2 fused: agg + FC2 -> H2 (row-major)
    aggfc<1><<<gAgg, 512, G_SMEM>>>(Gf16, Xt2, W2h, b2, H2); // 6

    // Output
    fconv<<<(H_ * 2 * H_) / 1024, 256>>>(Wout, Woh);         // 7
    fcout<<<gFc, 512, G_SMEM>>>(Nf, H2, Woh, bout, out);     // 8
}

// round 11
// speedup vs baseline: 6.9343x; 1.0436x over previous
#include <cuda_runtime.h>
#include <cuda_fp16.h>
#include <cstdint>

#define B_ 8
#define N_ 2048
#define H_ 256
#define M_TOT (B_ * N_)  // 16384

// ---------------------------------------------------------------------------
// Device scratch (fp16 everywhere)
// ---------------------------------------------------------------------------
__device__ __half g_Gf16[(size_t)B_ * N_ * N_];
__device__ __half g_Xt[(size_t)B_ * H_ * N_];
__device__ __half g_Xt2[(size_t)B_ * H_ * N_];
__device__ __half g_Nf[(size_t)M_TOT * H_];
__device__ __half g_W1[H_ * H_];
__device__ __half g_W2[H_ * H_];
__device__ __half g_Wo[H_ * 2 * H_];
__device__ float  g_dinv[B_ * N_];

// ---------------------------------------------------------------------------
// PTX helpers (sm_80-portable only)
// ---------------------------------------------------------------------------
__device__ __forceinline__ uint32_t s2u(const void* p) {
    uint32_t r;
    asm("{ .reg .u64 t; cvta.to.shared.u64 t, %1; cvt.u32.u64 %0, t; }"
        : "=r"(r) : "l"(p));
    return r;
}
__device__ __forceinline__ void cp16(uint32_t s, const void* g) {
    asm volatile("cp.async.cg.shared.global [%0], [%1], 16;" :: "r"(s), "l"(g) : "memory");
}
#define CP_COMMIT() asm volatile("cp.async.commit_group;" ::: "memory")
#define CP_WAITG1() asm volatile("cp.async.wait_group 1;" ::: "memory")
#define CP_WAITG0() asm volatile("cp.async.wait_group 0;" ::: "memory")

__device__ __forceinline__ void ldsm4(uint32_t* r, uint32_t a) {
    asm volatile("ldmatrix.sync.aligned.m8n8.x4.shared.b16 {%0,%1,%2,%3}, [%4];"
                 : "=r"(r[0]), "=r"(r[1]), "=r"(r[2]), "=r"(r[3]) : "r"(a));
}
__device__ __forceinline__ void mma_f16(float* d, const uint32_t* a, const uint32_t* b) {
    asm volatile(
        "mma.sync.aligned.m16n8k16.row.col.f32.f16.f16.f32 "
        "{%0,%1,%2,%3}, {%4,%5,%6,%7}, {%8,%9}, {%0,%1,%2,%3};"
        : "+f"(d[0]), "+f"(d[1]), "+f"(d[2]), "+f"(d[3])
        : "r"(a[0]), "r"(a[1]), "r"(a[2]), "r"(a[3]), "r"(b[0]), "r"(b[1]));
}
__device__ __forceinline__ uint32_t packh2(float a, float b) {
    __half2 t(__float2half_rn(a), __float2half_rn(b));
    return *reinterpret_cast<uint32_t*>(&t);
}

// ---------------------------------------------------------------------------
// graph -> fp16 + fused row-sum -> dinv
// ---------------------------------------------------------------------------
__global__ void graph_conv(const float* __restrict__ graph) {
    int row = blockIdx.x;
    size_t base = (size_t)row * N_;
    float s = 0.f;
#pragma unroll
    for (int it = 0; it < 2; it++) {
        int j = (threadIdx.x + it * 256) * 4;
        float4 v = *(const float4*)(graph + base + j);
        s += v.x + v.y + v.z + v.w;
        *(uint2*)(g_Gf16 + base + j) =
            make_uint2(packh2(v.x, v.y), packh2(v.z, v.w));
    }
#pragma unroll
    for (int o = 16; o; o >>= 1) s += __shfl_down_sync(0xffffffffu, s, o);
    __shared__ float ws[8];
    int lane = threadIdx.x & 31, w = threadIdx.x >> 5;
    if (lane == 0) ws[w] = s;
    __syncthreads();
    if (threadIdx.x == 0) {
        float t = 0.f;
#pragma unroll
        for (int i = 0; i < 8; i++) t += ws[i];
        g_dinv[row] = rsqrtf(t);
    }
}

// ---------------------------------------------------------------------------
// prep_node: one read of node -> Xt (transposed * dinv) AND Nf (row-major)
// ---------------------------------------------------------------------------
__global__ void prep_node(const float* __restrict__ node) {
    __shared__ float t[32][33];
    int b = blockIdx.z, k0 = blockIdx.x * 32, n0 = blockIdx.y * 32;
    const float* S = node + (size_t)b * N_ * H_;
    for (int j = threadIdx.y; j < 32; j += 8) {
        float v = S[(size_t)(k0 + j) * H_ + n0 + threadIdx.x];
        g_Nf[(size_t)(b * N_ + k0 + j) * H_ + n0 + threadIdx.x] = __float2half_rn(v);
        t[j][threadIdx.x] = v * g_dinv[b * N_ + k0 + j];
    }
    __syncthreads();
    for (int j = threadIdx.y; j < 32; j += 8) {
        size_t o = (size_t)(b * H_ + n0 + j) * N_ + k0 + threadIdx.x;
        g_Xt[o] = __float2half_rn(t[threadIdx.x][j]);
    }
}

// ---------------------------------------------------------------------------
// wconv: convert W1, W2, Wout fp32 -> fp16 in one kernel
// ---------------------------------------------------------------------------
__global__ void wconv(const float* __restrict__ W1, const float* __restrict__ W2,
                      const float* __restrict__ Wo) {
    int e = (blockIdx.x * 256 + threadIdx.x) * 4;   // 0 .. 262143
    const float* src;
    __half* dst;
    int off;
    if (e < 65536)       { src = W1; dst = g_W1; off = e; }
    else if (e < 131072) { src = W2; dst = g_W2; off = e - 65536; }
    else                 { src = Wo; dst = g_Wo; off = e - 131072; }
    float4 v = *(const float4*)(src + off);
    *(uint2*)(dst + off) = make_uint2(packh2(v.x, v.y), packh2(v.z, v.w));
}

// ===========================================================================
// Common tiling constants
// ===========================================================================
#define LDSB 144                            // pipeline rows: 64 fp16 + pad
#define G_A_PART (128 * LDSB)               // 18432
#define G_B_PART (256 * LDSB)               // 36864
#define G_STAGE (G_A_PART + G_B_PART)       // 55296
#define G_NSTAGE 3
// FC-phase smem (reuses pipeline region):
#define CLD 528                             // C/h rows: 256 fp16 + 16B pad
#define WB0_OFF 67584                       // 128*528
#define WB1_OFF 104448                      // +256*144
#define NB0_OFF 141312                      // +256*144
#define NB1_OFF 159744                      // +128*144
#define SMEM_ALL 178176                     // NB1 end
#define HT_LD 272                           // transposed h rows: 128 fp16 + pad

// ===========================================================================
// Layer 1 fused: C = dinv*(G@Xt^T); h = relu(C@W1^T+b1);
// out Xt2[b][h][tok] = h^T * dinv.
// ===========================================================================
__global__ void __launch_bounds__(512, 1) aggfc1(
    const __half* __restrict__ G, const __half* __restrict__ Xin,
    const __half* __restrict__ W, const float* __restrict__ bias,
    __half* __restrict__ out)
{
    extern __shared__ char smem[];
    const uint32_t sb = s2u(smem);
    constexpr int NC = N_ / 64;  // 32

    const int tid = threadIdx.x, wid = tid >> 5, lane = tid & 31;
    const int b = blockIdx.z;
    const int m0 = blockIdx.y * 128;
    const int warp_m = (wid & 3) * 32;
    const int warp_n = (wid >> 2) * 64;

    const __half* pA = G + (size_t)b * N_ * N_ + (size_t)m0 * N_;
    const __half* pB = Xin + (size_t)b * H_ * N_;

    float acc[2][8][4];
#pragma unroll
    for (int i = 0; i < 2; i++)
#pragma unroll
        for (int j = 0; j < 8; j++)
#pragma unroll
            for (int q = 0; q < 4; q++) acc[i][j][q] = 0.f;

    auto load_stage = [&](int s, int kc) {
        const int k0 = kc * 64;
        const uint32_t base = sb + s * G_STAGE;
#pragma unroll
        for (int it = 0; it < 6; it++) {
            int c = it * 512 + tid;
            if (c < 1024) {
                int row = c >> 3, seg = c & 7;
                cp16(base + row * LDSB + seg * 16,
                     pA + (size_t)row * N_ + k0 + seg * 8);
            } else {
                int cb = c - 1024;
                int row = cb >> 3, seg = cb & 7;
                cp16(base + G_A_PART + row * LDSB + seg * 16,
                     pB + (size_t)row * N_ + k0 + seg * 8);
            }
        }
    };

    const uint32_t a_row = (uint32_t)(lane & 15);
    const uint32_t a_cb  = (uint32_t)((lane >> 4) * 16);
    const uint32_t b_row = (uint32_t)((lane & 7) + ((lane & 16) ? 8 : 0));
    const uint32_t b_cb  = (uint32_t)((lane & 8) << 1);

    load_stage(0, 0); CP_COMMIT();
    load_stage(1, 1); CP_COMMIT();

    for (int k = 0; k < NC; k++) {
        CP_WAITG1();
        __syncthreads();
        if (k + 2 < NC) load_stage((k + 2) % G_NSTAGE, k + 2);
        CP_COMMIT();

        const uint32_t sA = sb + (k % G_NSTAGE) * G_STAGE;
        const uint32_t sB = sA + G_A_PART;
#pragma unroll
        for (int ks = 0; ks < 4; ks++) {
            const uint32_t kb = ks * 32;
            uint32_t Af[2][4];
#pragma unroll
            for (int mi = 0; mi < 2; mi++) {
                uint32_t ra = (warp_m + mi * 16 + a_row) * LDSB + kb + a_cb;
                ldsm4(Af[mi], sA + ra);
            }
#pragma unroll
            for (int g = 0; g < 4; g++) {
                uint32_t rb = (warp_n + g * 16 + b_row) * LDSB + kb + b_cb;
                uint32_t th[4];
                ldsm4(th, sB + rb);
#pragma unroll
                for (int mi = 0; mi < 2; mi++) {
                    mma_f16(acc[mi][2 * g],     Af[mi], th);
                    mma_f16(acc[mi][2 * g + 1], Af[mi], th + 2);
                }
            }
        }
    }

    // ---------------- FC1 phase ----------------
    __syncthreads();
    CP_WAITG0();

    auto load_w = [&](uint32_t buf, int kc) {
        const int k0 = kc * 64;
#pragma unroll
        for (int it = 0; it < 4; it++) {
            int c = it * 512 + tid;
            int row = c >> 3, seg = c & 7;
            cp16(buf + row * LDSB + seg * 16,
                 W + (size_t)row * H_ + k0 + seg * 8);
        }
    };
    load_w(sb + WB0_OFF, 0); CP_COMMIT();
    load_w(sb + WB1_OFF, 1); CP_COMMIT();

    const int colb = warp_n + (lane & 3) * 2;
#pragma unroll
    for (int mi = 0; mi < 2; mi++) {
#pragma unroll
        for (int p = 0; p < 2; p++) {
            const int ml = warp_m + mi * 16 + (lane >> 2) + p * 8;
            const float dv = g_dinv[b * N_ + m0 + ml];
#pragma unroll
            for (int ni = 0; ni < 8; ni++) {
                *(uint32_t*)(smem + ml * CLD + (colb + ni * 8) * 2) =
                    packh2(acc[mi][ni][2 * p] * dv, acc[mi][ni][2 * p + 1] * dv);
            }
        }
    }
#pragma unroll
    for (int i = 0; i < 2; i++)
#pragma unroll
        for (int j = 0; j < 8; j++)
#pragma unroll
            for (int q = 0; q < 4; q++) acc[i][j][q] = 0.f;

    CP_WAITG1();
    __syncthreads();

    auto fc_chunk = [&](int kc, uint32_t wb) {
#pragma unroll
        for (int ks = 0; ks < 4; ks++) {
            const uint32_t kb = ks * 32;
            uint32_t Af[2][4];
#pragma unroll
            for (int mi = 0; mi < 2; mi++) {
                uint32_t ra = (warp_m + mi * 16 + a_row) * CLD + kc * 128 + kb + a_cb;
                ldsm4(Af[mi], sb + ra);
            }
#pragma unroll
            for (int g = 0; g < 4; g++) {
                uint32_t rb = (warp_n + g * 16 + b_row) * LDSB + kb + b_cb;
                uint32_t th[4];
                ldsm4(th, wb + rb);
#pragma unroll
                for (int mi = 0; mi < 2; mi++) {
                    mma_f16(acc[mi][2 * g],     Af[mi], th);
                    mma_f16(acc[mi][2 * g + 1], Af[mi], th + 2);
                }
            }
        }
    };

    fc_chunk(0, sb + WB0_OFF);
    __syncthreads();
    load_w(sb + WB0_OFF, 2); CP_COMMIT();
    CP_WAITG1(); __syncthreads();
    fc_chunk(1, sb + WB1_OFF);
    __syncthreads();
    load_w(sb + WB1_OFF, 3); CP_COMMIT();
    CP_WAITG1(); __syncthreads();
    fc_chunk(2, sb + WB0_OFF);
    CP_WAITG0(); __syncthreads();
    fc_chunk(3, sb + WB1_OFF);

    // ---------------- transpose-out ----------------
    __syncthreads();
#pragma unroll
    for (int mi = 0; mi < 2; mi++) {
#pragma unroll
        for (int p = 0; p < 2; p++) {
            const int ml = warp_m + mi * 16 + (lane >> 2) + p * 8;
            const float dv = g_dinv[b * N_ + m0 + ml];
#pragma unroll
            for (int ni = 0; ni < 8; ni++) {
                int c = colb + ni * 8;
                float v0 = fmaxf(acc[mi][ni][2 * p]     + bias[c],     0.f) * dv;
                float v1 = fmaxf(acc[mi][ni][2 * p + 1] + bias[c + 1], 0.f) * dv;
                *(__half*)(smem + c * HT_LD + ml * 2)       = __float2half_rn(v0);
                *(__half*)(smem + (c + 1) * HT_LD + ml * 2) = __float2half_rn(v1);
            }
        }
    }
    __syncthreads();
    const int h = tid >> 1, seg = tid & 1;
    const char* srow = smem + h * HT_LD + seg * 128;
    __half* drow = out + (size_t)(b * H_ + h) * N_ + m0 + seg * 64;
#pragma unroll
    for (int q = 0; q < 8; q++)
        *(uint4*)(drow + q * 8) = *(const uint4*)(srow + q * 16);
}

// ===========================================================================
// Layer 2 fused + output FC:
//   C = dinv*(G@Xt2^T); h = relu(C@W2^T+b2);
//   out = relu([Nf | h] @ Wo^T + bout)  (f32, final)
// ===========================================================================
__global__ void __launch_bounds__(512, 1) aggfc2(
    const __half* __restrict__ G, const __half* __restrict__ Xin,
    const __half* __restrict__ W2h, const float* __restrict__ b2,
    const __half* __restrict__ Nf, const __half* __restrict__ Wo,
    const float* __restrict__ bout, float* __restrict__ out)
{
    extern __shared__ char smem[];
    const uint32_t sb = s2u(smem);
    constexpr int NC = N_ / 64;  // 32

    const int tid = threadIdx.x, wid = tid >> 5, lane = tid & 31;
    const int b = blockIdx.z;
    const int m0 = blockIdx.y * 128;
    const int warp_m = (wid & 3) * 32;
    const int warp_n = (wid >> 2) * 64;

    const __half* pA = G + (size_t)b * N_ * N_ + (size_t)m0 * N_;
    const __half* pB = Xin + (size_t)b * H_ * N_;

    float acc[2][8][4];
#pragma unroll
    for (int i = 0; i < 2; i++)
#pragma unroll
        for (int j = 0; j < 8; j++)
#pragma unroll
            for (int q = 0; q < 4; q++) acc[i][j][q] = 0.f;

    auto load_stage = [&](int s, int kc) {
        const int k0 = kc * 64;
        const uint32_t base = sb + s * G_STAGE;
#pragma unroll
        for (int it = 0; it < 6; it++) {
            int c = it * 512 + tid;
            if (c < 1024) {
                int row = c >> 3, seg = c & 7;
                cp16(base + row * LDSB + seg * 16,
                     pA + (size_t)row * N_ + k0 + seg * 8);
            } else {
                int cb = c - 1024;
                int row = cb >> 3, seg = cb & 7;
                cp16(base + G_A_PART + row * LDSB + seg * 16,
                     pB + (size_t)row * N_ + k0 + seg * 8);
            }
        }
    };

    const uint32_t a_row = (uint32_t)(lane & 15);
    const uint32_t a_cb  = (uint32_t)((lane >> 4) * 16);
    const uint32_t b_row = (uint32_t)((lane & 7) + ((lane & 16) ? 8 : 0));
    const uint32_t b_cb  = (uint32_t)((lane & 8) << 1);

    load_stage(0, 0); CP_COMMIT();
    load_stage(1, 1); CP_COMMIT();

    for (int k = 0; k < NC; k++) {
        CP_WAITG1();
        __syncthreads();
        if (k + 2 < NC) load_stage((k + 2) % G_NSTAGE, k + 2);
        CP_COMMIT();

        const uint32_t sA = sb + (k % G_NSTAGE) * G_STAGE;
        const uint32_t sB = sA + G_A_PART;
#pragma unroll
        for (int ks = 0; ks < 4; ks++) {
            const uint32_t kb = ks * 32;
            uint32_t Af[2][4];
#pragma unroll
            for (int mi = 0; mi < 2; mi++) {
                uint32_t ra = (warp_m + mi * 16 + a_row) * LDSB + kb + a_cb;
                ldsm4(Af[mi], sA + ra);
            }
#pragma unroll
            for (int g = 0; g < 4; g++) {
                uint32_t rb = (warp_n + g * 16 + b_row) * LDSB + kb + b_cb;
                uint32_t th[4];
                ldsm4(th, sB + rb);
#pragma unroll
                for (int mi = 0; mi < 2; mi++) {
                    mma_f16(acc[mi][2 * g],     Af[mi], th);
                    mma_f16(acc[mi][2 * g + 1], Af[mi], th + 2);
                }
            }
        }
    }

    // ---------------- FC2 phase ----------------
    __syncthreads();
    CP_WAITG0();

    auto load_w2 = [&](uint32_t buf, int kc) {
        const int k0 = kc * 64;
#pragma unroll
        for (int it = 0; it < 4; it++) {
            int c = it * 512 + tid;
            int row = c >> 3, seg = c & 7;
            cp16(buf + row * LDSB + seg * 16,
                 W2h + (size_t)row * H_ + k0 + seg * 8);
        }
    };
    load_w2(sb + WB0_OFF, 0); CP_COMMIT();
    load_w2(sb + WB1_OFF, 1); CP_COMMIT();

    const int colb = warp_n + (lane & 3) * 2;
#pragma unroll
    for (int mi = 0; mi < 2; mi++) {
#pragma unroll
        for (int p = 0; p < 2; p++) {
            const int ml = warp_m + mi * 16 + (lane >> 2) + p * 8;
            const float dv = g_dinv[b * N_ + m0 + ml];
#pragma unroll
            for (int ni = 0; ni < 8; ni++) {
                *(uint32_t*)(smem + ml * CLD + (colb + ni * 8) * 2) =
                    packh2(acc[mi][ni][2 * p] * dv, acc[mi][ni][2 * p + 1] * dv);
            }
        }
    }
#pragma unroll
    for (int i = 0; i < 2; i++)
#pragma unroll
        for (int j = 0; j < 8; j++)
#pragma unroll
            for (int q = 0; q < 4; q++) acc[i][j][q] = 0.f;

    CP_WAITG1();
    __syncthreads();

    // generic A-from-smem chunk: A rows stride a_ld at a_base (+koff bytes)
    auto gen_chunk = [&](uint32_t a_base, uint32_t a_ld, uint32_t koff, uint32_t wb) {
#pragma unroll
        for (int ks = 0; ks < 4; ks++) {
            const uint32_t kb = ks * 32;
            uint32_t Af[2][4];
#pragma unroll
            for (int mi = 0; mi < 2; mi++) {
                uint32_t ra = (warp_m + mi * 16 + a_row) * a_ld + koff + kb + a_cb;
                ldsm4(Af[mi], a_base + ra);
            }
#pragma unroll
            for (int g = 0; g < 4; g++) {
                uint32_t rb = (warp_n + g * 16 + b_row) * LDSB + kb + b_cb;
                uint32_t th[4];
                ldsm4(th, wb + rb);
#pragma unroll
                for (int mi = 0; mi < 2; mi++) {
                    mma_f16(acc[mi][2 * g],     Af[mi], th);
                    mma_f16(acc[mi][2 * g + 1], Af[mi], th + 2);
                }
            }
        }
    };

    gen_chunk(sb, CLD, 0,   sb + WB0_OFF);
    __syncthreads();
    load_w2(sb + WB0_OFF, 2); CP_COMMIT();
    CP_WAITG1(); __syncthreads();
    gen_chunk(sb, CLD, 128, sb + WB1_OFF);
    __syncthreads();
    load_w2(sb + WB1_OFF, 3); CP_COMMIT();
    CP_WAITG1(); __syncthreads();
    gen_chunk(sb, CLD, 256, sb + WB0_OFF);
    CP_WAITG0(); __syncthreads();
    gen_chunk(sb, CLD, 384, sb + WB1_OFF);

    // ---------------- fcout phase: out = relu([Nf|h] @ Wo^T + bout) --------
    __syncthreads();   // all warps done with CLD (C) and W buffers

    auto load_wo = [&](uint32_t buf, int kc) {
        const int k0 = kc * 64;
#pragma unroll
        for (int it = 0; it < 4; it++) {
            int c = it * 512 + tid;
            int row = c >> 3, seg = c & 7;
            cp16(buf + row * LDSB + seg * 16,
                 Wo + (size_t)row * (2 * H_) + k0 + seg * 8);
        }
    };
    auto load_n = [&](uint32_t buf, int kc) {
        const int k0 = kc * 64;
#pragma unroll
        for (int it = 0; it < 2; it++) {
            int c = it * 512 + tid;
            int row = c >> 3, seg = c & 7;
            cp16(buf + row * LDSB + seg * 16,
                 Nf + (size_t)(b * N_ + m0 + row) * H_ + k0 + seg * 8);
        }
    };
    load_wo(sb + WB0_OFF, 0); load_n(sb + NB0_OFF, 0); CP_COMMIT();
    load_wo(sb + WB1_OFF, 1); load_n(sb + NB1_OFF, 1); CP_COMMIT();

    // h = relu(acc + b2) -> CLD region; re-zero acc
#pragma unroll
    for (int mi = 0; mi < 2; mi++) {
#pragma unroll
        for (int p = 0; p < 2; p++) {
            const int ml = warp_m + mi * 16 + (lane >> 2) + p * 8;
#pragma unroll
            for (int ni = 0; ni < 8; ni++) {
                int c = colb + ni * 8;
                *(uint32_t*)(smem + ml * CLD + c * 2) =
                    packh2(fmaxf(acc[mi][ni][2 * p]     + b2[c],     0.f),
                           fmaxf(acc[mi][ni][2 * p + 1] + b2[c + 1], 0.f));
            }
        }
    }
#pragma unroll
    for (int i = 0; i < 2; i++)
#pragma unroll
        for (int j = 0; j < 8; j++)
#pragma unroll
            for (int q = 0; q < 4; q++) acc[i][j][q] = 0.f;

    CP_WAITG1();
    __syncthreads();   // chunk0 (Wo+N) arrived, h visible

    for (int kc = 0; kc < 8; kc++) {
        const uint32_t wb = sb + ((kc & 1) ? WB1_OFF : WB0_OFF);
        if (kc < 4) {
            const uint32_t nb = sb + ((kc & 1) ? NB1_OFF : NB0_OFF);
            gen_chunk(nb, LDSB, 0, wb);
        } else {
            gen_chunk(sb, CLD, (uint32_t)(kc - 4) * 128, wb);
        }
        if (kc + 2 < 8) {
            __syncthreads();               // buffer (kc&1) free to overwrite
            load_wo(sb + ((kc & 1) ? WB1_OFF : WB0_OFF), kc + 2);
            if (kc + 2 < 4) load_n(sb + ((kc & 1) ? NB1_OFF : NB0_OFF), kc + 2);
            CP_COMMIT();
            CP_WAITG1(); __syncthreads();  // chunk kc+1 ready
        } else if (kc + 1 < 8) {
            CP_WAITG0(); __syncthreads();  // final chunk ready
        }
    }

    // ---------------- final epilogue: f32 out ----------------
#pragma unroll
    for (int mi = 0; mi < 2; mi++) {
#pragma unroll
        for (int p = 0; p < 2; p++) {
            const int ml = warp_m + mi * 16 + (lane >> 2) + p * 8;
            const size_t orow = (size_t)(b * N_ + m0 + ml) * H_;
#pragma unroll
            for (int ni = 0; ni < 8; ni++) {
                int c = colb + ni * 8;
                float2 o;
                o.x = fmaxf(acc[mi][ni][2 * p]     + bout[c],     0.f);
                o.y = fmaxf(acc[mi][ni][2 * p + 1] + bout[c + 1], 0.f);
                *(float2*)(out + orow + c) = o;
            }
        }
    }
}

// ---------------------------------------------------------------------------
// Launch — 5 kernels total
// ---------------------------------------------------------------------------
extern "C" void kernel_launch(void* const* d_in, const int* in_sizes, int n_in,
                              void* d_out, int out_size) {
    const float* node  = (const float*)d_in[0];
    const float* graph = (const float*)d_in[1];
    const float* W1    = (const float*)d_in[2];
    const float* b1    = (const float*)d_in[3];
    const float* W2    = (const float*)d_in[4];
    const float* b2    = (const float*)d_in[5];
    const float* Wout  = (const float*)d_in[6];
    const float* bout  = (const float*)d_in[7];
    float* out = (float*)d_out;

    __half *Gf16, *Xt, *Xt2, *Nf, *W1h, *W2h, *Woh;
    cudaGetSymbolAddress((void**)&Gf16, g_Gf16);
    cudaGetSymbolAddress((void**)&Xt, g_Xt);
    cudaGetSymbolAddress((void**)&Xt2, g_Xt2);
    cudaGetSymbolAddress((void**)&Nf, g_Nf);
    cudaGetSymbolAddress((void**)&W1h, g_W1);
    cudaGetSymbolAddress((void**)&W2h, g_W2);
    cudaGetSymbolAddress((void**)&Woh, g_Wo);

    cudaFuncSetAttribute(aggfc1, cudaFuncAttributeMaxDynamicSharedMemorySize, SMEM_ALL);
    cudaFuncSetAttribute(aggfc2, cudaFuncAttributeMaxDynamicSharedMemorySize, SMEM_ALL);

    dim3 gAgg(1, N_ / 128, B_);       // 128 CTAs
    dim3 gXt(64, 8, 8), bXt(32, 8);

    graph_conv<<<B_ * N_, 256>>>(graph);                               // 0
    prep_node<<<gXt, bXt>>>(node);                                     // 1
    wconv<<<256, 256>>>(W1, W2, Wout);                                 // 2
    aggfc1<<<gAgg, 512, SMEM_ALL>>>(Gf16, Xt, W1h, b1, Xt2);           // 3
    aggfc2<<<gAgg, 512, SMEM_ALL>>>(Gf16, Xt2, W2h, b2,
                                    Nf, Woh, bout, out);               // 4
}

// round 12
// speedup vs baseline: 7.0250x; 1.0131x over previous
#include <cuda_runtime.h>
#include <cuda_fp16.h>
#include <cstdint>

#define B_ 8
#define N_ 2048
#define H_ 256
#define M_TOT (B_ * N_)  // 16384

// ---------------------------------------------------------------------------
// Device scratch (fp16 everywhere)
// ---------------------------------------------------------------------------
__device__ __half g_Gf16[(size_t)B_ * N_ * N_];
__device__ __half g_Xt[(size_t)B_ * H_ * N_];
__device__ __half g_Xt2[(size_t)B_ * H_ * N_];
__device__ __half g_Nf[(size_t)M_TOT * H_];
__device__ __half g_W1[H_ * H_];
__device__ __half g_W2[H_ * H_];
__device__ __half g_Wo[H_ * 2 * H_];
__device__ float  g_dinv[B_ * N_];

// ---------------------------------------------------------------------------
// PTX helpers (sm_80-portable only)
// ---------------------------------------------------------------------------
__device__ __forceinline__ uint32_t s2u(const void* p) {
    uint32_t r;
    asm("{ .reg .u64 t; cvta.to.shared.u64 t, %1; cvt.u32.u64 %0, t; }"
        : "=r"(r) : "l"(p));
    return r;
}
__device__ __forceinline__ void cp16(uint32_t s, const void* g) {
    asm volatile("cp.async.cg.shared.global [%0], [%1], 16;" :: "r"(s), "l"(g) : "memory");
}
#define CP_COMMIT() asm volatile("cp.async.commit_group;" ::: "memory")
#define CP_WAITG1() asm volatile("cp.async.wait_group 1;" ::: "memory")
#define CP_WAITG0() asm volatile("cp.async.wait_group 0;" ::: "memory")

__device__ __forceinline__ void ldsm4(uint32_t* r, uint32_t a) {
    asm volatile("ldmatrix.sync.aligned.m8n8.x4.shared.b16 {%0,%1,%2,%3}, [%4];"
                 : "=r"(r[0]), "=r"(r[1]), "=r"(r[2]), "=r"(r[3]) : "r"(a));
}
__device__ __forceinline__ void mma_f16(float* d, const uint32_t* a, const uint32_t* b) {
    asm volatile(
        "mma.sync.aligned.m16n8k16.row.col.f32.f16.f16.f32 "
        "{%0,%1,%2,%3}, {%4,%5,%6,%7}, {%8,%9}, {%0,%1,%2,%3};"
        : "+f"(d[0]), "+f"(d[1]), "+f"(d[2]), "+f"(d[3])
        : "r"(a[0]), "r"(a[1]), "r"(a[2]), "r"(a[3]), "r"(b[0]), "r"(b[1]));
}
__device__ __forceinline__ uint32_t packh2(float a, float b) {
    __half2 t(__float2half_rn(a), __float2half_rn(b));
    return *reinterpret_cast<uint32_t*>(&t);
}

// ---------------------------------------------------------------------------
// graph -> fp16 + fused row-sum -> dinv
// ---------------------------------------------------------------------------
__global__ void graph_conv(const float* __restrict__ graph) {
    int row = blockIdx.x;
    size_t base = (size_t)row * N_;
    float s = 0.f;
#pragma unroll
    for (int it = 0; it < 2; it++) {
        int j = (threadIdx.x + it * 256) * 4;
        float4 v = *(const float4*)(graph + base + j);
        s += v.x + v.y + v.z + v.w;
        *(uint2*)(g_Gf16 + base + j) =
            make_uint2(packh2(v.x, v.y), packh2(v.z, v.w));
    }
#pragma unroll
    for (int o = 16; o; o >>= 1) s += __shfl_down_sync(0xffffffffu, s, o);
    __shared__ float ws[8];
    int lane = threadIdx.x & 31, w = threadIdx.x >> 5;
    if (lane == 0) ws[w] = s;
    __syncthreads();
    if (threadIdx.x == 0) {
        float t = 0.f;
#pragma unroll
        for (int i = 0; i < 8; i++) t += ws[i];
        g_dinv[row] = rsqrtf(t);
    }
}

// ---------------------------------------------------------------------------
// prep_node: one read of node -> Xt (transposed * dinv) AND Nf (row-major)
// ---------------------------------------------------------------------------
__global__ void prep_node(const float* __restrict__ node) {
    __shared__ float t[32][33];
    int b = blockIdx.z, k0 = blockIdx.x * 32, n0 = blockIdx.y * 32;
    const float* S = node + (size_t)b * N_ * H_;
    for (int j = threadIdx.y; j < 32; j += 8) {
        float v = S[(size_t)(k0 + j) * H_ + n0 + threadIdx.x];
        g_Nf[(size_t)(b * N_ + k0 + j) * H_ + n0 + threadIdx.x] = __float2half_rn(v);
        t[j][threadIdx.x] = v * g_dinv[b * N_ + k0 + j];
    }
    __syncthreads();
    for (int j = threadIdx.y; j < 32; j += 8) {
        size_t o = (size_t)(b * H_ + n0 + j) * N_ + k0 + threadIdx.x;
        g_Xt[o] = __float2half_rn(t[threadIdx.x][j]);
    }
}

// ---------------------------------------------------------------------------
// wconv: convert W1, W2, Wout fp32 -> fp16 in one kernel
// ---------------------------------------------------------------------------
__global__ void wconv(const float* __restrict__ W1, const float* __restrict__ W2,
                      const float* __restrict__ Wo) {
    int e = (blockIdx.x * 256 + threadIdx.x) * 4;   // 0 .. 262143
    const float* src;
    __half* dst;
    int off;
    if (e < 65536)       { src = W1; dst = g_W1; off = e; }
    else if (e < 131072) { src = W2; dst = g_W2; off = e - 65536; }
    else                 { src = Wo; dst = g_Wo; off = e - 131072; }
    float4 v = *(const float4*)(src + off);
    *(uint2*)(dst + off) = make_uint2(packh2(v.x, v.y), packh2(v.z, v.w));
}

// ===========================================================================
// Common tiling constants
// ===========================================================================
#define LDSB 144                            // pipeline rows: 64 fp16 + pad
#define G_A_PART (128 * LDSB)               // 18432
#define G_B_PART (256 * LDSB)               // 36864
#define G_STAGE (G_A_PART + G_B_PART)       // 55296
#define G_NSTAGE 3
// FC-phase smem (reuses pipeline region):
#define CLD 528                             // C/h rows: 256 fp16 + 16B pad
#define WB0_OFF 67584                       // 128*528
#define WB1_OFF 104448                      // +256*144
#define NB0_OFF 141312                      // +256*144
#define NB1_OFF 159744                      // +128*144
#define SMEM_ALL 178176                     // NB1 end
#define HT_LD 272                           // transposed h rows: 128 fp16 + pad

// Batched-fragment MMA step: issue ALL 6 LDSM first, then 16 MMAs.
// a_base rows stride a_ld (+koff bytes); weights at wb (LDSB stride).
#define MMA_STEP(a_base, a_ld, koff, wb, kb)                                   \
    do {                                                                       \
        uint32_t Af[2][4], Bf[4][4];                                           \
        _Pragma("unroll")                                                      \
        for (int mi = 0; mi < 2; mi++)                                         \
            ldsm4(Af[mi], (a_base) + (warp_m + mi * 16 + a_row) * (a_ld) +     \
                           (koff) + (kb) + a_cb);                              \
        _Pragma("unroll")                                                      \
        for (int g = 0; g < 4; g++)                                            \
            ldsm4(Bf[g], (wb) + (warp_n + g * 16 + b_row) * LDSB + (kb) + b_cb); \
        _Pragma("unroll")                                                      \
        for (int g = 0; g < 4; g++)                                            \
            _Pragma("unroll")                                                  \
            for (int mi = 0; mi < 2; mi++) {                                   \
                mma_f16(acc[mi][2 * g],     Af[mi], Bf[g]);                    \
                mma_f16(acc[mi][2 * g + 1], Af[mi], Bf[g] + 2);                \
            }                                                                  \
    } while (0)

// ===========================================================================
// Layer 1 fused: C = dinv*(G@Xt^T); h = relu(C@W1^T+b1);
// out Xt2[b][h][tok] = h^T * dinv.
// ===========================================================================
__global__ void __launch_bounds__(512, 1) aggfc1(
    const __half* __restrict__ G, const __half* __restrict__ Xin,
    const __half* __restrict__ W, const float* __restrict__ bias,
    __half* __restrict__ out)
{
    extern __shared__ char smem[];
    const uint32_t sb = s2u(smem);
    constexpr int NC = N_ / 64;  // 32

    const int tid = threadIdx.x, wid = tid >> 5, lane = tid & 31;
    const int b = blockIdx.z;
    const int m0 = blockIdx.y * 128;
    const int warp_m = (wid & 3) * 32;
    const int warp_n = (wid >> 2) * 64;

    const __half* pA = G + (size_t)b * N_ * N_ + (size_t)m0 * N_;
    const __half* pB = Xin + (size_t)b * H_ * N_;

    float acc[2][8][4];
#pragma unroll
    for (int i = 0; i < 2; i++)
#pragma unroll
        for (int j = 0; j < 8; j++)
#pragma unroll
            for (int q = 0; q < 4; q++) acc[i][j][q] = 0.f;

    auto load_stage = [&](int s, int kc) {
        const int k0 = kc * 64;
        const uint32_t base = sb + s * G_STAGE;
#pragma unroll
        for (int it = 0; it < 6; it++) {
            int c = it * 512 + tid;
            if (c < 1024) {
                int row = c >> 3, seg = c & 7;
                cp16(base + row * LDSB + seg * 16,
                     pA + (size_t)row * N_ + k0 + seg * 8);
            } else {
                int cb = c - 1024;
                int row = cb >> 3, seg = cb & 7;
                cp16(base + G_A_PART + row * LDSB + seg * 16,
                     pB + (size_t)row * N_ + k0 + seg * 8);
            }
        }
    };

    const uint32_t a_row = (uint32_t)(lane & 15);
    const uint32_t a_cb  = (uint32_t)((lane >> 4) * 16);
    const uint32_t b_row = (uint32_t)((lane & 7) + ((lane & 16) ? 8 : 0));
    const uint32_t b_cb  = (uint32_t)((lane & 8) << 1);

    load_stage(0, 0); CP_COMMIT();
    load_stage(1, 1); CP_COMMIT();

    for (int k = 0; k < NC; k++) {
        CP_WAITG1();
        __syncthreads();
        if (k + 2 < NC) load_stage((k + 2) % G_NSTAGE, k + 2);
        CP_COMMIT();

        const uint32_t sA = sb + (k % G_NSTAGE) * G_STAGE;
        const uint32_t sB = sA + G_A_PART;
#pragma unroll
        for (int ks = 0; ks < 4; ks++)
            MMA_STEP(sA, LDSB, 0u, sB, (uint32_t)(ks * 32));
    }

    // ---------------- FC1 phase ----------------
    __syncthreads();
    CP_WAITG0();

    auto load_w = [&](uint32_t buf, int kc) {
        const int k0 = kc * 64;
#pragma unroll
        for (int it = 0; it < 4; it++) {
            int c = it * 512 + tid;
            int row = c >> 3, seg = c & 7;
            cp16(buf + row * LDSB + seg * 16,
                 W + (size_t)row * H_ + k0 + seg * 8);
        }
    };
    load_w(sb + WB0_OFF, 0); CP_COMMIT();
    load_w(sb + WB1_OFF, 1); CP_COMMIT();

    const int colb = warp_n + (lane & 3) * 2;
#pragma unroll
    for (int mi = 0; mi < 2; mi++) {
#pragma unroll
        for (int p = 0; p < 2; p++) {
            const int ml = warp_m + mi * 16 + (lane >> 2) + p * 8;
            const float dv = g_dinv[b * N_ + m0 + ml];
#pragma unroll
            for (int ni = 0; ni < 8; ni++) {
                *(uint32_t*)(smem + ml * CLD + (colb + ni * 8) * 2) =
                    packh2(acc[mi][ni][2 * p] * dv, acc[mi][ni][2 * p + 1] * dv);
            }
        }
    }
#pragma unroll
    for (int i = 0; i < 2; i++)
#pragma unroll
        for (int j = 0; j < 8; j++)
#pragma unroll
            for (int q = 0; q < 4; q++) acc[i][j][q] = 0.f;

    CP_WAITG1();
    __syncthreads();

    auto fc_chunk = [&](int kc, uint32_t wb) {
#pragma unroll
        for (int ks = 0; ks < 4; ks++)
            MMA_STEP(sb, CLD, (uint32_t)(kc * 128), wb, (uint32_t)(ks * 32));
    };

    fc_chunk(0, sb + WB0_OFF);
    __syncthreads();
    load_w(sb + WB0_OFF, 2); CP_COMMIT();
    CP_WAITG1(); __syncthreads();
    fc_chunk(1, sb + WB1_OFF);
    __syncthreads();
    load_w(sb + WB1_OFF, 3); CP_COMMIT();
    CP_WAITG1(); __syncthreads();
    fc_chunk(2, sb + WB0_OFF);
    CP_WAITG0(); __syncthreads();
    fc_chunk(3, sb + WB1_OFF);

    // ---------------- transpose-out ----------------
    __syncthreads();
#pragma unroll
    for (int mi = 0; mi < 2; mi++) {
#pragma unroll
        for (int p = 0; p < 2; p++) {
            const int ml = warp_m + mi * 16 + (lane >> 2) + p * 8;
            const float dv = g_dinv[b * N_ + m0 + ml];
#pragma unroll
            for (int ni = 0; ni < 8; ni++) {
                int c = colb + ni * 8;
                float v0 = fmaxf(acc[mi][ni][2 * p]     + bias[c],     0.f) * dv;
                float v1 = fmaxf(acc[mi][ni][2 * p + 1] + bias[c + 1], 0.f) * dv;
                *(__half*)(smem + c * HT_LD + ml * 2)       = __float2half_rn(v0);
                *(__half*)(smem + (c + 1) * HT_LD + ml * 2) = __float2half_rn(v1);
            }
        }
    }
    __syncthreads();
    const int h = tid >> 1, seg = tid & 1;
    const char* srow = smem + h * HT_LD + seg * 128;
    __half* drow = out + (size_t)(b * H_ + h) * N_ + m0 + seg * 64;
#pragma unroll
    for (int q = 0; q < 8; q++)
        *(uint4*)(drow + q * 8) = *(const uint4*)(srow + q * 16);
}

// ===========================================================================
// Layer 2 fused + output FC:
//   C = dinv*(G@Xt2^T); h = relu(C@W2^T+b2);
//   out = relu([Nf | h] @ Wo^T + bout)  (f32, final)
// ===========================================================================
__global__ void __launch_bounds__(512, 1) aggfc2(
    const __half* __restrict__ G, const __half* __restrict__ Xin,
    const __half* __restrict__ W2h, const float* __restrict__ b2,
    const __half* __restrict__ Nf, const __half* __restrict__ Wo,
    const float* __restrict__ bout, float* __restrict__ out)
{
    extern __shared__ char smem[];
    const uint32_t sb = s2u(smem);
    constexpr int NC = N_ / 64;  // 32

    const int tid = threadIdx.x, wid = tid >> 5, lane = tid & 31;
    const int b = blockIdx.z;
    const int m0 = blockIdx.y * 128;
    const int warp_m = (wid & 3) * 32;
    const int warp_n = (wid >> 2) * 64;

    const __half* pA = G + (size_t)b * N_ * N_ + (size_t)m0 * N_;
    const __half* pB = Xin + (size_t)b * H_ * N_;

    float acc[2][8][4];
#pragma unroll
    for (int i = 0; i < 2; i++)
#pragma unroll
        for (int j = 0; j < 8; j++)
#pragma unroll
            for (int q = 0; q < 4; q++) acc[i][j][q] = 0.f;

    auto load_stage = [&](int s, int kc) {
        const int k0 = kc * 64;
        const uint32_t base = sb + s * G_STAGE;
#pragma unroll
        for (int it = 0; it < 6; it++) {
            int c = it * 512 + tid;
            if (c < 1024) {
                int row = c >> 3, seg = c & 7;
                cp16(base + row * LDSB + seg * 16,
                     pA + (size_t)row * N_ + k0 + seg * 8);
            } else {
                int cb = c - 1024;
                int row = cb >> 3, seg = cb & 7;
                cp16(base + G_A_PART + row * LDSB + seg * 16,
                     pB + (size_t)row * N_ + k0 + seg * 8);
            }
        }
    };

    const uint32_t a_row = (uint32_t)(lane & 15);
    const uint32_t a_cb  = (uint32_t)((lane >> 4) * 16);
    const uint32_t b_row = (uint32_t)((lane & 7) + ((lane & 16) ? 8 : 0));
    const uint32_t b_cb  = (uint32_t)((lane & 8) << 1);

    load_stage(0, 0); CP_COMMIT();
    load_stage(1, 1); CP_COMMIT();

    for (int k = 0; k < NC; k++) {
        CP_WAITG1();
        __syncthreads();
        if (k + 2 < NC) load_stage((k + 2) % G_NSTAGE, k + 2);
        CP_COMMIT();

        const uint32_t sA = sb + (k % G_NSTAGE) * G_STAGE;
        const uint32_t sB = sA + G_A_PART;
#pragma unroll
        for (int ks = 0; ks < 4; ks++)
            MMA_STEP(sA, LDSB, 0u, sB, (uint32_t)(ks * 32));
    }

    // ---------------- FC2 phase ----------------
    __syncthreads();
    CP_WAITG0();

    auto load_w2 = [&](uint32_t buf, int kc) {
        const int k0 = kc * 64;
#pragma unroll
        for (int it = 0; it < 4; it++) {
            int c = it * 512 + tid;
            int row = c >> 3, seg = c & 7;
            cp16(buf + row * LDSB + seg * 16,
                 W2h + (size_t)row * H_ + k0 + seg * 8);
        }
    };
    load_w2(sb + WB0_OFF, 0); CP_COMMIT();
    load_w2(sb + WB1_OFF, 1); CP_COMMIT();

    const int colb = warp_n + (lane & 3) * 2;
#pragma unroll
    for (int mi = 0; mi < 2; mi++) {
#pragma unroll
        for (int p = 0; p < 2; p++) {
            const int ml = warp_m + mi * 16 + (lane >> 2) + p * 8;
            const float dv = g_dinv[b * N_ + m0 + ml];
#pragma unroll
            for (int ni = 0; ni < 8; ni++) {
                *(uint32_t*)(smem + ml * CLD + (colb + ni * 8) * 2) =
                    packh2(acc[mi][ni][2 * p] * dv, acc[mi][ni][2 * p + 1] * dv);
            }
        }
    }
#pragma unroll
    for (int i = 0; i < 2; i++)
#pragma unroll
        for (int j = 0; j < 8; j++)
#pragma unroll
            for (int q = 0; q < 4; q++) acc[i][j][q] = 0.f;

    CP_WAITG1();
    __syncthreads();

    auto gen_chunk = [&](uint32_t a_base, uint32_t a_ld, uint32_t koff, uint32_t wb) {
#pragma unroll
        for (int ks = 0; ks < 4; ks++)
            MMA_STEP(a_base, a_ld, koff, wb, (uint32_t)(ks * 32));
    };

    gen_chunk(sb, CLD, 0,   sb + WB0_OFF);
    __syncthreads();
    load_w2(sb + WB0_OFF, 2); CP_COMMIT();
    CP_WAITG1(); __syncthreads();
    gen_chunk(sb, CLD, 128, sb + WB1_OFF);
    __syncthreads();
    load_w2(sb + WB1_OFF, 3); CP_COMMIT();
    CP_WAITG1(); __syncthreads();
    gen_chunk(sb, CLD, 256, sb + WB0_OFF);
    CP_WAITG0(); __syncthreads();
    gen_chunk(sb, CLD, 384, sb + WB1_OFF);

    // ---------------- fcout phase: out = relu([Nf|h] @ Wo^T + bout) --------
    __syncthreads();   // all warps done with CLD (C) and W buffers

    auto load_wo = [&](uint32_t buf, int kc) {
        const int k0 = kc * 64;
#pragma unroll
        for (int it = 0; it < 4; it++) {
            int c = it * 512 + tid;
            int row = c >> 3, seg = c & 7;
            cp16(buf + row * LDSB + seg * 16,
                 Wo + (size_t)row * (2 * H_) + k0 + seg * 8);
        }
    };
    auto load_n = [&](uint32_t buf, int kc) {
        const int k0 = kc * 64;
#pragma unroll
        for (int it = 0; it < 2; it++) {
            int c = it * 512 + tid;
            int row = c >> 3, seg = c & 7;
            cp16(buf + row * LDSB + seg * 16,
                 Nf + (size_t)(b * N_ + m0 + row) * H_ + k0 + seg * 8);
        }
    };
    load_wo(sb + WB0_OFF, 0); load_n(sb + NB0_OFF, 0); CP_COMMIT();
    load_wo(sb + WB1_OFF, 1); load_n(sb + NB1_OFF, 1); CP_COMMIT();

    // h = relu(acc + b2) -> CLD region; re-zero acc
#pragma unroll
    for (int mi = 0; mi < 2; mi++) {
#pragma unroll
        for (int p = 0; p < 2; p++) {
            const int ml = warp_m + mi * 16 + (lane >> 2) + p * 8;
#pragma unroll
            for (int ni = 0; ni < 8; ni++) {
                int c = colb + ni * 8;
                *(uint32_t*)(smem + ml * CLD + c * 2) =
                    packh2(fmaxf(acc[mi][ni][2 * p]     + b2[c],     0.f),
                           fmaxf(acc[mi][ni][2 * p + 1] + b2[c + 1], 0.f));
            }
        }
    }
#pragma unroll
    for (int i = 0; i < 2; i++)
#pragma unroll
        for (int j = 0; j < 8; j++)
#pragma unroll
            for (int q = 0; q < 4; q++) acc[i][j][q] = 0.f;

    CP_WAITG1();
    __syncthreads();   // chunk0 (Wo+N) arrived, h visible

    for (int kc = 0; kc < 8; kc++) {
        const uint32_t wb = sb + ((kc & 1) ? WB1_OFF : WB0_OFF);
        if (kc < 4) {
            const uint32_t nb = sb + ((kc & 1) ? NB1_OFF : NB0_OFF);
            gen_chunk(nb, LDSB, 0, wb);
        } else {
            gen_chunk(sb, CLD, (uint32_t)(kc - 4) * 128, wb);
        }
        if (kc + 2 < 8) {
            __syncthreads();               // buffer (kc&1) free to overwrite
            load_wo(sb + ((kc & 1) ? WB1_OFF : WB0_OFF), kc + 2);
            if (kc + 2 < 4) load_n(sb + ((kc & 1) ? NB1_OFF : NB0_OFF), kc + 2);
            CP_COMMIT();
            CP_WAITG1(); __syncthreads();  // chunk kc+1 ready
        } else if (kc + 1 < 8) {
            CP_WAITG0(); __syncthreads();  // final chunk ready
        }
    }

    // ---------------- final epilogue: f32 out ----------------
#pragma unroll
    for (int mi = 0; mi < 2; mi++) {
#pragma unroll
        for (int p = 0; p < 2; p++) {
            const int ml = warp_m + mi * 16 + (lane >> 2) + p * 8;
            const size_t orow = (size_t)(b * N_ + m0 + ml) * H_;
#pragma unroll
            for (int ni = 0; ni < 8; ni++) {
                int c = colb + ni * 8;
                float2 o;
                o.x = fmaxf(acc[mi][ni][2 * p]     + bout[c],     0.f);
                o.y = fmaxf(acc[mi][ni][2 * p + 1] + bout[c + 1], 0.f);
                *(float2*)(out + orow + c) = o;
            }
        }
    }
}

// ---------------------------------------------------------------------------
// Launch — 5 kernels total
// ---------------------------------------------------------------------------
extern "C" void kernel_launch(void* const* d_in, const int* in_sizes, int n_in,
                              void* d_out, int out_size) {
    const float* node  = (const float*)d_in[0];
    const float* graph = (const float*)d_in[1];
    const float* W1    = (const float*)d_in[2];
    const float* b1    = (const float*)d_in[3];
    const float* W2    = (const float*)d_in[4];
    const float* b2    = (const float*)d_in[5];
    const float* Wout  = (const float*)d_in[6];
    const float* bout  = (const float*)d_in[7];
    float* out = (float*)d_out;

    __half *Gf16, *Xt, *Xt2, *Nf, *W1h, *W2h, *Woh;
    cudaGetSymbolAddress((void**)&Gf16, g_Gf16);
    cudaGetSymbolAddress((void**)&Xt, g_Xt);
    cudaGetSymbolAddress((void**)&Xt2, g_Xt2);
    cudaGetSymbolAddress((void**)&Nf, g_Nf);
    cudaGetSymbolAddress((void**)&W1h, g_W1);
    cudaGetSymbolAddress((void**)&W2h, g_W2);
    cudaGetSymbolAddress((void**)&Woh, g_Wo);

    cudaFuncSetAttribute(aggfc1, cudaFuncAttributeMaxDynamicSharedMemorySize, SMEM_ALL);
    cudaFuncSetAttribute(aggfc2, cudaFuncAttributeMaxDynamicSharedMemorySize, SMEM_ALL);

    dim3 gAgg(1, N_ / 128, B_);       // 128 CTAs
    dim3 gXt(64, 8, 8), bXt(32, 8);

    graph_conv<<<B_ * N_, 256>>>(graph);                               // 0
    prep_node<<<gXt, bXt>>>(node);                                     // 1
    wconv<<<256, 256>>>(W1, W2, Wout);                                 // 2
    aggfc1<<<gAgg, 512, SMEM_ALL>>>(Gf16, Xt, W1h, b1, Xt2);           // 3
    aggfc2<<<gAgg, 512, SMEM_ALL>>>(Gf16, Xt2, W2h, b2,
                                    Nf, Woh, bout, out);               // 4
}